// round 1
// baseline (speedup 1.0000x reference)
#include <cuda_runtime.h>

#define THREADS 512

// Smem layout (floats):
//  sCS   [128][33] float2  : (cos, sin)(2*pi*w*v/128)        -> 8448 f
//  sPM   [64][128] float2  : (cas+, cas-)(2*pi*f(u)*h/128)   -> 16384 f
//  sY12  [128][33] float2  : stage A intermediates / stage C U1,U2 -> 8448 f
//  sPM32 [32][32]  float2  : (cas+, cas-)(2*pi*u*h/32)       -> 2048 f
//  sCS32 [32][33]  float2  : (cos, sin)(2*pi*w*v/32)         -> 2112 f
//  sR12  [32][33]  float2  : 32-DHT pass-1 scratch           -> 2112 f
//  sXf   [64][33]  float   : selected-mode spectrum / G      -> 2112 f
//  sAh   [32][33]  float   : DHT32(a), then prod             -> 1056 f
//  sWr   [32][33]  float   : raw weight block                -> 1056 f
//  sX    [64][128] float   : half of the input image         -> 8192 f
// total = 51968 floats = 207872 bytes

static __device__ __forceinline__ void dht32_pass1(const float* __restrict__ src,
                                                   float2* __restrict__ sR12,
                                                   const float2* __restrict__ sCS32,
                                                   int wid, int lane)
{
    const int h0 = wid * 2;
    float r1[2] = {0.f, 0.f}, r2[2] = {0.f, 0.f};
#pragma unroll 4
    for (int w = 0; w < 32; ++w) {
        float2 cs = sCS32[w * 33 + lane];
#pragma unroll
        for (int r = 0; r < 2; ++r) {
            float av = src[(h0 + r) * 33 + w];
            r1[r] += av * cs.x;
            r2[r] += av * cs.y;
        }
    }
#pragma unroll
    for (int r = 0; r < 2; ++r)
        sR12[(h0 + r) * 33 + lane] = make_float2(r1[r], r2[r]);
}

static __device__ __forceinline__ void dht32_pass2(const float2* __restrict__ sR12,
                                                   const float2* __restrict__ sPM32,
                                                   float* __restrict__ dst,
                                                   float scale, int wid, int lane)
{
    const int u0 = wid * 2;
    float acc[2] = {0.f, 0.f};
#pragma unroll 4
    for (int h = 0; h < 32; ++h) {
        float2 rr = sR12[h * 33 + lane];
#pragma unroll
        for (int r = 0; r < 2; ++r) {
            float2 pm = sPM32[(u0 + r) * 32 + h];
            acc[r] += pm.x * rr.x + pm.y * rr.y;
        }
    }
#pragma unroll
    for (int r = 0; r < 2; ++r)
        dst[(u0 + r) * 33 + lane] = acc[r] * scale;
}

__global__ __launch_bounds__(THREADS, 1)
void spectral_kernel(const float* __restrict__ Xg,
                     const float* __restrict__ W1g,
                     const float* __restrict__ W2g,
                     float* __restrict__ Og)
{
    extern __shared__ float sm[];
    float2* sCS   = (float2*)sm;            // [128][33]
    float2* sPM   = sCS   + 128 * 33;       // [64][128]
    float2* sY12  = sPM   + 64 * 128;       // [128][33]
    float2* sPM32 = sY12  + 128 * 33;       // [32][32]
    float2* sCS32 = sPM32 + 32 * 32;        // [32][33]
    float2* sR12  = sCS32 + 32 * 33;        // [32][33]
    float*  sXf   = (float*)(sR12 + 32 * 33); // [64][33]
    float*  sAh   = sXf + 64 * 33;          // [32][33]
    float*  sWr   = sAh + 32 * 33;          // [32][33]
    float*  sX    = sWr + 32 * 33;          // [64][128]

    const int tid  = threadIdx.x;
    const int lane = tid & 31;
    const int wid  = tid >> 5;
    const int img  = blockIdx.x;

    const float* X = Xg + (size_t)img * 16384;
    float*       O = Og + (size_t)img * 16384;

    // ---- build transform tables (sincospif: args are multiples of pi -> exact) ----
    for (int i = tid; i < 128 * 32; i += THREADS) {
        int w = i >> 5, v = i & 31;
        float s, c;
        sincospif((float)((w * v) & 127) * (1.0f / 64.0f), &s, &c);
        sCS[w * 33 + v] = make_float2(c, s);
    }
    for (int i = tid; i < 64 * 128; i += THREADS) {
        int u = i >> 7, h = i & 127;
        int f = (u < 32) ? u : (u + 64);           // selected freqs: 0..31, 96..127
        float s, c;
        sincospif((float)((f * h) & 127) * (1.0f / 64.0f), &s, &c);
        sPM[u * 128 + h] = make_float2(c + s, c - s);
    }
    for (int i = tid; i < 32 * 32; i += THREADS) {
        int u = i >> 5, h = i & 31;
        float s, c;
        sincospif((float)((u * h) & 31) * (1.0f / 16.0f), &s, &c);
        sPM32[u * 32 + h] = make_float2(c + s, c - s);
        sCS32[h * 33 + u] = make_float2(c, s);     // symmetric in (u,h): full coverage
    }
    __syncthreads();

    // ---- Stage A1: Y1[h][v] = sum_w x[h][w] cos(2pi v w/128); Y2 with sin ----
    for (int pass = 0; pass < 2; ++pass) {
        const float4* src = (const float4*)(X + pass * 8192);
        float4* dst = (float4*)sX;
        for (int i = tid; i < 2048; i += THREADS) dst[i] = src[i];
        __syncthreads();

        float a1[4] = {0.f, 0.f, 0.f, 0.f}, a2[4] = {0.f, 0.f, 0.f, 0.f};
        const int r0 = wid * 4;
#pragma unroll 4
        for (int w = 0; w < 128; ++w) {
            float2 cs = sCS[w * 33 + lane];
#pragma unroll
            for (int r = 0; r < 4; ++r) {
                float xv = sX[(r0 + r) * 128 + w];
                a1[r] += xv * cs.x;
                a2[r] += xv * cs.y;
            }
        }
#pragma unroll
        for (int r = 0; r < 4; ++r)
            sY12[(pass * 64 + r0 + r) * 33 + lane] = make_float2(a1[r], a2[r]);
        __syncthreads();
    }

    // ---- Stage A2: Xf[u][v] = (1/16384) sum_h (P[u,h] Y1[h,v] + M[u,h] Y2[h,v]) ----
    {
        const int u0 = wid * 4;
        float b[4] = {0.f, 0.f, 0.f, 0.f};
#pragma unroll 4
        for (int h = 0; h < 128; ++h) {
            float2 y = sY12[h * 33 + lane];
#pragma unroll
            for (int r = 0; r < 4; ++r) {
                float2 pm = sPM[(u0 + r) * 128 + h];
                b[r] += pm.x * y.x + pm.y * y.y;
            }
        }
#pragma unroll
        for (int r = 0; r < 4; ++r)
            sXf[(u0 + r) * 33 + lane] = b[r] * (1.0f / 16384.0f);
    }
    __syncthreads();

    // ---- Stage B: per 32x32 block: c = (1/(64*1024)) DHT32( (DHT32(a)) * (DHT32(w)) ) ----
    for (int t = 0; t < 2; ++t) {
        const float* Wsrc = ((t == 0) ? W1g : W2g) + (size_t)img * 1024;
        for (int i = tid; i < 1024; i += THREADS)
            sWr[(i >> 5) * 33 + (i & 31)] = Wsrc[i];

        dht32_pass1(sXf + t * 32 * 33, sR12, sCS32, wid, lane);   // a -> R
        __syncthreads();
        dht32_pass2(sR12, sPM32, sAh, 1.0f / 1024.0f, wid, lane); // Ah = DHT32(a)
        __syncthreads();
        dht32_pass1(sWr, sR12, sCS32, wid, lane);                 // w -> R
        __syncthreads();
        {   // Wh = DHT32(w), fused: sAh <- Ah * Wh
            const int u0 = wid * 2;
            float acc[2] = {0.f, 0.f};
#pragma unroll 4
            for (int h = 0; h < 32; ++h) {
                float2 rr = sR12[h * 33 + lane];
#pragma unroll
                for (int r = 0; r < 2; ++r) {
                    float2 pm = sPM32[(u0 + r) * 32 + h];
                    acc[r] += pm.x * rr.x + pm.y * rr.y;
                }
            }
#pragma unroll
            for (int r = 0; r < 2; ++r) {
                int idx = (u0 + r) * 33 + lane;
                sAh[idx] = sAh[idx] * (acc[r] * (1.0f / 1024.0f));
            }
        }
        __syncthreads();
        dht32_pass1(sAh, sR12, sCS32, wid, lane);                 // prod -> R
        __syncthreads();
        // c into the same Xf block slot, scale 1/(64*1024)
        dht32_pass2(sR12, sPM32, sXf + t * 32 * 33, 1.0f / 65536.0f, wid, lane);
        __syncthreads();
    }

    // ---- Stage C1: U1[h'][s] = sum_r P[r][h'] G[r][s]; U2 with M ----
#pragma unroll
    for (int g = 0; g < 2; ++g) {
        const int h0 = (wid * 2 + g) * 4;
        float u1[4] = {0.f, 0.f, 0.f, 0.f}, u2[4] = {0.f, 0.f, 0.f, 0.f};
#pragma unroll 2
        for (int r = 0; r < 64; ++r) {
            float gv = sXf[r * 33 + lane];
#pragma unroll
            for (int i2 = 0; i2 < 4; ++i2) {
                float2 pm = sPM[r * 128 + h0 + i2];
                u1[i2] += pm.x * gv;
                u2[i2] += pm.y * gv;
            }
        }
#pragma unroll
        for (int i2 = 0; i2 < 4; ++i2)
            sY12[(h0 + i2) * 33 + lane] = make_float2(u1[i2], u2[i2]);
    }
    __syncthreads();

    // ---- Stage C2: y[h'][w'] = (1/(64*16384)) sum_s (U1 cos + U2 sin)(2pi s w'/128) ----
    for (int tt = wid; tt < 64; tt += 16) {
        const int hb = (tt >> 2) * 8;
        const int wp = (tt & 3) * 32 + lane;
        float acc[8] = {0.f, 0.f, 0.f, 0.f, 0.f, 0.f, 0.f, 0.f};
#pragma unroll 4
        for (int s = 0; s < 32; ++s) {
            float2 cs = sCS[wp * 33 + s];
#pragma unroll
            for (int i2 = 0; i2 < 8; ++i2) {
                float2 uu = sY12[(hb + i2) * 33 + s];
                acc[i2] += uu.x * cs.x + uu.y * cs.y;
            }
        }
#pragma unroll
        for (int i2 = 0; i2 < 8; ++i2)
            O[(hb + i2) * 128 + wp] = acc[i2] * (1.0f / 1048576.0f);
    }
}

extern "C" void kernel_launch(void* const* d_in, const int* in_sizes, int n_in,
                              void* d_out, int out_size)
{
    const float* x  = (const float*)d_in[0];
    const float* w1 = (const float*)d_in[1];
    const float* w2 = (const float*)d_in[2];
    float* out = (float*)d_out;

    const int smem_bytes = 51968 * 4; // 207872
    cudaFuncSetAttribute(spectral_kernel,
                         cudaFuncAttributeMaxDynamicSharedMemorySize, smem_bytes);
    spectral_kernel<<<4096, THREADS, smem_bytes>>>(x, w1, w2, out);
}

// round 2
// speedup vs baseline: 1.0020x; 1.0020x over previous
#include <cuda_runtime.h>

#define THREADS 512

// Smem layout (floats):
//  sCS   [128][33] float2  : (cos, sin)(2*pi*w*v/128)        -> 8448 f
//  sPM   [64][128] float2  : (cas+, cas-)(2*pi*f(u)*h/128)   -> 16384 f
//  sY12  [128][33] float2  : stage A intermediates / stage C U1,U2 -> 8448 f
//  sPM32 [32][32]  float2  : (cas+, cas-)(2*pi*u*h/32)       -> 2048 f
//  sCS32 [32][33]  float2  : (cos, sin)(2*pi*w*v/32)         -> 2112 f
//  sR12  [32][33]  float2  : 32-DHT pass-1 scratch           -> 2112 f
//  sXf   [64][33]  float   : selected-mode spectrum / G      -> 2112 f
//  sAh   [32][33]  float   : DHT32(a), then prod             -> 1056 f
//  sWr   [32][33]  float   : raw weight block                -> 1056 f
//  sX    [64][128] float   : half of the input image         -> 8192 f
// total = 51968 floats = 207872 bytes

static __device__ __forceinline__ void dht32_pass1(const float* __restrict__ src,
                                                   float2* __restrict__ sR12,
                                                   const float2* __restrict__ sCS32,
                                                   int wid, int lane)
{
    const int h0 = wid * 2;
    float r1[2] = {0.f, 0.f}, r2[2] = {0.f, 0.f};
#pragma unroll 4
    for (int w = 0; w < 32; ++w) {
        float2 cs = sCS32[w * 33 + lane];
#pragma unroll
        for (int r = 0; r < 2; ++r) {
            float av = src[(h0 + r) * 33 + w];
            r1[r] += av * cs.x;
            r2[r] += av * cs.y;
        }
    }
#pragma unroll
    for (int r = 0; r < 2; ++r)
        sR12[(h0 + r) * 33 + lane] = make_float2(r1[r], r2[r]);
}

static __device__ __forceinline__ void dht32_pass2(const float2* __restrict__ sR12,
                                                   const float2* __restrict__ sPM32,
                                                   float* __restrict__ dst,
                                                   float scale, int wid, int lane)
{
    const int u0 = wid * 2;
    float acc[2] = {0.f, 0.f};
#pragma unroll 4
    for (int h = 0; h < 32; ++h) {
        float2 rr = sR12[h * 33 + lane];
#pragma unroll
        for (int r = 0; r < 2; ++r) {
            float2 pm = sPM32[(u0 + r) * 32 + h];
            acc[r] += pm.x * rr.x + pm.y * rr.y;
        }
    }
#pragma unroll
    for (int r = 0; r < 2; ++r)
        dst[(u0 + r) * 33 + lane] = acc[r] * scale;
}

__global__ __launch_bounds__(THREADS, 1)
void spectral_kernel(const float* __restrict__ Xg,
                     const float* __restrict__ W1g,
                     const float* __restrict__ W2g,
                     float* __restrict__ Og)
{
    extern __shared__ float sm[];
    float2* sCS   = (float2*)sm;            // [128][33]
    float2* sPM   = sCS   + 128 * 33;       // [64][128]
    float2* sY12  = sPM   + 64 * 128;       // [128][33]
    float2* sPM32 = sY12  + 128 * 33;       // [32][32]
    float2* sCS32 = sPM32 + 32 * 32;        // [32][33]
    float2* sR12  = sCS32 + 32 * 33;        // [32][33]
    float*  sXf   = (float*)(sR12 + 32 * 33); // [64][33]
    float*  sAh   = sXf + 64 * 33;          // [32][33]
    float*  sWr   = sAh + 32 * 33;          // [32][33]
    float*  sX    = sWr + 32 * 33;          // [64][128]

    const int tid  = threadIdx.x;
    const int lane = tid & 31;
    const int wid  = tid >> 5;
    const int img  = blockIdx.x;

    const float* X = Xg + (size_t)img * 16384;
    float*       O = Og + (size_t)img * 16384;

    // ---- build transform tables (sincospif: args are multiples of pi -> exact) ----
    for (int i = tid; i < 128 * 32; i += THREADS) {
        int w = i >> 5, v = i & 31;
        float s, c;
        sincospif((float)((w * v) & 127) * (1.0f / 64.0f), &s, &c);
        sCS[w * 33 + v] = make_float2(c, s);
    }
    for (int i = tid; i < 64 * 128; i += THREADS) {
        int u = i >> 7, h = i & 127;
        int f = (u < 32) ? u : (u + 64);           // selected freqs: 0..31, 96..127
        float s, c;
        sincospif((float)((f * h) & 127) * (1.0f / 64.0f), &s, &c);
        sPM[u * 128 + h] = make_float2(c + s, c - s);
    }
    for (int i = tid; i < 32 * 32; i += THREADS) {
        int u = i >> 5, h = i & 31;
        float s, c;
        sincospif((float)((u * h) & 31) * (1.0f / 16.0f), &s, &c);
        sPM32[u * 32 + h] = make_float2(c + s, c - s);
        sCS32[h * 33 + u] = make_float2(c, s);     // symmetric in (u,h): full coverage
    }
    __syncthreads();

    // ---- Stage A1: Y1[h][v] = sum_w x[h][w] cos(2pi v w/128); Y2 with sin ----
    for (int pass = 0; pass < 2; ++pass) {
        const float4* src = (const float4*)(X + pass * 8192);
        float4* dst = (float4*)sX;
        for (int i = tid; i < 2048; i += THREADS) dst[i] = src[i];
        __syncthreads();

        float a1[4] = {0.f, 0.f, 0.f, 0.f}, a2[4] = {0.f, 0.f, 0.f, 0.f};
        const int r0 = wid * 4;
#pragma unroll 4
        for (int w = 0; w < 128; ++w) {
            float2 cs = sCS[w * 33 + lane];
#pragma unroll
            for (int r = 0; r < 4; ++r) {
                float xv = sX[(r0 + r) * 128 + w];
                a1[r] += xv * cs.x;
                a2[r] += xv * cs.y;
            }
        }
#pragma unroll
        for (int r = 0; r < 4; ++r)
            sY12[(pass * 64 + r0 + r) * 33 + lane] = make_float2(a1[r], a2[r]);
        __syncthreads();
    }

    // ---- Stage A2: Xf[u][v] = (1/16384) sum_h (P[u,h] Y1[h,v] + M[u,h] Y2[h,v]) ----
    {
        const int u0 = wid * 4;
        float b[4] = {0.f, 0.f, 0.f, 0.f};
#pragma unroll 4
        for (int h = 0; h < 128; ++h) {
            float2 y = sY12[h * 33 + lane];
#pragma unroll
            for (int r = 0; r < 4; ++r) {
                float2 pm = sPM[(u0 + r) * 128 + h];
                b[r] += pm.x * y.x + pm.y * y.y;
            }
        }
#pragma unroll
        for (int r = 0; r < 4; ++r)
            sXf[(u0 + r) * 33 + lane] = b[r] * (1.0f / 16384.0f);
    }
    __syncthreads();

    // ---- Stage B: per 32x32 block: c = (1/(64*1024)) DHT32( (DHT32(a)) * (DHT32(w)) ) ----
    for (int t = 0; t < 2; ++t) {
        const float* Wsrc = ((t == 0) ? W1g : W2g) + (size_t)img * 1024;
        for (int i = tid; i < 1024; i += THREADS)
            sWr[(i >> 5) * 33 + (i & 31)] = Wsrc[i];

        dht32_pass1(sXf + t * 32 * 33, sR12, sCS32, wid, lane);   // a -> R
        __syncthreads();
        dht32_pass2(sR12, sPM32, sAh, 1.0f / 1024.0f, wid, lane); // Ah = DHT32(a)
        __syncthreads();
        dht32_pass1(sWr, sR12, sCS32, wid, lane);                 // w -> R
        __syncthreads();
        {   // Wh = DHT32(w), fused: sAh <- Ah * Wh
            const int u0 = wid * 2;
            float acc[2] = {0.f, 0.f};
#pragma unroll 4
            for (int h = 0; h < 32; ++h) {
                float2 rr = sR12[h * 33 + lane];
#pragma unroll
                for (int r = 0; r < 2; ++r) {
                    float2 pm = sPM32[(u0 + r) * 32 + h];
                    acc[r] += pm.x * rr.x + pm.y * rr.y;
                }
            }
#pragma unroll
            for (int r = 0; r < 2; ++r) {
                int idx = (u0 + r) * 33 + lane;
                sAh[idx] = sAh[idx] * (acc[r] * (1.0f / 1024.0f));
            }
        }
        __syncthreads();
        dht32_pass1(sAh, sR12, sCS32, wid, lane);                 // prod -> R
        __syncthreads();
        // c into the same Xf block slot, scale 1/(64*1024)
        dht32_pass2(sR12, sPM32, sXf + t * 32 * 33, 1.0f / 65536.0f, wid, lane);
        __syncthreads();
    }

    // ---- Stage C1: U1[h'][s] = sum_r P[r][h'] G[r][s]; U2 with M ----
#pragma unroll
    for (int g = 0; g < 2; ++g) {
        const int h0 = (wid * 2 + g) * 4;
        float u1[4] = {0.f, 0.f, 0.f, 0.f}, u2[4] = {0.f, 0.f, 0.f, 0.f};
#pragma unroll 2
        for (int r = 0; r < 64; ++r) {
            float gv = sXf[r * 33 + lane];
#pragma unroll
            for (int i2 = 0; i2 < 4; ++i2) {
                float2 pm = sPM[r * 128 + h0 + i2];
                u1[i2] += pm.x * gv;
                u2[i2] += pm.y * gv;
            }
        }
#pragma unroll
        for (int i2 = 0; i2 < 4; ++i2)
            sY12[(h0 + i2) * 33 + lane] = make_float2(u1[i2], u2[i2]);
    }
    __syncthreads();

    // ---- Stage C2: y[h'][w'] = (1/(64*16384)) sum_s (U1 cos + U2 sin)(2pi s w'/128) ----
    for (int tt = wid; tt < 64; tt += 16) {
        const int hb = (tt >> 2) * 8;
        const int wp = (tt & 3) * 32 + lane;
        float acc[8] = {0.f, 0.f, 0.f, 0.f, 0.f, 0.f, 0.f, 0.f};
#pragma unroll 4
        for (int s = 0; s < 32; ++s) {
            float2 cs = sCS[wp * 33 + s];
#pragma unroll
            for (int i2 = 0; i2 < 8; ++i2) {
                float2 uu = sY12[(hb + i2) * 33 + s];
                acc[i2] += uu.x * cs.x + uu.y * cs.y;
            }
        }
#pragma unroll
        for (int i2 = 0; i2 < 8; ++i2)
            O[(hb + i2) * 128 + wp] = acc[i2] * (1.0f / 1048576.0f);
    }
}

extern "C" void kernel_launch(void* const* d_in, const int* in_sizes, int n_in,
                              void* d_out, int out_size)
{
    const float* x  = (const float*)d_in[0];
    const float* w1 = (const float*)d_in[1];
    const float* w2 = (const float*)d_in[2];
    float* out = (float*)d_out;

    const int smem_bytes = 51968 * 4; // 207872
    cudaFuncSetAttribute(spectral_kernel,
                         cudaFuncAttributeMaxDynamicSharedMemorySize, smem_bytes);
    spectral_kernel<<<4096, THREADS, smem_bytes>>>(x, w1, w2, out);
}

// round 3
// speedup vs baseline: 1.0427x; 1.0406x over previous
#include <cuda_runtime.h>

#define THREADS 512
#define P_CS   34   // float2 pitch, [128][34]
#define P_Y    34   // float2 pitch, [128][34]
#define P_CS32 34   // float2 pitch, [32][34]
#define P_R    33   // float2 pitch, [32][33]
#define P_F    36   // float pitch,  [.][36]

// Smem (floats):
//  sCS   0      : [128][34] float2  (cos,sin)(2pi*w*v/128)      8704
//  sPM   8704   : [64][128] float2  (cas+,cas-)(2pi*f(u)*h/128) 16384
//  sY12  25088  : [128][34] float2  stage A / C intermediates   8704
//  sPM32 33792  : [32][32]  float2  (cas+,cas-)(2pi*u*h/32)     2048
//  sCS32 35840  : [32][34]  float2  (cos,sin)(2pi*u*h/32)       2176
//  sR12  38016  : [2][32][33] float2  32-DHT scratch            4224
//  sXf   42240  : [64][36]  float   mode spectrum / G           2304
//  sAh   44544  : [2][32][36] float                             2304
//  sWr   46848  : [2][32][36] float                             2304
//  sX    49152  : [64][128] float                               8192
// total 57344 floats = 229376 bytes

static __device__ __forceinline__ void dht32_p1(const float* __restrict__ src,
                                                float2* __restrict__ R,
                                                const float2* __restrict__ sCS32,
                                                int wwid, int lane)
{
    const int h0 = wwid * 4;
    float r1[4] = {0.f,0.f,0.f,0.f}, r2[4] = {0.f,0.f,0.f,0.f};
#pragma unroll 4
    for (int w = 0; w < 32; w += 2) {
        float4 cs = *(const float4*)&sCS32[lane * P_CS32 + w]; // (c(l,w),s(l,w),c(l,w+1),s(l,w+1))
#pragma unroll
        for (int r = 0; r < 4; ++r) {
            float2 av = *(const float2*)&src[(h0 + r) * P_F + w];
            r1[r] += av.x * cs.x + av.y * cs.z;
            r2[r] += av.x * cs.y + av.y * cs.w;
        }
    }
#pragma unroll
    for (int r = 0; r < 4; ++r)
        R[(h0 + r) * P_R + lane] = make_float2(r1[r], r2[r]);
}

static __device__ __forceinline__ void dht32_p2(const float2* __restrict__ R,
                                                const float2* __restrict__ sPM32,
                                                float* __restrict__ dst,
                                                float scale, int wwid, int lane)
{
    const int u0 = wwid * 4;
    float acc[4] = {0.f,0.f,0.f,0.f};
#pragma unroll 4
    for (int h = 0; h < 32; h += 2) {
        float2 rr0 = R[(h + 0) * P_R + lane];
        float2 rr1 = R[(h + 1) * P_R + lane];
#pragma unroll
        for (int r = 0; r < 4; ++r) {
            float4 pm = *(const float4*)&sPM32[(u0 + r) * 32 + h];
            acc[r] += pm.x * rr0.x + pm.y * rr0.y + pm.z * rr1.x + pm.w * rr1.y;
        }
    }
#pragma unroll
    for (int r = 0; r < 4; ++r)
        dst[(u0 + r) * P_F + lane] = acc[r] * scale;
}

__global__ __launch_bounds__(THREADS, 1)
void spectral_kernel(const float* __restrict__ Xg,
                     const float* __restrict__ W1g,
                     const float* __restrict__ W2g,
                     float* __restrict__ Og)
{
    extern __shared__ float sm[];
    float2* sCS   = (float2*)sm;                    // [128][34]
    float2* sPM   = sCS   + 128 * P_CS;             // [64][128]
    float2* sY12  = sPM   + 64 * 128;               // [128][34]
    float2* sPM32 = sY12  + 128 * P_Y;              // [32][32]
    float2* sCS32 = sPM32 + 32 * 32;                // [32][34]
    float2* sR12  = sCS32 + 32 * P_CS32;            // [2][32][33]
    float*  sXf   = (float*)(sR12 + 2 * 32 * P_R);  // [64][36]
    float*  sAh   = sXf + 64 * P_F;                 // [2][32][36]
    float*  sWr   = sAh + 2 * 32 * P_F;             // [2][32][36]
    float*  sX    = sWr + 2 * 32 * P_F;             // [64][128]

    const int tid  = threadIdx.x;
    const int lane = tid & 31;
    const int wid  = tid >> 5;
    const int img  = blockIdx.x;

    const float* X = Xg + (size_t)img * 16384;
    float*       O = Og + (size_t)img * 16384;

    // ---- transform tables (sincospif on exact multiples of pi) + weight preload ----
    for (int i = tid; i < 128 * 32; i += THREADS) {
        int w = i >> 5, v = i & 31;
        float s, c;
        sincospif((float)((w * v) & 127) * (1.0f / 64.0f), &s, &c);
        sCS[w * P_CS + v] = make_float2(c, s);
    }
    for (int i = tid; i < 64 * 128; i += THREADS) {
        int u = i >> 7, h = i & 127;
        int f = (u < 32) ? u : (u + 64);            // selected freqs 0..31, 96..127
        float s, c;
        sincospif((float)((f * h) & 127) * (1.0f / 64.0f), &s, &c);
        sPM[u * 128 + h] = make_float2(c + s, c - s);
    }
    for (int i = tid; i < 32 * 32; i += THREADS) {
        int u = i >> 5, h = i & 31;
        float s, c;
        sincospif((float)((u * h) & 31) * (1.0f / 16.0f), &s, &c);
        sPM32[u * 32 + h]    = make_float2(c + s, c - s);
        sCS32[u * P_CS32 + h] = make_float2(c, s); // symmetric in (u,h)
    }
    for (int i = tid; i < 2048; i += THREADS) {
        int t = i >> 10, idx = i & 1023;
        const float* Wsrc = (t == 0 ? W1g : W2g) + (size_t)img * 1024;
        sWr[t * 32 * P_F + (idx >> 5) * P_F + (idx & 31)] = Wsrc[idx];
    }
    __syncthreads();

    // ---- Stage A1: Y1[h][v] = sum_w x[h][w] cos(vw); Y2 with sin ----
    for (int pass = 0; pass < 2; ++pass) {
        const float4* src = (const float4*)(X + pass * 8192);
        float4* dst = (float4*)sX;
        for (int i = tid; i < 2048; i += THREADS) dst[i] = src[i];
        __syncthreads();

        const int r0 = wid * 4;
        float a1[4] = {0.f,0.f,0.f,0.f}, a2[4] = {0.f,0.f,0.f,0.f};
#pragma unroll 2
        for (int w = 0; w < 128; w += 4) {
            float2 cs0 = sCS[(w + 0) * P_CS + lane];
            float2 cs1 = sCS[(w + 1) * P_CS + lane];
            float2 cs2 = sCS[(w + 2) * P_CS + lane];
            float2 cs3 = sCS[(w + 3) * P_CS + lane];
#pragma unroll
            for (int r = 0; r < 4; ++r) {
                float4 xv = *(const float4*)&sX[(r0 + r) * 128 + w];
                a1[r] += xv.x * cs0.x + xv.y * cs1.x + xv.z * cs2.x + xv.w * cs3.x;
                a2[r] += xv.x * cs0.y + xv.y * cs1.y + xv.z * cs2.y + xv.w * cs3.y;
            }
        }
#pragma unroll
        for (int r = 0; r < 4; ++r)
            sY12[(pass * 64 + r0 + r) * P_Y + lane] = make_float2(a1[r], a2[r]);
        __syncthreads();
    }

    // ---- Stage A2: Xf[u][v] = (1/16384) sum_h (P Y1 + M Y2) ----
    {
        const int u0 = wid * 4;
        float b[4] = {0.f,0.f,0.f,0.f};
#pragma unroll 4
        for (int h = 0; h < 128; h += 2) {
            float2 y0 = sY12[(h + 0) * P_Y + lane];
            float2 y1 = sY12[(h + 1) * P_Y + lane];
#pragma unroll
            for (int r = 0; r < 4; ++r) {
                float4 pm = *(const float4*)&sPM[(u0 + r) * 128 + h];
                b[r] += pm.x * y0.x + pm.y * y0.y + pm.z * y1.x + pm.w * y1.y;
            }
        }
#pragma unroll
        for (int r = 0; r < 4; ++r)
            sXf[(u0 + r) * P_F + lane] = b[r] * (1.0f / 16384.0f);
    }
    __syncthreads();

    // ---- Stage B: both 32x32 spectral blocks concurrently (warp groups) ----
    {
        const int g    = wid >> 3;    // 0: block t=0 (warps 0-7), 1: block t=1 (warps 8-15)
        const int wwid = wid & 7;
        float*  aSrc = sXf  + g * 32 * P_F;
        float2* Rg   = sR12 + g * 32 * P_R;
        float*  Ahg  = sAh  + g * 32 * P_F;
        float*  Wg   = sWr  + g * 32 * P_F;

        dht32_p1(aSrc, Rg, sCS32, wwid, lane);                   __syncthreads();
        dht32_p2(Rg, sPM32, Ahg, 1.0f / 1024.0f, wwid, lane);    __syncthreads();
        dht32_p1(Wg, Rg, sCS32, wwid, lane);                     __syncthreads();
        {   // fused: Ah *= DHT32(w)/1024
            const int u0 = wwid * 4;
            float acc[4] = {0.f,0.f,0.f,0.f};
#pragma unroll 4
            for (int h = 0; h < 32; h += 2) {
                float2 rr0 = Rg[(h + 0) * P_R + lane];
                float2 rr1 = Rg[(h + 1) * P_R + lane];
#pragma unroll
                for (int r = 0; r < 4; ++r) {
                    float4 pm = *(const float4*)&sPM32[(u0 + r) * 32 + h];
                    acc[r] += pm.x * rr0.x + pm.y * rr0.y + pm.z * rr1.x + pm.w * rr1.y;
                }
            }
#pragma unroll
            for (int r = 0; r < 4; ++r) {
                int idx = (u0 + r) * P_F + lane;
                Ahg[idx] = Ahg[idx] * (acc[r] * (1.0f / 1024.0f));
            }
        }
        __syncthreads();
        dht32_p1(Ahg, Rg, sCS32, wwid, lane);                    __syncthreads();
        dht32_p2(Rg, sPM32, aSrc, 1.0f / 65536.0f, wwid, lane);  __syncthreads();
    }

    // ---- Stage C1: U1[h'][s] = sum_r P[r][h'] G[r][s]; U2 with M ----
    {
        const int hbase = wid * 8;
        float u1[2][4] = {{0.f,0.f,0.f,0.f},{0.f,0.f,0.f,0.f}};
        float u2[2][4] = {{0.f,0.f,0.f,0.f},{0.f,0.f,0.f,0.f}};
#pragma unroll 2
        for (int r = 0; r < 64; ++r) {
            float gv = sXf[r * P_F + lane];
#pragma unroll
            for (int g = 0; g < 2; ++g) {
                float4 pa = *(const float4*)&sPM[r * 128 + hbase + g * 4];
                float4 pb = *(const float4*)&sPM[r * 128 + hbase + g * 4 + 2];
                u1[g][0] += pa.x * gv; u2[g][0] += pa.y * gv;
                u1[g][1] += pa.z * gv; u2[g][1] += pa.w * gv;
                u1[g][2] += pb.x * gv; u2[g][2] += pb.y * gv;
                u1[g][3] += pb.z * gv; u2[g][3] += pb.w * gv;
            }
        }
#pragma unroll
        for (int g = 0; g < 2; ++g)
#pragma unroll
            for (int i2 = 0; i2 < 4; ++i2)
                sY12[(hbase + g * 4 + i2) * P_Y + lane] = make_float2(u1[g][i2], u2[g][i2]);
    }
    __syncthreads();

    // ---- Stage C2: y[h'][w'] = (1/2^20) sum_s (U1 cos + U2 sin)(s w') ----
    for (int tt = wid; tt < 64; tt += 16) {
        const int hb = (tt >> 2) * 8;
        const int wp = (tt & 3) * 32 + lane;
        float acc[8] = {0.f,0.f,0.f,0.f,0.f,0.f,0.f,0.f};
#pragma unroll 4
        for (int s = 0; s < 32; s += 2) {
            float4 cs = *(const float4*)&sCS[wp * P_CS + s]; // (c(wp,s),s(wp,s),c(wp,s+1),s(wp,s+1))
#pragma unroll
            for (int i2 = 0; i2 < 8; ++i2) {
                float4 uu = *(const float4*)&sY12[(hb + i2) * P_Y + s];
                acc[i2] += uu.x * cs.x + uu.y * cs.y + uu.z * cs.z + uu.w * cs.w;
            }
        }
#pragma unroll
        for (int i2 = 0; i2 < 8; ++i2)
            O[(hb + i2) * 128 + wp] = acc[i2] * (1.0f / 1048576.0f);
    }
}

extern "C" void kernel_launch(void* const* d_in, const int* in_sizes, int n_in,
                              void* d_out, int out_size)
{
    const float* x  = (const float*)d_in[0];
    const float* w1 = (const float*)d_in[1];
    const float* w2 = (const float*)d_in[2];
    float* out = (float*)d_out;

    const int smem_bytes = 57344 * 4; // 229376
    cudaFuncSetAttribute(spectral_kernel,
                         cudaFuncAttributeMaxDynamicSharedMemorySize, smem_bytes);
    spectral_kernel<<<4096, THREADS, smem_bytes>>>(x, w1, w2, out);
}

// round 4
// speedup vs baseline: 1.0432x; 1.0005x over previous
#include <cuda_runtime.h>

#define THREADS 512
#define P_CS   34   // float2 pitch, [128][34]
#define P_Y    34   // float2 pitch, [128][34]
#define P_CS32 34   // float2 pitch, [32][34]
#define P_R    33   // float2 pitch, [32][33]
#define P_F    36   // float pitch,  [.][36]

// Smem (floats):
//  sCS   0      : [128][34] float2  (cos,sin)(2pi*w*v/128)      8704
//  sPM   8704   : [64][128] float2  (cas+,cas-)(2pi*f(u)*h/128) 16384
//  sY12  25088  : [128][34] float2  stage A / C intermediates   8704
//  sPM32 33792  : [32][32]  float2  (cas+,cas-)(2pi*u*h/32)     2048
//  sCS32 35840  : [32][34]  float2  (cos,sin)(2pi*u*h/32)       2176
//  sR12  38016  : [2][32][33] float2  32-DHT scratch            4224
//  sXf   42240  : [64][36]  float   mode spectrum / G           2304
//  sAh   44544  : [2][32][36] float                             2304
//  sWr   46848  : [2][32][36] float                             2304
//  sX    49152  : [64][128] float                               8192
// total 57344 floats = 229376 bytes

static __device__ __forceinline__ void dht32_p1(const float* __restrict__ src,
                                                float2* __restrict__ R,
                                                const float2* __restrict__ sCS32,
                                                int wwid, int lane)
{
    const int h0 = wwid * 4;
    float r1[4] = {0.f,0.f,0.f,0.f}, r2[4] = {0.f,0.f,0.f,0.f};
#pragma unroll 4
    for (int w = 0; w < 32; w += 2) {
        float4 cs = *(const float4*)&sCS32[lane * P_CS32 + w]; // (c(l,w),s(l,w),c(l,w+1),s(l,w+1))
#pragma unroll
        for (int r = 0; r < 4; ++r) {
            float2 av = *(const float2*)&src[(h0 + r) * P_F + w];
            r1[r] += av.x * cs.x + av.y * cs.z;
            r2[r] += av.x * cs.y + av.y * cs.w;
        }
    }
#pragma unroll
    for (int r = 0; r < 4; ++r)
        R[(h0 + r) * P_R + lane] = make_float2(r1[r], r2[r]);
}

static __device__ __forceinline__ void dht32_p2(const float2* __restrict__ R,
                                                const float2* __restrict__ sPM32,
                                                float* __restrict__ dst,
                                                float scale, int wwid, int lane)
{
    const int u0 = wwid * 4;
    float acc[4] = {0.f,0.f,0.f,0.f};
#pragma unroll 4
    for (int h = 0; h < 32; h += 2) {
        float2 rr0 = R[(h + 0) * P_R + lane];
        float2 rr1 = R[(h + 1) * P_R + lane];
#pragma unroll
        for (int r = 0; r < 4; ++r) {
            float4 pm = *(const float4*)&sPM32[(u0 + r) * 32 + h];
            acc[r] += pm.x * rr0.x + pm.y * rr0.y + pm.z * rr1.x + pm.w * rr1.y;
        }
    }
#pragma unroll
    for (int r = 0; r < 4; ++r)
        dst[(u0 + r) * P_F + lane] = acc[r] * scale;
}

__global__ __launch_bounds__(THREADS, 1)
void spectral_kernel(const float* __restrict__ Xg,
                     const float* __restrict__ W1g,
                     const float* __restrict__ W2g,
                     float* __restrict__ Og)
{
    extern __shared__ float sm[];
    float2* sCS   = (float2*)sm;                    // [128][34]
    float2* sPM   = sCS   + 128 * P_CS;             // [64][128]
    float2* sY12  = sPM   + 64 * 128;               // [128][34]
    float2* sPM32 = sY12  + 128 * P_Y;              // [32][32]
    float2* sCS32 = sPM32 + 32 * 32;                // [32][34]
    float2* sR12  = sCS32 + 32 * P_CS32;            // [2][32][33]
    float*  sXf   = (float*)(sR12 + 2 * 32 * P_R);  // [64][36]
    float*  sAh   = sXf + 64 * P_F;                 // [2][32][36]
    float*  sWr   = sAh + 2 * 32 * P_F;             // [2][32][36]
    float*  sX    = sWr + 2 * 32 * P_F;             // [64][128]

    const int tid  = threadIdx.x;
    const int lane = tid & 31;
    const int wid  = tid >> 5;
    const int img  = blockIdx.x;

    const float* X = Xg + (size_t)img * 16384;
    float*       O = Og + (size_t)img * 16384;

    // ---- transform tables (sincospif on exact multiples of pi) + weight preload ----
    for (int i = tid; i < 128 * 32; i += THREADS) {
        int w = i >> 5, v = i & 31;
        float s, c;
        sincospif((float)((w * v) & 127) * (1.0f / 64.0f), &s, &c);
        sCS[w * P_CS + v] = make_float2(c, s);
    }
    for (int i = tid; i < 64 * 128; i += THREADS) {
        int u = i >> 7, h = i & 127;
        int f = (u < 32) ? u : (u + 64);            // selected freqs 0..31, 96..127
        float s, c;
        sincospif((float)((f * h) & 127) * (1.0f / 64.0f), &s, &c);
        sPM[u * 128 + h] = make_float2(c + s, c - s);
    }
    for (int i = tid; i < 32 * 32; i += THREADS) {
        int u = i >> 5, h = i & 31;
        float s, c;
        sincospif((float)((u * h) & 31) * (1.0f / 16.0f), &s, &c);
        sPM32[u * 32 + h]    = make_float2(c + s, c - s);
        sCS32[u * P_CS32 + h] = make_float2(c, s); // symmetric in (u,h)
    }
    for (int i = tid; i < 2048; i += THREADS) {
        int t = i >> 10, idx = i & 1023;
        const float* Wsrc = (t == 0 ? W1g : W2g) + (size_t)img * 1024;
        sWr[t * 32 * P_F + (idx >> 5) * P_F + (idx & 31)] = Wsrc[idx];
    }
    __syncthreads();

    // ---- Stage A1: Y1[h][v] = sum_w x[h][w] cos(vw); Y2 with sin ----
    for (int pass = 0; pass < 2; ++pass) {
        const float4* src = (const float4*)(X + pass * 8192);
        float4* dst = (float4*)sX;
        for (int i = tid; i < 2048; i += THREADS) dst[i] = src[i];
        __syncthreads();

        const int r0 = wid * 4;
        float a1[4] = {0.f,0.f,0.f,0.f}, a2[4] = {0.f,0.f,0.f,0.f};
#pragma unroll 2
        for (int w = 0; w < 128; w += 4) {
            float2 cs0 = sCS[(w + 0) * P_CS + lane];
            float2 cs1 = sCS[(w + 1) * P_CS + lane];
            float2 cs2 = sCS[(w + 2) * P_CS + lane];
            float2 cs3 = sCS[(w + 3) * P_CS + lane];
#pragma unroll
            for (int r = 0; r < 4; ++r) {
                float4 xv = *(const float4*)&sX[(r0 + r) * 128 + w];
                a1[r] += xv.x * cs0.x + xv.y * cs1.x + xv.z * cs2.x + xv.w * cs3.x;
                a2[r] += xv.x * cs0.y + xv.y * cs1.y + xv.z * cs2.y + xv.w * cs3.y;
            }
        }
#pragma unroll
        for (int r = 0; r < 4; ++r)
            sY12[(pass * 64 + r0 + r) * P_Y + lane] = make_float2(a1[r], a2[r]);
        __syncthreads();
    }

    // ---- Stage A2: Xf[u][v] = (1/16384) sum_h (P Y1 + M Y2) ----
    {
        const int u0 = wid * 4;
        float b[4] = {0.f,0.f,0.f,0.f};
#pragma unroll 4
        for (int h = 0; h < 128; h += 2) {
            float2 y0 = sY12[(h + 0) * P_Y + lane];
            float2 y1 = sY12[(h + 1) * P_Y + lane];
#pragma unroll
            for (int r = 0; r < 4; ++r) {
                float4 pm = *(const float4*)&sPM[(u0 + r) * 128 + h];
                b[r] += pm.x * y0.x + pm.y * y0.y + pm.z * y1.x + pm.w * y1.y;
            }
        }
#pragma unroll
        for (int r = 0; r < 4; ++r)
            sXf[(u0 + r) * P_F + lane] = b[r] * (1.0f / 16384.0f);
    }
    __syncthreads();

    // ---- Stage B: both 32x32 spectral blocks concurrently (warp groups) ----
    {
        const int g    = wid >> 3;    // 0: block t=0 (warps 0-7), 1: block t=1 (warps 8-15)
        const int wwid = wid & 7;
        float*  aSrc = sXf  + g * 32 * P_F;
        float2* Rg   = sR12 + g * 32 * P_R;
        float*  Ahg  = sAh  + g * 32 * P_F;
        float*  Wg   = sWr  + g * 32 * P_F;

        dht32_p1(aSrc, Rg, sCS32, wwid, lane);                   __syncthreads();
        dht32_p2(Rg, sPM32, Ahg, 1.0f / 1024.0f, wwid, lane);    __syncthreads();
        dht32_p1(Wg, Rg, sCS32, wwid, lane);                     __syncthreads();
        {   // fused: Ah *= DHT32(w)/1024
            const int u0 = wwid * 4;
            float acc[4] = {0.f,0.f,0.f,0.f};
#pragma unroll 4
            for (int h = 0; h < 32; h += 2) {
                float2 rr0 = Rg[(h + 0) * P_R + lane];
                float2 rr1 = Rg[(h + 1) * P_R + lane];
#pragma unroll
                for (int r = 0; r < 4; ++r) {
                    float4 pm = *(const float4*)&sPM32[(u0 + r) * 32 + h];
                    acc[r] += pm.x * rr0.x + pm.y * rr0.y + pm.z * rr1.x + pm.w * rr1.y;
                }
            }
#pragma unroll
            for (int r = 0; r < 4; ++r) {
                int idx = (u0 + r) * P_F + lane;
                Ahg[idx] = Ahg[idx] * (acc[r] * (1.0f / 1024.0f));
            }
        }
        __syncthreads();
        dht32_p1(Ahg, Rg, sCS32, wwid, lane);                    __syncthreads();
        dht32_p2(Rg, sPM32, aSrc, 1.0f / 65536.0f, wwid, lane);  __syncthreads();
    }

    // ---- Stage C1: U1[h'][s] = sum_r P[r][h'] G[r][s]; U2 with M ----
    {
        const int hbase = wid * 8;
        float u1[2][4] = {{0.f,0.f,0.f,0.f},{0.f,0.f,0.f,0.f}};
        float u2[2][4] = {{0.f,0.f,0.f,0.f},{0.f,0.f,0.f,0.f}};
#pragma unroll 2
        for (int r = 0; r < 64; ++r) {
            float gv = sXf[r * P_F + lane];
#pragma unroll
            for (int g = 0; g < 2; ++g) {
                float4 pa = *(const float4*)&sPM[r * 128 + hbase + g * 4];
                float4 pb = *(const float4*)&sPM[r * 128 + hbase + g * 4 + 2];
                u1[g][0] += pa.x * gv; u2[g][0] += pa.y * gv;
                u1[g][1] += pa.z * gv; u2[g][1] += pa.w * gv;
                u1[g][2] += pb.x * gv; u2[g][2] += pb.y * gv;
                u1[g][3] += pb.z * gv; u2[g][3] += pb.w * gv;
            }
        }
#pragma unroll
        for (int g = 0; g < 2; ++g)
#pragma unroll
            for (int i2 = 0; i2 < 4; ++i2)
                sY12[(hbase + g * 4 + i2) * P_Y + lane] = make_float2(u1[g][i2], u2[g][i2]);
    }
    __syncthreads();

    // ---- Stage C2: y[h'][w'] = (1/2^20) sum_s (U1 cos + U2 sin)(s w') ----
    for (int tt = wid; tt < 64; tt += 16) {
        const int hb = (tt >> 2) * 8;
        const int wp = (tt & 3) * 32 + lane;
        float acc[8] = {0.f,0.f,0.f,0.f,0.f,0.f,0.f,0.f};
#pragma unroll 4
        for (int s = 0; s < 32; s += 2) {
            float4 cs = *(const float4*)&sCS[wp * P_CS + s]; // (c(wp,s),s(wp,s),c(wp,s+1),s(wp,s+1))
#pragma unroll
            for (int i2 = 0; i2 < 8; ++i2) {
                float4 uu = *(const float4*)&sY12[(hb + i2) * P_Y + s];
                acc[i2] += uu.x * cs.x + uu.y * cs.y + uu.z * cs.z + uu.w * cs.w;
            }
        }
#pragma unroll
        for (int i2 = 0; i2 < 8; ++i2)
            O[(hb + i2) * 128 + wp] = acc[i2] * (1.0f / 1048576.0f);
    }
}

extern "C" void kernel_launch(void* const* d_in, const int* in_sizes, int n_in,
                              void* d_out, int out_size)
{
    const float* x  = (const float*)d_in[0];
    const float* w1 = (const float*)d_in[1];
    const float* w2 = (const float*)d_in[2];
    float* out = (float*)d_out;

    const int smem_bytes = 57344 * 4; // 229376
    cudaFuncSetAttribute(spectral_kernel,
                         cudaFuncAttributeMaxDynamicSharedMemorySize, smem_bytes);
    spectral_kernel<<<4096, THREADS, smem_bytes>>>(x, w1, w2, out);
}

// round 5
// speedup vs baseline: 1.3000x; 1.2461x over previous
#include <cuda_runtime.h>
#define THREADS 512
#define P_F 36

// float offsets in dynamic smem
#define O_CS    0        // [65][34] float2 : (cos,sin)(2pi*w*v/128), w<=64, v<=31
#define O_PMC   4420     // [33][128] float2: (cos,sin)(2pi*f(b)*h/128), f=b (b<32) or 96
#define O_SD    12868    // [128][34] float2: (S,D) then (U1,U2)
#define O_PM32  21572    // [32][32] float2
#define O_CS32  23620    // [32][34] float2
#define O_R12   25796    // [2][32][33] float2
#define O_XF    30020    // [64][36] float
#define O_AH    32324    // [2][32][36] float ; later Gp[33][36]
#define O_WR    34628    // [2][32][36] float ; later Gm[33][36]
#define O_X     36932    // [64][128] float
#define O_XE    45124    // [64][68] float
#define O_XO    49476    // [64][68] float
#define F_TOT   53828

static __device__ __forceinline__ void dht32_p1(const float* __restrict__ src,
                                                float2* __restrict__ R,
                                                const float2* __restrict__ cs32,
                                                int wwid, int lane)
{
    const int h0 = wwid * 4;
    float r1[4] = {0.f,0.f,0.f,0.f}, r2[4] = {0.f,0.f,0.f,0.f};
#pragma unroll 4
    for (int w = 0; w < 32; w += 2) {
        float4 cs = *(const float4*)&cs32[lane * 34 + w];
#pragma unroll
        for (int r = 0; r < 4; ++r) {
            float2 av = *(const float2*)&src[(h0 + r) * P_F + w];
            r1[r] += av.x * cs.x + av.y * cs.z;
            r2[r] += av.x * cs.y + av.y * cs.w;
        }
    }
#pragma unroll
    for (int r = 0; r < 4; ++r)
        R[(h0 + r) * 33 + lane] = make_float2(r1[r], r2[r]);
}

static __device__ __forceinline__ void dht32_p2(const float2* __restrict__ R,
                                                const float2* __restrict__ pm32,
                                                float* __restrict__ dst,
                                                float scale, int wwid, int lane)
{
    const int u0 = wwid * 4;
    float acc[4] = {0.f,0.f,0.f,0.f};
#pragma unroll 4
    for (int h = 0; h < 32; h += 2) {
        float2 rr0 = R[(h + 0) * 33 + lane];
        float2 rr1 = R[(h + 1) * 33 + lane];
#pragma unroll
        for (int r = 0; r < 4; ++r) {
            float4 pm = *(const float4*)&pm32[(u0 + r) * 32 + h];
            acc[r] += pm.x * rr0.x + pm.y * rr0.y + pm.z * rr1.x + pm.w * rr1.y;
        }
    }
#pragma unroll
    for (int r = 0; r < 4; ++r)
        dst[(u0 + r) * P_F + lane] = acc[r] * scale;
}

__global__ __launch_bounds__(THREADS, 1)
void spectral_kernel(const float* __restrict__ Xg,
                     const float* __restrict__ W1g,
                     const float* __restrict__ W2g,
                     float* __restrict__ Og)
{
    extern __shared__ float sm[];
    float2* sCS   = (float2*)(sm + O_CS);
    float2* sPMc  = (float2*)(sm + O_PMC);
    float2* sSD   = (float2*)(sm + O_SD);
    float2* sPM32 = (float2*)(sm + O_PM32);
    float2* sCS32 = (float2*)(sm + O_CS32);
    float2* sR12  = (float2*)(sm + O_R12);
    float*  sXf   = sm + O_XF;
    float*  sAh   = sm + O_AH;
    float*  sWr   = sm + O_WR;
    float*  sX    = sm + O_X;
    float*  sXE   = sm + O_XE;
    float*  sXO   = sm + O_XO;
    float*  sGp   = sm + O_AH;   // reuse after stage B
    float*  sGm   = sm + O_WR;

    const int tid  = threadIdx.x;
    const int lane = tid & 31;
    const int wid  = tid >> 5;
    const int img  = blockIdx.x;
    const float* X = Xg + (size_t)img * 16384;
    float*       O = Og + (size_t)img * 16384;

    // ---- tables ----
    for (int i = tid; i < 65 * 32; i += THREADS) {
        int w = i >> 5, v = i & 31;
        float s, c; sincospif((float)((w * v) & 127) * (1.0f / 64.0f), &s, &c);
        sCS[w * 34 + v] = make_float2(c, s);
    }
    for (int i = tid; i < 33 * 128; i += THREADS) {
        int b = i >> 7, h = i & 127;
        int f = (b < 32) ? b : 96;
        float s, c; sincospif((float)((f * h) & 127) * (1.0f / 64.0f), &s, &c);
        sPMc[b * 128 + h] = make_float2(c, s);
    }
    for (int i = tid; i < 32 * 32; i += THREADS) {
        int u = i >> 5, h = i & 31;
        float s, c; sincospif((float)((u * h) & 31) * (1.0f / 16.0f), &s, &c);
        sPM32[u * 32 + h] = make_float2(c + s, c - s);
        sCS32[u * 34 + h] = make_float2(c, s);
    }
    for (int i = tid; i < 2048; i += THREADS) {
        int t = i >> 10, idx = i & 1023;
        const float* Wsrc = (t == 0 ? W1g : W2g) + (size_t)img * 1024;
        sWr[t * 32 * P_F + (idx >> 5) * P_F + (idx & 31)] = Wsrc[idx];
    }
    __syncthreads();

    // ---- Stage A1 (folded): S,D = Y1+-Y2 ----
    for (int pass = 0; pass < 2; ++pass) {
        const float4* src = (const float4*)(X + pass * 8192);
        float4* dst = (float4*)sX;
        for (int i = tid; i < 2048; i += THREADS) dst[i] = src[i];
        __syncthreads();
        for (int i = tid; i < 64 * 64; i += THREADS) {
            int h = i >> 6, w = i & 63;
            float a = sX[h * 128 + w];
            if (w == 0) { sXE[h * 68] = a; sXO[h * 68] = 0.f; }
            else {
                float b = sX[h * 128 + 128 - w];
                sXE[h * 68 + w] = a + b; sXO[h * 68 + w] = a - b;
            }
        }
        for (int i = tid; i < 64; i += THREADS) {
            sXE[i * 68 + 64] = sX[i * 128 + 64]; sXO[i * 68 + 64] = 0.f;
        }
        __syncthreads();

        const int r0 = wid * 4;
        float a1[4] = {0.f,0.f,0.f,0.f}, a2[4] = {0.f,0.f,0.f,0.f};
#pragma unroll 4
        for (int w = 0; w < 64; w += 4) {
            float2 cs0 = sCS[(w + 0) * 34 + lane];
            float2 cs1 = sCS[(w + 1) * 34 + lane];
            float2 cs2 = sCS[(w + 2) * 34 + lane];
            float2 cs3 = sCS[(w + 3) * 34 + lane];
#pragma unroll
            for (int r = 0; r < 4; ++r) {
                float4 e = *(const float4*)&sXE[(r0 + r) * 68 + w];
                float4 o = *(const float4*)&sXO[(r0 + r) * 68 + w];
                a1[r] += e.x * cs0.x + e.y * cs1.x + e.z * cs2.x + e.w * cs3.x;
                a2[r] += o.x * cs0.y + o.y * cs1.y + o.z * cs2.y + o.w * cs3.y;
            }
        }
        {
            float2 cs = sCS[64 * 34 + lane];
#pragma unroll
            for (int r = 0; r < 4; ++r) a1[r] += sXE[(r0 + r) * 68 + 64] * cs.x;
        }
#pragma unroll
        for (int r = 0; r < 4; ++r)
            sSD[(pass * 64 + r0 + r) * 34 + lane] = make_float2(a1[r] + a2[r], a1[r] - a2[r]);
        __syncthreads();
    }

    // ---- Stage A2 (freq-paired): Xf ----
    {
        const int b0 = wid * 2, b1 = wid * 2 + 1;
        float C0=0.f,S0=0.f,C1=0.f,S1=0.f,C2a=0.f,S2a=0.f;
#pragma unroll 4
        for (int h = 0; h < 128; h += 2) {
            float4 p0 = *(const float4*)&sPMc[b0 * 128 + h];
            float4 p1 = *(const float4*)&sPMc[b1 * 128 + h];
            float4 p2 = *(const float4*)&sPMc[32 * 128 + h];
            float2 d0 = sSD[(h + 0) * 34 + lane];
            float2 d1 = sSD[(h + 1) * 34 + lane];
            C0 += p0.x * d0.x + p0.z * d1.x;  S0 += p0.y * d0.y + p0.w * d1.y;
            C1 += p1.x * d0.x + p1.z * d1.x;  S1 += p1.y * d0.y + p1.w * d1.y;
            C2a += p2.x * d0.x + p2.z * d1.x; S2a += p2.y * d0.y + p2.w * d1.y;
        }
        const float sc = 1.0f / 16384.0f;
        sXf[b0 * P_F + lane] = (C0 + S0) * sc;
        if (b0 >= 1) sXf[(64 - b0) * P_F + lane] = (C0 - S0) * sc;
        sXf[b1 * P_F + lane] = (C1 + S1) * sc;
        sXf[(64 - b1) * P_F + lane] = (C1 - S1) * sc;
        if (wid == 0) sXf[32 * P_F + lane] = (C2a + S2a) * sc;
    }
    __syncthreads();

    // ---- Stage B (unchanged): two 32x32 spectral blocks ----
    {
        const int g = wid >> 3, wwid = wid & 7;
        float*  aSrc = sXf  + g * 32 * P_F;
        float2* Rg   = sR12 + g * 32 * 33;
        float*  Ahg  = sAh  + g * 32 * P_F;
        float*  Wg   = sWr  + g * 32 * P_F;

        dht32_p1(aSrc, Rg, sCS32, wwid, lane);                   __syncthreads();
        dht32_p2(Rg, sPM32, Ahg, 1.0f / 1024.0f, wwid, lane);    __syncthreads();
        dht32_p1(Wg, Rg, sCS32, wwid, lane);                     __syncthreads();
        {
            const int u0 = wwid * 4;
            float acc[4] = {0.f,0.f,0.f,0.f};
#pragma unroll 4
            for (int h = 0; h < 32; h += 2) {
                float2 rr0 = Rg[(h + 0) * 33 + lane];
                float2 rr1 = Rg[(h + 1) * 33 + lane];
#pragma unroll
                for (int r = 0; r < 4; ++r) {
                    float4 pm = *(const float4*)&sPM32[(u0 + r) * 32 + h];
                    acc[r] += pm.x * rr0.x + pm.y * rr0.y + pm.z * rr1.x + pm.w * rr1.y;
                }
            }
#pragma unroll
            for (int r = 0; r < 4; ++r) {
                int idx = (u0 + r) * P_F + lane;
                Ahg[idx] = Ahg[idx] * (acc[r] * (1.0f / 1024.0f));
            }
        }
        __syncthreads();
        dht32_p1(Ahg, Rg, sCS32, wwid, lane);                    __syncthreads();
        dht32_p2(Rg, sPM32, aSrc, 1.0f / 65536.0f, wwid, lane);  __syncthreads();
    }

    // ---- Stage C1 (freq-paired): U1,U2 -> sSD ----
    for (int i = tid; i < 33 * 32; i += THREADS) {
        int b = i >> 5, s = i & 31;
        float gp, gm;
        if (b == 0)      { gp = sXf[s];              gm = 0.f; }
        else if (b == 32){ gp = sXf[32 * P_F + s];   gm = gp;  }
        else {
            float xa = sXf[b * P_F + s], xb = sXf[(64 - b) * P_F + s];
            gp = xa + xb; gm = xa - xb;
        }
        sGp[b * P_F + s] = gp; sGm[b * P_F + s] = gm;
    }
    __syncthreads();
    {
        const int hb = wid * 8;
        float Uc[8] = {0.f,0.f,0.f,0.f,0.f,0.f,0.f,0.f};
        float Us[8] = {0.f,0.f,0.f,0.f,0.f,0.f,0.f,0.f};
#pragma unroll 1
        for (int b = 0; b < 33; ++b) {
            float gp = sGp[b * P_F + lane];
            float gm = sGm[b * P_F + lane];
#pragma unroll
            for (int j = 0; j < 8; j += 2) {
                float4 p = *(const float4*)&sPMc[b * 128 + hb + j];
                Uc[j]     += p.x * gp;  Us[j]     += p.y * gm;
                Uc[j + 1] += p.z * gp;  Us[j + 1] += p.w * gm;
            }
        }
#pragma unroll
        for (int j = 0; j < 8; ++j)
            sSD[(hb + j) * 34 + lane] = make_float2(Uc[j] + Us[j], Uc[j] - Us[j]);
    }
    __syncthreads();

    // ---- Stage C2 (w'-folded) ----
    {
        const int hb = wid * 8;
        const float sc = 1.0f / 1048576.0f;
        for (int c = 0; c < 2; ++c) {
            const int wp = c * 32 + lane;
            float A[8] = {0.f,0.f,0.f,0.f,0.f,0.f,0.f,0.f};
            float Bv[8] = {0.f,0.f,0.f,0.f,0.f,0.f,0.f,0.f};
#pragma unroll 4
            for (int s = 0; s < 32; s += 2) {
                float4 cs = *(const float4*)&sCS[wp * 34 + s];
#pragma unroll
                for (int j = 0; j < 8; ++j) {
                    float4 uu = *(const float4*)&sSD[(hb + j) * 34 + s];
                    A[j]  += uu.x * cs.x + uu.z * cs.z;
                    Bv[j] += uu.y * cs.y + uu.w * cs.w;
                }
            }
#pragma unroll
            for (int j = 0; j < 8; ++j) {
                O[(hb + j) * 128 + wp] = (A[j] + Bv[j]) * sc;
                if (wp) O[(hb + j) * 128 + (128 - wp)] = (A[j] - Bv[j]) * sc;
            }
        }
    }
    if (tid < 128) {
        float acc = 0.f;
#pragma unroll 4
        for (int s = 0; s < 32; s += 2)
            acc += sSD[tid * 34 + s].x - sSD[tid * 34 + s + 1].x;
        O[tid * 128 + 64] = acc * (1.0f / 1048576.0f);
    }
}

extern "C" void kernel_launch(void* const* d_in, const int* in_sizes, int n_in,
                              void* d_out, int out_size)
{
    const float* x  = (const float*)d_in[0];
    const float* w1 = (const float*)d_in[1];
    const float* w2 = (const float*)d_in[2];
    float* out = (float*)d_out;

    const int smem_bytes = F_TOT * 4; // 215312
    cudaFuncSetAttribute(spectral_kernel,
                         cudaFuncAttributeMaxDynamicSharedMemorySize, smem_bytes);
    spectral_kernel<<<4096, THREADS, smem_bytes>>>(x, w1, w2, out);
}

// round 6
// speedup vs baseline: 1.3770x; 1.0593x over previous
#include <cuda_runtime.h>
#define THREADS 512
#define P_F 36

// float offsets in dynamic smem
#define O_CS    0        // [65][34] float2 : (cos,sin)(2pi*w*v/128), w<=64, v<=31
#define O_PMC   4420     // [33][128] float2: (cos,sin)(2pi*f(b)*h/128), f=b or 96
#define O_SD    12868    // [128][34] float2: (S,D) then (U1,U2)
#define O_PM32  21572    // [32][32] float2
#define O_CS32  23620    // [32][34] float2
#define O_R12   25796    // [2][32][33] float2
#define O_XF    30020    // [64][36] float
#define O_AH    32324    // [2][32][36] float ; later Gp[33][36]
#define O_WR    34628    // [2][32][36] float ; later Gm[33][36]
#define O_XE    36932    // [128][68] float  ; later sFD2 [32][66] float2
#define O_XO    45636    // [128][68] float
#define F_TOT   54340

static __device__ __forceinline__ void dht32_p1(const float* __restrict__ src,
                                                float2* __restrict__ R,
                                                const float2* __restrict__ cs32,
                                                int wwid, int lane)
{
    const int h0 = wwid * 4;
    float r1[4] = {0.f,0.f,0.f,0.f}, r2[4] = {0.f,0.f,0.f,0.f};
#pragma unroll 4
    for (int w = 0; w < 32; w += 2) {
        float4 cs = *(const float4*)&cs32[lane * 34 + w];
#pragma unroll
        for (int r = 0; r < 4; ++r) {
            float2 av = *(const float2*)&src[(h0 + r) * P_F + w];
            r1[r] += av.x * cs.x + av.y * cs.z;
            r2[r] += av.x * cs.y + av.y * cs.w;
        }
    }
#pragma unroll
    for (int r = 0; r < 4; ++r)
        R[(h0 + r) * 33 + lane] = make_float2(r1[r], r2[r]);
}

static __device__ __forceinline__ void dht32_p2(const float2* __restrict__ R,
                                                const float2* __restrict__ pm32,
                                                float* __restrict__ dst,
                                                float scale, int wwid, int lane)
{
    const int u0 = wwid * 4;
    float acc[4] = {0.f,0.f,0.f,0.f};
#pragma unroll 4
    for (int h = 0; h < 32; h += 2) {
        float2 rr0 = R[(h + 0) * 33 + lane];
        float2 rr1 = R[(h + 1) * 33 + lane];
#pragma unroll
        for (int r = 0; r < 4; ++r) {
            float4 pm = *(const float4*)&pm32[(u0 + r) * 32 + h];
            acc[r] += pm.x * rr0.x + pm.y * rr0.y + pm.z * rr1.x + pm.w * rr1.y;
        }
    }
#pragma unroll
    for (int r = 0; r < 4; ++r)
        dst[(u0 + r) * P_F + lane] = acc[r] * scale;
}

__global__ __launch_bounds__(THREADS, 1)
void spectral_kernel(const float* __restrict__ Xg,
                     const float* __restrict__ W1g,
                     const float* __restrict__ W2g,
                     float* __restrict__ Og)
{
    extern __shared__ float sm[];
    float2* sCS   = (float2*)(sm + O_CS);
    float2* sPMc  = (float2*)(sm + O_PMC);
    float2* sSD   = (float2*)(sm + O_SD);
    float2* sPM32 = (float2*)(sm + O_PM32);
    float2* sCS32 = (float2*)(sm + O_CS32);
    float2* sR12  = (float2*)(sm + O_R12);
    float*  sXf   = sm + O_XF;
    float*  sAh   = sm + O_AH;
    float*  sWr   = sm + O_WR;
    float*  sXE   = sm + O_XE;
    float*  sXO   = sm + O_XO;
    float2* sFD2  = (float2*)(sm + O_XE);   // reuse after A1
    float*  sGp   = sm + O_AH;              // reuse after stage B
    float*  sGm   = sm + O_WR;

    const int tid  = threadIdx.x;
    const int lane = tid & 31;
    const int wid  = tid >> 5;
    const int img  = blockIdx.x;
    const float* X = Xg + (size_t)img * 16384;
    float*       O = Og + (size_t)img * 16384;

    // ---- tables + weight preload ----
    for (int i = tid; i < 65 * 32; i += THREADS) {
        int w = i >> 5, v = i & 31;
        float s, c; sincospif((float)((w * v) & 127) * (1.0f / 64.0f), &s, &c);
        sCS[w * 34 + v] = make_float2(c, s);
    }
    for (int i = tid; i < 33 * 128; i += THREADS) {
        int b = i >> 7, h = i & 127;
        int f = (b < 32) ? b : 96;
        float s, c; sincospif((float)((f * h) & 127) * (1.0f / 64.0f), &s, &c);
        sPMc[b * 128 + h] = make_float2(c, s);
    }
    for (int i = tid; i < 32 * 32; i += THREADS) {
        int u = i >> 5, h = i & 31;
        float s, c; sincospif((float)((u * h) & 31) * (1.0f / 16.0f), &s, &c);
        sPM32[u * 32 + h] = make_float2(c + s, c - s);
        sCS32[u * 34 + h] = make_float2(c, s);
    }
    for (int i = tid; i < 2048; i += THREADS) {
        int t = i >> 10, idx = i & 1023;
        const float* Wsrc = (t == 0 ? W1g : W2g) + (size_t)img * 1024;
        sWr[t * 32 * P_F + (idx >> 5) * P_F + (idx & 31)] = Wsrc[idx];
    }
    // ---- A1 fold straight from gmem ----
    for (int i = tid; i < 128 * 64; i += THREADS) {
        int h = i >> 6, w = i & 63;
        float a = X[h * 128 + w];
        float e, o;
        if (w == 0) { e = a; o = 0.f; }
        else { float b = X[h * 128 + 128 - w]; e = a + b; o = a - b; }
        sXE[h * 68 + w] = e; sXO[h * 68 + w] = o;
    }
    for (int h = tid; h < 128; h += THREADS) sXE[h * 68 + 64] = X[h * 128 + 64];
    __syncthreads();

    // ---- Stage A1 (single shot, 8 rows/warp): S,D = Y1+-Y2 ----
    {
        const int r0 = wid * 8;
        float a1[8] = {0,0,0,0,0,0,0,0}, a2[8] = {0,0,0,0,0,0,0,0};
#pragma unroll 2
        for (int w = 0; w < 64; w += 4) {
            float2 cs0 = sCS[(w + 0) * 34 + lane];
            float2 cs1 = sCS[(w + 1) * 34 + lane];
            float2 cs2 = sCS[(w + 2) * 34 + lane];
            float2 cs3 = sCS[(w + 3) * 34 + lane];
#pragma unroll
            for (int r = 0; r < 8; ++r) {
                float4 e = *(const float4*)&sXE[(r0 + r) * 68 + w];
                float4 o = *(const float4*)&sXO[(r0 + r) * 68 + w];
                a1[r] += e.x * cs0.x + e.y * cs1.x + e.z * cs2.x + e.w * cs3.x;
                a2[r] += o.x * cs0.y + o.y * cs1.y + o.z * cs2.y + o.w * cs3.y;
            }
        }
        {
            float2 cs = sCS[64 * 34 + lane];
#pragma unroll
            for (int r = 0; r < 8; ++r) a1[r] += sXE[(r0 + r) * 68 + 64] * cs.x;
        }
#pragma unroll
        for (int r = 0; r < 8; ++r)
            sSD[(r0 + r) * 34 + lane] = make_float2(a1[r] + a2[r], a1[r] - a2[r]);
    }
    __syncthreads();

    // ---- A2 fold over h (cos even / sin odd): sFD2[v][h] = (S+, D-) ----
    for (int i = tid; i < 32 * 65; i += THREADS) {
        int v = i / 65, h = i - v * 65;
        float2 a = sSD[h * 34 + v];
        float sp, dm;
        if (h == 0 || h == 64) { sp = a.x; dm = 0.f; }
        else { float2 b = sSD[(128 - h) * 34 + v]; sp = a.x + b.x; dm = a.y - b.y; }
        sFD2[v * 66 + h] = make_float2(sp, dm);
    }
    __syncthreads();

    // ---- Stage A2 (freq-paired + h-folded): Xf ----
    {
        const int b0 = wid * 2, b1 = wid * 2 + 1;
        float C0=0.f,S0=0.f,C1=0.f,S1=0.f,C2a=0.f,S2a=0.f;
#pragma unroll 4
        for (int h = 0; h < 64; h += 2) {
            float4 p0 = *(const float4*)&sPMc[b0 * 128 + h];
            float4 p1 = *(const float4*)&sPMc[b1 * 128 + h];
            float4 p2 = *(const float4*)&sPMc[32 * 128 + h];
            float4 d  = *(const float4*)&sFD2[lane * 66 + h]; // (S+_h, D-_h, S+_h1, D-_h1)
            C0 += p0.x * d.x + p0.z * d.z;  S0 += p0.y * d.y + p0.w * d.w;
            C1 += p1.x * d.x + p1.z * d.z;  S1 += p1.y * d.y + p1.w * d.w;
            C2a += p2.x * d.x + p2.z * d.z; S2a += p2.y * d.y + p2.w * d.w;
        }
        {   // h = 64 tail (D- is 0 there)
            float2 d = sFD2[lane * 66 + 64];
            C0  += sPMc[b0 * 128 + 64].x * d.x;
            C1  += sPMc[b1 * 128 + 64].x * d.x;
            C2a += sPMc[32 * 128 + 64].x * d.x;
        }
        const float sc = 1.0f / 16384.0f;
        sXf[b0 * P_F + lane] = (C0 + S0) * sc;
        if (b0 >= 1) sXf[(64 - b0) * P_F + lane] = (C0 - S0) * sc;
        sXf[b1 * P_F + lane] = (C1 + S1) * sc;
        sXf[(64 - b1) * P_F + lane] = (C1 - S1) * sc;
        if (wid == 0) sXf[32 * P_F + lane] = (C2a + S2a) * sc;
    }
    __syncthreads();

    // ---- Stage B (unchanged): two 32x32 spectral blocks ----
    {
        const int g = wid >> 3, wwid = wid & 7;
        float*  aSrc = sXf  + g * 32 * P_F;
        float2* Rg   = sR12 + g * 32 * 33;
        float*  Ahg  = sAh  + g * 32 * P_F;
        float*  Wg   = sWr  + g * 32 * P_F;

        dht32_p1(aSrc, Rg, sCS32, wwid, lane);                   __syncthreads();
        dht32_p2(Rg, sPM32, Ahg, 1.0f / 1024.0f, wwid, lane);    __syncthreads();
        dht32_p1(Wg, Rg, sCS32, wwid, lane);                     __syncthreads();
        {
            const int u0 = wwid * 4;
            float acc[4] = {0.f,0.f,0.f,0.f};
#pragma unroll 4
            for (int h = 0; h < 32; h += 2) {
                float2 rr0 = Rg[(h + 0) * 33 + lane];
                float2 rr1 = Rg[(h + 1) * 33 + lane];
#pragma unroll
                for (int r = 0; r < 4; ++r) {
                    float4 pm = *(const float4*)&sPM32[(u0 + r) * 32 + h];
                    acc[r] += pm.x * rr0.x + pm.y * rr0.y + pm.z * rr1.x + pm.w * rr1.y;
                }
            }
#pragma unroll
            for (int r = 0; r < 4; ++r) {
                int idx = (u0 + r) * P_F + lane;
                Ahg[idx] = Ahg[idx] * (acc[r] * (1.0f / 1024.0f));
            }
        }
        __syncthreads();
        dht32_p1(Ahg, Rg, sCS32, wwid, lane);                    __syncthreads();
        dht32_p2(Rg, sPM32, aSrc, 1.0f / 65536.0f, wwid, lane);  __syncthreads();
    }

    // ---- Stage C1 (freq-paired): U1,U2 -> sSD ----
    for (int i = tid; i < 33 * 32; i += THREADS) {
        int b = i >> 5, s = i & 31;
        float gp, gm;
        if (b == 0)      { gp = sXf[s];              gm = 0.f; }
        else if (b == 32){ gp = sXf[32 * P_F + s];   gm = gp;  }
        else {
            float xa = sXf[b * P_F + s], xb = sXf[(64 - b) * P_F + s];
            gp = xa + xb; gm = xa - xb;
        }
        sGp[b * P_F + s] = gp; sGm[b * P_F + s] = gm;
    }
    __syncthreads();
    {
        const int hb = wid * 8;
        float Uc[8] = {0.f,0.f,0.f,0.f,0.f,0.f,0.f,0.f};
        float Us[8] = {0.f,0.f,0.f,0.f,0.f,0.f,0.f,0.f};
#pragma unroll 1
        for (int b = 0; b < 33; ++b) {
            float gp = sGp[b * P_F + lane];
            float gm = sGm[b * P_F + lane];
#pragma unroll
            for (int j = 0; j < 8; j += 2) {
                float4 p = *(const float4*)&sPMc[b * 128 + hb + j];
                Uc[j]     += p.x * gp;  Us[j]     += p.y * gm;
                Uc[j + 1] += p.z * gp;  Us[j + 1] += p.w * gm;
            }
        }
#pragma unroll
        for (int j = 0; j < 8; ++j)
            sSD[(hb + j) * 34 + lane] = make_float2(Uc[j] + Us[j], Uc[j] - Us[j]);
    }
    __syncthreads();

    // ---- Stage C2 (w'-folded + partner-column): lane covers wp=lane and wq ----
    {
        const int hb = wid * 8;
        const float sc = 1.0f / 1048576.0f;
        const int wp = lane;
        float A[8]  = {0,0,0,0,0,0,0,0}, B[8]  = {0,0,0,0,0,0,0,0};
        float Ap[8] = {0,0,0,0,0,0,0,0}, Bp[8] = {0,0,0,0,0,0,0,0};
#pragma unroll 4
        for (int s = 0; s < 32; s += 2) {
            float4 cs = *(const float4*)&sCS[wp * 34 + s];
            float4 cp;
            if (lane == 0) cp = *(const float4*)&sCS[32 * 34 + s];
            else           cp = make_float4(cs.x, -cs.y, -cs.z, cs.w);
#pragma unroll
            for (int j = 0; j < 8; ++j) {
                float4 uu = *(const float4*)&sSD[(hb + j) * 34 + s];
                A[j]  += uu.x * cs.x + uu.z * cs.z;
                B[j]  += uu.y * cs.y + uu.w * cs.w;
                Ap[j] += uu.x * cp.x + uu.z * cp.z;
                Bp[j] += uu.y * cp.y + uu.w * cp.w;
            }
        }
        const int wq = lane ? (64 - lane) : 32;
#pragma unroll
        for (int j = 0; j < 8; ++j) {
            O[(hb + j) * 128 + wp] = (A[j] + B[j]) * sc;
            if (wp) O[(hb + j) * 128 + (128 - wp)] = (A[j] - B[j]) * sc;
            O[(hb + j) * 128 + wq] = (Ap[j] + Bp[j]) * sc;
            O[(hb + j) * 128 + (128 - wq)] = (Ap[j] - Bp[j]) * sc;
        }
    }
    if (tid < 128) {   // w' = 64 column: (-1)^s weights
        float acc = 0.f;
#pragma unroll 4
        for (int s = 0; s < 32; s += 2)
            acc += sSD[tid * 34 + s].x - sSD[tid * 34 + s + 1].x;
        O[tid * 128 + 64] = acc * (1.0f / 1048576.0f);
    }
}

extern "C" void kernel_launch(void* const* d_in, const int* in_sizes, int n_in,
                              void* d_out, int out_size)
{
    const float* x  = (const float*)d_in[0];
    const float* w1 = (const float*)d_in[1];
    const float* w2 = (const float*)d_in[2];
    float* out = (float*)d_out;

    const int smem_bytes = F_TOT * 4; // 217360
    cudaFuncSetAttribute(spectral_kernel,
                         cudaFuncAttributeMaxDynamicSharedMemorySize, smem_bytes);
    spectral_kernel<<<4096, THREADS, smem_bytes>>>(x, w1, w2, out);
}

// round 7
// speedup vs baseline: 1.8729x; 1.3601x over previous
#include <cuda_runtime.h>
#define THREADS 512

// float offsets in dynamic smem (total 26184 floats = 104736 B -> 2 CTAs/SM)
#define O_CS   0       // [65][34] float2 : (cos,sin)(2pi*w*v/128), w<=64, v<=31   (4420 f)
#define O_PMC  4420    // [33][66] float2 : (cos,sin)(2pi*f(b)*h/128), h<=64       (4356 f)
#define O_SD   8776    // region 8704 f : SD[128][34]f2 | {WR,AH,R1} | {U,Gp,Gm}
#define O_BIG  17480   // region 8704 f : {XE,XO} | {FD2,Xf,CS32} | {R2,Xf,CS32}
#define F_TOT  26184

// region-internal float offsets
#define SD_WR   0
#define SD_AH   2176
#define SD_R1   4352
#define SD_GP   4420
#define SD_GM   5542
#define BG_XO   4352
#define BG_XF   4352
#define BG_CS32 6528

template<int NR>
static __device__ __forceinline__ void dht32_p1(const float* __restrict__ src,
                                                float2* __restrict__ R,
                                                const float2* __restrict__ cs32,
                                                int h0, int lane)
{
    float r1[NR], r2[NR];
#pragma unroll
    for (int r = 0; r < NR; ++r) { r1[r] = 0.f; r2[r] = 0.f; }
#pragma unroll 4
    for (int w = 0; w < 32; w += 2) {
        float4 cs = *(const float4*)&cs32[lane * 34 + w];
#pragma unroll
        for (int r = 0; r < NR; ++r) {
            float2 av = *(const float2*)&src[(h0 + r) * 34 + w];
            r1[r] += av.x * cs.x + av.y * cs.z;
            r2[r] += av.x * cs.y + av.y * cs.w;
        }
    }
#pragma unroll
    for (int r = 0; r < NR; ++r)
        R[(h0 + r) * 33 + lane] = make_float2(r1[r], r2[r]);
}

template<int NR>
static __device__ __forceinline__ void dht32_p2(const float2* __restrict__ R,
                                                const float2* __restrict__ cs32,
                                                float* __restrict__ dst,
                                                float scale, int u0, int lane)
{
    float acc[NR];
#pragma unroll
    for (int r = 0; r < NR; ++r) acc[r] = 0.f;
#pragma unroll 4
    for (int h = 0; h < 32; h += 2) {
        float2 a = R[h * 33 + lane], b = R[(h + 1) * 33 + lane];
        float p0 = a.x + a.y, m0 = a.x - a.y;
        float p1 = b.x + b.y, m1 = b.x - b.y;
#pragma unroll
        for (int r = 0; r < NR; ++r) {
            float4 cs = *(const float4*)&cs32[(u0 + r) * 34 + h];
            acc[r] += cs.x * p0 + cs.y * m0 + cs.z * p1 + cs.w * m1;
        }
    }
#pragma unroll
    for (int r = 0; r < NR; ++r)
        dst[(u0 + r) * 34 + lane] = acc[r] * scale;
}

static __device__ __forceinline__ void dht32_p1m(const float* __restrict__ A,
                                                 const float* __restrict__ W,
                                                 float2* __restrict__ R,
                                                 const float2* __restrict__ cs32,
                                                 int h0, int lane)
{
    float r1[4] = {0,0,0,0}, r2[4] = {0,0,0,0};
#pragma unroll 4
    for (int w = 0; w < 32; w += 2) {
        float4 cs = *(const float4*)&cs32[lane * 34 + w];
#pragma unroll
        for (int r = 0; r < 4; ++r) {
            float2 a  = *(const float2*)&A[(h0 + r) * 34 + w];
            float2 ww = *(const float2*)&W[(h0 + r) * 34 + w];
            float v0 = a.x * ww.x, v1 = a.y * ww.y;
            r1[r] += v0 * cs.x + v1 * cs.z;
            r2[r] += v0 * cs.y + v1 * cs.w;
        }
    }
#pragma unroll
    for (int r = 0; r < 4; ++r)
        R[(h0 + r) * 33 + lane] = make_float2(r1[r], r2[r]);
}

__global__ __launch_bounds__(THREADS, 2)
void spectral_kernel(const float* __restrict__ Xg,
                     const float* __restrict__ W1g,
                     const float* __restrict__ W2g,
                     float* __restrict__ Og)
{
    extern __shared__ float sm[];
    float2* sCS   = (float2*)(sm + O_CS);
    float2* sPMc  = (float2*)(sm + O_PMC);
    float2* sSD   = (float2*)(sm + O_SD);
    float*  sWR   = sm + O_SD + SD_WR;
    float*  sAH   = sm + O_SD + SD_AH;
    float2* sR1   = (float2*)(sm + O_SD + SD_R1);
    float2* sU    = (float2*)(sm + O_SD);
    float*  sGp   = sm + O_SD + SD_GP;
    float*  sGm   = sm + O_SD + SD_GM;
    float*  sXE   = sm + O_BIG;
    float*  sXO   = sm + O_BIG + BG_XO;
    float2* sFD2  = (float2*)(sm + O_BIG);
    float*  sXf   = sm + O_BIG + BG_XF;
    float2* sCS32 = (float2*)(sm + O_BIG + BG_CS32);
    float2* sR2   = (float2*)(sm + O_BIG);

    const int tid  = threadIdx.x;
    const int lane = tid & 31;
    const int wid  = tid >> 5;
    const int img  = blockIdx.x;
    const float* X = Xg + (size_t)img * 16384;
    float*       O = Og + (size_t)img * 16384;

    // ---- persistent tables ----
    for (int i = tid; i < 65 * 32; i += THREADS) {
        int w = i >> 5, v = i & 31;
        float s, c; sincospif((float)((w * v) & 127) * (1.0f / 64.0f), &s, &c);
        sCS[w * 34 + v] = make_float2(c, s);
    }
    for (int i = tid; i < 33 * 65; i += THREADS) {
        int b = i / 65, h = i - b * 65;
        int f = (b < 32) ? b : 96;
        float s, c; sincospif((float)((f * h) & 127) * (1.0f / 64.0f), &s, &c);
        sPMc[b * 66 + h] = make_float2(c, s);
    }

    // ---- Stage A1, two passes of 64 rows ----
#pragma unroll 1
    for (int pass = 0; pass < 2; ++pass) {
        for (int i = tid; i < 64 * 64; i += THREADS) {
            int hl = i >> 6, w = i & 63;
            int h = pass * 64 + hl;
            float a = X[h * 128 + w];
            float e, o;
            if (w == 0) { e = a; o = 0.f; }
            else { float b = X[h * 128 + 128 - w]; e = a + b; o = a - b; }
            sXE[hl * 68 + w] = e; sXO[hl * 68 + w] = o;
        }
        if (tid < 64) sXE[tid * 68 + 64] = X[(pass * 64 + tid) * 128 + 64];
        __syncthreads();

        const int r0 = wid * 4;
        float a1[4] = {0,0,0,0}, a2[4] = {0,0,0,0};
#pragma unroll 2
        for (int w = 0; w < 64; w += 4) {
            float2 cs0 = sCS[(w + 0) * 34 + lane];
            float2 cs1 = sCS[(w + 1) * 34 + lane];
            float2 cs2 = sCS[(w + 2) * 34 + lane];
            float2 cs3 = sCS[(w + 3) * 34 + lane];
#pragma unroll
            for (int r = 0; r < 4; ++r) {
                float4 e = *(const float4*)&sXE[(r0 + r) * 68 + w];
                float4 o = *(const float4*)&sXO[(r0 + r) * 68 + w];
                a1[r] += e.x * cs0.x + e.y * cs1.x + e.z * cs2.x + e.w * cs3.x;
                a2[r] += o.x * cs0.y + o.y * cs1.y + o.z * cs2.y + o.w * cs3.y;
            }
        }
        {
            float2 cs = sCS[64 * 34 + lane];
#pragma unroll
            for (int r = 0; r < 4; ++r) a1[r] += sXE[(r0 + r) * 68 + 64] * cs.x;
        }
#pragma unroll
        for (int r = 0; r < 4; ++r)
            sSD[(pass * 64 + r0 + r) * 34 + lane] = make_float2(a1[r] + a2[r], a1[r] - a2[r]);
        __syncthreads();
    }

    // ---- fold SD -> FD2 ; build CS32 ----
    for (int i = tid; i < 32 * 65; i += THREADS) {
        int v = i / 65, h = i - v * 65;
        float2 a = sSD[h * 34 + v];
        float sp, dm;
        if (h == 0 || h == 64) { sp = a.x; dm = 0.f; }
        else { float2 b = sSD[(128 - h) * 34 + v]; sp = a.x + b.x; dm = a.y - b.y; }
        sFD2[v * 66 + h] = make_float2(sp, dm);
    }
    for (int i = tid; i < 32 * 32; i += THREADS) {
        int u = i >> 5, h = i & 31;
        float s, c; sincospif((float)((u * h) & 31) * (1.0f / 16.0f), &s, &c);
        sCS32[u * 34 + h] = make_float2(c, s);
    }
    __syncthreads();

    // ---- Stage A2 (writes Xf) + weight load (SD region dead) ----
    for (int i = tid; i < 2048; i += THREADS) {
        int t = i >> 10, idx = i & 1023;
        const float* Wsrc = (t == 0 ? W1g : W2g) + (size_t)img * 1024;
        sWR[t * 32 * 34 + (idx >> 5) * 34 + (idx & 31)] = Wsrc[idx];
    }
    {
        const int b0 = wid * 2, b1 = wid * 2 + 1;
        float C0=0.f,S0=0.f,C1=0.f,S1=0.f,C2a=0.f,S2a=0.f;
#pragma unroll 4
        for (int h = 0; h < 64; h += 2) {
            float4 p0 = *(const float4*)&sPMc[b0 * 66 + h];
            float4 p1 = *(const float4*)&sPMc[b1 * 66 + h];
            float4 p2 = *(const float4*)&sPMc[32 * 66 + h];
            float4 d  = *(const float4*)&sFD2[lane * 66 + h];
            C0 += p0.x * d.x + p0.z * d.z;  S0 += p0.y * d.y + p0.w * d.w;
            C1 += p1.x * d.x + p1.z * d.z;  S1 += p1.y * d.y + p1.w * d.w;
            C2a += p2.x * d.x + p2.z * d.z; S2a += p2.y * d.y + p2.w * d.w;
        }
        {
            float2 d = sFD2[lane * 66 + 64];
            C0  += sPMc[b0 * 66 + 64].x * d.x;
            C1  += sPMc[b1 * 66 + 64].x * d.x;
            C2a += sPMc[32 * 66 + 64].x * d.x;
        }
        const float sc = 1.0f / 16384.0f;
        sXf[b0 * 34 + lane] = (C0 + S0) * sc;
        if (b0 >= 1) sXf[(64 - b0) * 34 + lane] = (C0 - S0) * sc;
        sXf[b1 * 34 + lane] = (C1 + S1) * sc;
        sXf[(64 - b1) * 34 + lane] = (C1 - S1) * sc;
        if (wid == 0) sXf[32 * 34 + lane] = (C2a + S2a) * sc;
    }
    __syncthreads();

    // ---- Stage B: 4 phases, role-split warps ----
    {
        const int g = wid >> 3, role = (wid >> 2) & 1, w4 = wid & 3, w8 = wid & 7;
        float*  Xfg = sXf + g * 32 * 34;
        float*  Wg  = sWR + g * 32 * 34;
        float*  Ahg = sAH + g * 32 * 34;
        float2* R1g = sR1 + g * 32 * 33;
        float2* R2g = sR2 + g * 32 * 33;

        if (role == 0) dht32_p1<8>(Xfg, R1g, sCS32, w4 * 8, lane);
        else           dht32_p1<8>(Wg,  R2g, sCS32, w4 * 8, lane);
        __syncthreads();
        if (role == 0) dht32_p2<8>(R1g, sCS32, Ahg, 1.0f / 1024.0f, w4 * 8, lane);
        else           dht32_p2<8>(R2g, sCS32, Wg,  1.0f / 1024.0f, w4 * 8, lane);
        __syncthreads();
        dht32_p1m(Ahg, Wg, R1g, sCS32, w8 * 4, lane);
        __syncthreads();
        dht32_p2<4>(R1g, sCS32, Xfg, 1.0f / 65536.0f, w8 * 4, lane);
        __syncthreads();
    }

    // ---- C1 prep: Gp/Gm from Xf ----
    for (int i = tid; i < 33 * 32; i += THREADS) {
        int b = i >> 5, s = i & 31;
        float gp, gm;
        if (b == 0)      { gp = sXf[s];             gm = 0.f; }
        else if (b == 32){ gp = sXf[32 * 34 + s];   gm = gp;  }
        else {
            float xa = sXf[b * 34 + s], xb = sXf[(64 - b) * 34 + s];
            gp = xa + xb; gm = xa - xb;
        }
        sGp[b * 34 + s] = gp; sGm[b * 34 + s] = gm;
    }
    __syncthreads();

    // ---- Stage C1: rows 0..63 (4/warp) + row 64 ----
    {
        const int hb = wid * 4;
        float Uc[4] = {0,0,0,0}, Us[4] = {0,0,0,0};
#pragma unroll 1
        for (int b = 0; b < 33; ++b) {
            float gp = sGp[b * 34 + lane];
            float gm = sGm[b * 34 + lane];
#pragma unroll
            for (int j = 0; j < 4; j += 2) {
                float4 p = *(const float4*)&sPMc[b * 66 + hb + j];
                Uc[j]     += p.x * gp;  Us[j]     += p.y * gm;
                Uc[j + 1] += p.z * gp;  Us[j + 1] += p.w * gm;
            }
        }
#pragma unroll
        for (int j = 0; j < 4; ++j)
            sU[(hb + j) * 34 + lane] = make_float2(Uc[j] + Us[j], Uc[j] - Us[j]);
    }
    if (tid < 32) {   // row 64: cos(pi*f) = (-1)^f, sin = 0
        float acc = 0.f;
#pragma unroll 1
        for (int b = 0; b < 32; b += 2)
            acc += sGp[b * 34 + tid] - sGp[(b + 1) * 34 + tid];
        acc += sGp[32 * 34 + tid];
        sU[64 * 34 + tid] = make_float2(acc, acc);
    }
    __syncthreads();

    // ---- copy-swap: U[h] = swap(U[128-h]) for h = 65..127 ----
    for (int i = tid; i < 63 * 32; i += THREADS) {
        int r = 65 + (i >> 5), s = i & 31;
        float2 v = sU[(128 - r) * 34 + s];
        sU[r * 34 + s] = make_float2(v.y, v.x);
    }
    __syncthreads();

    // ---- Stage C2: w'-folded + partner-column, two half passes ----
    {
        const float sc = 1.0f / 1048576.0f;
        const int wp = lane;
        const int wq = lane ? (64 - lane) : 32;
#pragma unroll 1
        for (int half = 0; half < 2; ++half) {
            const int hb = wid * 8 + half * 4;
            float A[4]  = {0,0,0,0}, B[4]  = {0,0,0,0};
            float Ap[4] = {0,0,0,0}, Bp[4] = {0,0,0,0};
#pragma unroll 4
            for (int s = 0; s < 32; s += 2) {
                float4 cs = *(const float4*)&sCS[wp * 34 + s];
                float4 cp;
                if (lane == 0) cp = *(const float4*)&sCS[32 * 34 + s];
                else           cp = make_float4(cs.x, -cs.y, -cs.z, cs.w);
#pragma unroll
                for (int j = 0; j < 4; ++j) {
                    float4 uu = *(const float4*)&sU[(hb + j) * 34 + s];
                    A[j]  += uu.x * cs.x + uu.z * cs.z;
                    B[j]  += uu.y * cs.y + uu.w * cs.w;
                    Ap[j] += uu.x * cp.x + uu.z * cp.z;
                    Bp[j] += uu.y * cp.y + uu.w * cp.w;
                }
            }
#pragma unroll
            for (int j = 0; j < 4; ++j) {
                O[(hb + j) * 128 + wp] = (A[j] + B[j]) * sc;
                if (wp) O[(hb + j) * 128 + (128 - wp)] = (A[j] - B[j]) * sc;
                O[(hb + j) * 128 + wq] = (Ap[j] + Bp[j]) * sc;
                O[(hb + j) * 128 + (128 - wq)] = (Ap[j] - Bp[j]) * sc;
            }
        }
    }
    if (tid < 128) {   // w' = 64 column: (-1)^s weights on U1
        float acc = 0.f;
#pragma unroll 4
        for (int s = 0; s < 32; s += 2)
            acc += sU[tid * 34 + s].x - sU[tid * 34 + s + 1].x;
        O[tid * 128 + 64] = acc * (1.0f / 1048576.0f);
    }
}

extern "C" void kernel_launch(void* const* d_in, const int* in_sizes, int n_in,
                              void* d_out, int out_size)
{
    const float* x  = (const float*)d_in[0];
    const float* w1 = (const float*)d_in[1];
    const float* w2 = (const float*)d_in[2];
    float* out = (float*)d_out;

    const int smem_bytes = F_TOT * 4; // 104736
    cudaFuncSetAttribute(spectral_kernel,
                         cudaFuncAttributeMaxDynamicSharedMemorySize, smem_bytes);
    spectral_kernel<<<4096, THREADS, smem_bytes>>>(x, w1, w2, out);
}

// round 8
// speedup vs baseline: 2.0623x; 1.1011x over previous
#include <cuda_runtime.h>
#define THREADS 512

// float offsets in dynamic smem (total 26184 floats = 104736 B -> 2 CTAs/SM)
#define O_CS   0       // [65][34] float2 : (cos,sin)(2pi*w*v/128)
#define O_PMC  4420    // [33][66] float2 : (cos,sin)(2pi*f(b)*h/128)
#define O_SD   8776    // region 8704 f : SD[128][34]f2 | {WR,AH,R1} | {U,Gp,Gm}
#define O_BIG  17480   // region 8704 f : {XE,XO} | {FD2,Xf,CS32} | {R2,Xf,CS32}
#define F_TOT  26184

#define SD_WR   0
#define SD_AH   2176
#define SD_R1   4352
#define SD_GP   4420
#define SD_GM   5542
#define BG_XO   4352
#define BG_XF   4352
#define BG_CS32 6528

// folded 32-DHT pass1: src EO layout: (E,O) pairs at [row*32+2w] (w=0..15), E16 at [1024+row]
template<int NR>
static __device__ __forceinline__ void dht32_p1f(const float* __restrict__ eo,
                                                 float2* __restrict__ R,
                                                 const float2* __restrict__ cs32,
                                                 int h0, int lane)
{
    float r1[NR], r2[NR];
#pragma unroll
    for (int r = 0; r < NR; ++r) { r1[r] = 0.f; r2[r] = 0.f; }
#pragma unroll
    for (int w = 0; w < 16; w += 2) {
        float4 cs = *(const float4*)&cs32[lane * 34 + w];
#pragma unroll
        for (int r = 0; r < NR; ++r) {
            float4 e = *(const float4*)&eo[(h0 + r) * 32 + 2 * w]; // (E_w,O_w,E_w1,O_w1)
            r1[r] += e.x * cs.x + e.z * cs.z;
            r2[r] += e.y * cs.y + e.w * cs.w;
        }
    }
    const float sgn = (lane & 1) ? -1.f : 1.f;
#pragma unroll
    for (int r = 0; r < NR; ++r) {
        float t1 = r1[r] + sgn * eo[1024 + h0 + r];
        R[(h0 + r) * 33 + lane] = make_float2(t1 + r2[r], t1 - r2[r]); // (p,m)
    }
}

// folded pass2: R holds (P,M) rows 0..16 (M0=M16=0 semantics; row16 via parity tail)
template<int NR>
static __device__ __forceinline__ void dht32_p2f(const float2* __restrict__ R,
                                                 const float2* __restrict__ cs32,
                                                 float* __restrict__ dst,
                                                 float scale, int u0, int lane)
{
    float acc[NR];
#pragma unroll
    for (int r = 0; r < NR; ++r) acc[r] = 0.f;
#pragma unroll
    for (int h = 0; h < 16; h += 2) {
        float2 a = R[h * 33 + lane], b = R[(h + 1) * 33 + lane];
#pragma unroll
        for (int r = 0; r < NR; ++r) {
            float4 cs = *(const float4*)&cs32[(u0 + r) * 34 + h];
            acc[r] += cs.x * a.x + cs.y * a.y + cs.z * b.x + cs.w * b.y;
        }
    }
    float p16 = R[16 * 33 + lane].x;
#pragma unroll
    for (int r = 0; r < NR; ++r) {
        float sg = ((u0 + r) & 1) ? -p16 : p16;
        dst[(u0 + r) * 34 + lane] = (acc[r] + sg) * scale;
    }
}

__global__ __launch_bounds__(THREADS, 2)
void spectral_kernel(const float* __restrict__ Xg,
                     const float* __restrict__ W1g,
                     const float* __restrict__ W2g,
                     float* __restrict__ Og)
{
    extern __shared__ float sm[];
    float2* sCS   = (float2*)(sm + O_CS);
    float2* sPMc  = (float2*)(sm + O_PMC);
    float2* sSD   = (float2*)(sm + O_SD);
    float*  sWR   = sm + O_SD + SD_WR;
    float*  sAH   = sm + O_SD + SD_AH;
    float2* sR1   = (float2*)(sm + O_SD + SD_R1);
    float2* sU    = (float2*)(sm + O_SD);
    float*  sGp   = sm + O_SD + SD_GP;
    float*  sGm   = sm + O_SD + SD_GM;
    float*  sXE   = sm + O_BIG;
    float*  sXO   = sm + O_BIG + BG_XO;
    float2* sFD2  = (float2*)(sm + O_BIG);
    float*  sXf   = sm + O_BIG + BG_XF;
    float2* sCS32 = (float2*)(sm + O_BIG + BG_CS32);
    float2* sR2   = (float2*)(sm + O_BIG);

    const int tid  = threadIdx.x;
    const int lane = tid & 31;
    const int wid  = tid >> 5;
    const int img  = blockIdx.x;
    const float* X = Xg + (size_t)img * 16384;
    float*       O = Og + (size_t)img * 16384;

    // ---- persistent tables ----
    for (int i = tid; i < 65 * 32; i += THREADS) {
        int w = i >> 5, v = i & 31;
        float s, c; sincospif((float)((w * v) & 127) * (1.0f / 64.0f), &s, &c);
        sCS[w * 34 + v] = make_float2(c, s);
    }
    for (int i = tid; i < 33 * 65; i += THREADS) {
        int b = i / 65, h = i - b * 65;
        int f = (b < 32) ? b : 96;
        float s, c; sincospif((float)((f * h) & 127) * (1.0f / 64.0f), &s, &c);
        sPMc[b * 66 + h] = make_float2(c, s);
    }

    // ---- Stage A1, two passes of 64 rows ----
#pragma unroll 1
    for (int pass = 0; pass < 2; ++pass) {
        for (int i = tid; i < 64 * 64; i += THREADS) {
            int hl = i >> 6, w = i & 63;
            int h = pass * 64 + hl;
            float a = X[h * 128 + w];
            float e, o;
            if (w == 0) { e = a; o = 0.f; }
            else { float b = X[h * 128 + 128 - w]; e = a + b; o = a - b; }
            sXE[hl * 68 + w] = e; sXO[hl * 68 + w] = o;
        }
        if (tid < 64) sXE[tid * 68 + 64] = X[(pass * 64 + tid) * 128 + 64];
        __syncthreads();

        const int r0 = wid * 4;
        float a1[4] = {0,0,0,0}, a2[4] = {0,0,0,0};
#pragma unroll 2
        for (int w = 0; w < 64; w += 4) {
            float2 cs0 = sCS[(w + 0) * 34 + lane];
            float2 cs1 = sCS[(w + 1) * 34 + lane];
            float2 cs2 = sCS[(w + 2) * 34 + lane];
            float2 cs3 = sCS[(w + 3) * 34 + lane];
#pragma unroll
            for (int r = 0; r < 4; ++r) {
                float4 e = *(const float4*)&sXE[(r0 + r) * 68 + w];
                float4 o = *(const float4*)&sXO[(r0 + r) * 68 + w];
                a1[r] += e.x * cs0.x + e.y * cs1.x + e.z * cs2.x + e.w * cs3.x;
                a2[r] += o.x * cs0.y + o.y * cs1.y + o.z * cs2.y + o.w * cs3.y;
            }
        }
        {
            float2 cs = sCS[64 * 34 + lane];
#pragma unroll
            for (int r = 0; r < 4; ++r) a1[r] += sXE[(r0 + r) * 68 + 64] * cs.x;
        }
#pragma unroll
        for (int r = 0; r < 4; ++r)
            sSD[(pass * 64 + r0 + r) * 34 + lane] = make_float2(a1[r] + a2[r], a1[r] - a2[r]);
        __syncthreads();
    }

    // ---- fold SD -> FD2 ; build CS32 ----
    for (int i = tid; i < 32 * 65; i += THREADS) {
        int v = i / 65, h = i - v * 65;
        float2 a = sSD[h * 34 + v];
        float sp, dm;
        if (h == 0 || h == 64) { sp = a.x; dm = 0.f; }
        else { float2 b = sSD[(128 - h) * 34 + v]; sp = a.x + b.x; dm = a.y - b.y; }
        sFD2[v * 66 + h] = make_float2(sp, dm);
    }
    for (int i = tid; i < 32 * 32; i += THREADS) {
        int u = i >> 5, h = i & 31;
        float s, c; sincospif((float)((u * h) & 31) * (1.0f / 16.0f), &s, &c);
        sCS32[u * 34 + h] = make_float2(c, s);
    }
    __syncthreads();

    // ---- Stage A2 (writes Xf) + weight load (SD region dead) ----
    for (int i = tid; i < 2048; i += THREADS) {
        int t = i >> 10, idx = i & 1023;
        const float* Wsrc = (t == 0 ? W1g : W2g) + (size_t)img * 1024;
        sWR[t * 1088 + (idx >> 5) * 34 + (idx & 31)] = Wsrc[idx];
    }
    {
        const int b0 = wid * 2, b1 = wid * 2 + 1;
        float C0=0.f,S0=0.f,C1=0.f,S1=0.f,C2a=0.f,S2a=0.f;
#pragma unroll 4
        for (int h = 0; h < 64; h += 2) {
            float4 p0 = *(const float4*)&sPMc[b0 * 66 + h];
            float4 p1 = *(const float4*)&sPMc[b1 * 66 + h];
            float4 p2 = *(const float4*)&sPMc[32 * 66 + h];
            float4 d  = *(const float4*)&sFD2[lane * 66 + h];
            C0 += p0.x * d.x + p0.z * d.z;  S0 += p0.y * d.y + p0.w * d.w;
            C1 += p1.x * d.x + p1.z * d.z;  S1 += p1.y * d.y + p1.w * d.w;
            C2a += p2.x * d.x + p2.z * d.z; S2a += p2.y * d.y + p2.w * d.w;
        }
        {
            float2 d = sFD2[lane * 66 + 64];
            C0  += sPMc[b0 * 66 + 64].x * d.x;
            C1  += sPMc[b1 * 66 + 64].x * d.x;
            C2a += sPMc[32 * 66 + 64].x * d.x;
        }
        const float sc = 1.0f / 16384.0f;
        sXf[b0 * 34 + lane] = (C0 + S0) * sc;
        if (b0 >= 1) sXf[(64 - b0) * 34 + lane] = (C0 - S0) * sc;
        sXf[b1 * 34 + lane] = (C1 + S1) * sc;
        sXf[(64 - b1) * 34 + lane] = (C1 - S1) * sc;
        if (wid == 0) sXf[32 * 34 + lane] = (C2a + S2a) * sc;
    }
    __syncthreads();

    // ======== Stage B: folded 32-DHTs ========
    {
        const int g = wid >> 3, role = (wid >> 2) & 1, w4 = wid & 3, w8 = wid & 7;
        float*  Xfg = sXf + g * 1088;
        float*  Wg  = sWR + g * 1088;
        float*  Ahg = sAH + g * 1088;
        float2* R1g = sR1 + g * 1056;
        float2* R2g = sR2 + g * 1056;

        // -- fold a -> EO@AH (direct) ; fold w -> EO@WR (in place, read-sync-write) --
        float wv0[2], wv1[2]; float e16w = 0.f;
#pragma unroll
        for (int k = 0; k < 2; ++k) {
            int i = tid + k * THREADS;
            int gg = i >> 9, rem = i & 511, row = rem >> 4, w = rem & 15;
            const float* Ws = sWR + gg * 1088;
            wv0[k] = Ws[row * 34 + w];
            wv1[k] = (w == 0) ? 0.f : Ws[row * 34 + 32 - w];
        }
        if (tid < 64) e16w = (sWR + (tid >> 5) * 1088)[(tid & 31) * 34 + 16];
        for (int i = tid; i < 1024; i += THREADS) {
            int gg = i >> 9, rem = i & 511, row = rem >> 4, w = rem & 15;
            const float* A = sXf + gg * 1088;
            float* EO = sAH + gg * 1088;
            float av = A[row * 34 + w], e, o;
            if (w == 0) { e = av; o = 0.f; }
            else { float bv = A[row * 34 + 32 - w]; e = av + bv; o = av - bv; }
            EO[row * 32 + 2 * w] = e; EO[row * 32 + 2 * w + 1] = o;
        }
        if (tid < 64) (sAH + (tid >> 5) * 1088)[1024 + (tid & 31)] =
                          (sXf + (tid >> 5) * 1088)[(tid & 31) * 34 + 16];
        __syncthreads();
#pragma unroll
        for (int k = 0; k < 2; ++k) {
            int i = tid + k * THREADS;
            int gg = i >> 9, rem = i & 511, row = rem >> 4, w = rem & 15;
            float* EO = sWR + gg * 1088;
            float e, o;
            if (w == 0) { e = wv0[k]; o = 0.f; }
            else { e = wv0[k] + wv1[k]; o = wv0[k] - wv1[k]; }
            EO[row * 32 + 2 * w] = e; EO[row * 32 + 2 * w + 1] = o;
        }
        if (tid < 64) (sWR + (tid >> 5) * 1088)[1024 + (tid & 31)] = e16w;
        __syncthreads();

        // -- pass1 (role split) --
        if (role == 0) dht32_p1f<8>(Ahg, R1g, sCS32, w4 * 8, lane);
        else           dht32_p1f<8>(Wg,  R2g, sCS32, w4 * 8, lane);
        __syncthreads();
        // -- fold R (in place, rows 0..16) --
        for (int i = tid; i < 2176; i += THREADS) {
            int c2 = i >> 10; int rem = i & 1023;      // 2176 = 2*1088; last chunk partial
            if (i >= 2176) break;
            int idx = i; int chain = idx / 1088; int r2i = idx - chain * 1088;
            int gg = r2i / 544; int r3 = r2i - gg * 544; int h = r3 >> 5, col = r3 & 31;
            (void)c2; (void)rem;
            float2* Rb = ((chain == 0) ? sR1 : sR2) + gg * 1056;
            float2 pm;
            if (h == 0)       { float2 v = Rb[col];            pm = make_float2(v.x, 0.f); }
            else if (h == 16) { float2 v = Rb[16 * 33 + col];  pm = make_float2(v.x, 0.f); }
            else { float2 va = Rb[h * 33 + col], vb = Rb[(32 - h) * 33 + col];
                   pm = make_float2(va.x + vb.x, va.y - vb.y); }
            Rb[h * 33 + col] = pm;
        }
        __syncthreads();
        // -- pass2 (role split): Ah = DHT(a)/1024 ; Wh = DHT(w)/1024 --
        if (role == 0) dht32_p2f<8>(R1g, sCS32, Ahg, 1.0f / 1024.0f, w4 * 8, lane);
        else           dht32_p2f<8>(R2g, sCS32, Wg,  1.0f / 1024.0f, w4 * 8, lane);
        __syncthreads();

        // -- prod = Ah*Wh, folded -> EO@Xf (a raw dead) --
        for (int i = tid; i < 1024; i += THREADS) {
            int gg = i >> 9, rem = i & 511, row = rem >> 4, w = rem & 15;
            const float* Ah = sAH + gg * 1088; const float* Wh = sWR + gg * 1088;
            float* EO = sXf + gg * 1088;
            float pv = Ah[row * 34 + w] * Wh[row * 34 + w], e, o;
            if (w == 0) { e = pv; o = 0.f; }
            else { float qv = Ah[row * 34 + 32 - w] * Wh[row * 34 + 32 - w];
                   e = pv + qv; o = pv - qv; }
            EO[row * 32 + 2 * w] = e; EO[row * 32 + 2 * w + 1] = o;
        }
        if (tid < 64) {
            int gg = tid >> 5, row = tid & 31;
            (sXf + gg * 1088)[1024 + row] =
                (sAH + gg * 1088)[row * 34 + 16] * (sWR + gg * 1088)[row * 34 + 16];
        }
        __syncthreads();
        // -- prod DHT: pass1, fold, pass2 (all 8 warps per group) --
        dht32_p1f<4>(Xfg, R1g, sCS32, w8 * 4, lane);
        __syncthreads();
        for (int i = tid; i < 1088; i += THREADS) {
            int gg = i / 544; int r3 = i - gg * 544; int h = r3 >> 5, col = r3 & 31;
            float2* Rb = sR1 + gg * 1056;
            float2 pm;
            if (h == 0)       { float2 v = Rb[col];            pm = make_float2(v.x, 0.f); }
            else if (h == 16) { float2 v = Rb[16 * 33 + col];  pm = make_float2(v.x, 0.f); }
            else { float2 va = Rb[h * 33 + col], vb = Rb[(32 - h) * 33 + col];
                   pm = make_float2(va.x + vb.x, va.y - vb.y); }
            Rb[h * 33 + col] = pm;
        }
        __syncthreads();
        dht32_p2f<4>(R1g, sCS32, Xfg, 1.0f / 65536.0f, w8 * 4, lane);
        __syncthreads();
    }

    // ---- C1 prep: Gp/Gm from Xf ----
    for (int i = tid; i < 33 * 32; i += THREADS) {
        int b = i >> 5, s = i & 31;
        float gp, gm;
        if (b == 0)      { gp = sXf[s];             gm = 0.f; }
        else if (b == 32){ gp = sXf[32 * 34 + s];   gm = gp;  }
        else {
            float xa = sXf[b * 34 + s], xb = sXf[(64 - b) * 34 + s];
            gp = xa + xb; gm = xa - xb;
        }
        sGp[b * 34 + s] = gp; sGm[b * 34 + s] = gm;
    }
    __syncthreads();

    // ---- Stage C1: rows 0..63 (4/warp) + row 64 ----
    {
        const int hb = wid * 4;
        float Uc[4] = {0,0,0,0}, Us[4] = {0,0,0,0};
#pragma unroll 1
        for (int b = 0; b < 33; ++b) {
            float gp = sGp[b * 34 + lane];
            float gm = sGm[b * 34 + lane];
#pragma unroll
            for (int j = 0; j < 4; j += 2) {
                float4 p = *(const float4*)&sPMc[b * 66 + hb + j];
                Uc[j]     += p.x * gp;  Us[j]     += p.y * gm;
                Uc[j + 1] += p.z * gp;  Us[j + 1] += p.w * gm;
            }
        }
#pragma unroll
        for (int j = 0; j < 4; ++j)
            sU[(hb + j) * 34 + lane] = make_float2(Uc[j] + Us[j], Uc[j] - Us[j]);
    }
    if (tid < 32) {
        float acc = 0.f;
#pragma unroll 1
        for (int b = 0; b < 32; b += 2)
            acc += sGp[b * 34 + tid] - sGp[(b + 1) * 34 + tid];
        acc += sGp[32 * 34 + tid];
        sU[64 * 34 + tid] = make_float2(acc, acc);
    }
    __syncthreads();

    // ---- copy-swap: U[h] = swap(U[128-h]) for h = 65..127 ----
    for (int i = tid; i < 63 * 32; i += THREADS) {
        int r = 65 + (i >> 5), s = i & 31;
        float2 v = sU[(128 - r) * 34 + s];
        sU[r * 34 + s] = make_float2(v.y, v.x);
    }
    __syncthreads();

    // ---- Stage C2: w'-folded + partner-column, two half passes ----
    {
        const float sc = 1.0f / 1048576.0f;
        const int wp = lane;
        const int wq = lane ? (64 - lane) : 32;
#pragma unroll 1
        for (int half = 0; half < 2; ++half) {
            const int hb = wid * 8 + half * 4;
            float A[4]  = {0,0,0,0}, B[4]  = {0,0,0,0};
            float Ap[4] = {0,0,0,0}, Bp[4] = {0,0,0,0};
#pragma unroll 4
            for (int s = 0; s < 32; s += 2) {
                float4 cs = *(const float4*)&sCS[wp * 34 + s];
                float4 cp;
                if (lane == 0) cp = *(const float4*)&sCS[32 * 34 + s];
                else           cp = make_float4(cs.x, -cs.y, -cs.z, cs.w);
#pragma unroll
                for (int j = 0; j < 4; ++j) {
                    float4 uu = *(const float4*)&sU[(hb + j) * 34 + s];
                    A[j]  += uu.x * cs.x + uu.z * cs.z;
                    B[j]  += uu.y * cs.y + uu.w * cs.w;
                    Ap[j] += uu.x * cp.x + uu.z * cp.z;
                    Bp[j] += uu.y * cp.y + uu.w * cp.w;
                }
            }
#pragma unroll
            for (int j = 0; j < 4; ++j) {
                O[(hb + j) * 128 + wp] = (A[j] + B[j]) * sc;
                if (wp) O[(hb + j) * 128 + (128 - wp)] = (A[j] - B[j]) * sc;
                O[(hb + j) * 128 + wq] = (Ap[j] + Bp[j]) * sc;
                O[(hb + j) * 128 + (128 - wq)] = (Ap[j] - Bp[j]) * sc;
            }
        }
    }
    if (tid < 128) {
        float acc = 0.f;
#pragma unroll 4
        for (int s = 0; s < 32; s += 2)
            acc += sU[tid * 34 + s].x - sU[tid * 34 + s + 1].x;
        O[tid * 128 + 64] = acc * (1.0f / 1048576.0f);
    }
}

extern "C" void kernel_launch(void* const* d_in, const int* in_sizes, int n_in,
                              void* d_out, int out_size)
{
    const float* x  = (const float*)d_in[0];
    const float* w1 = (const float*)d_in[1];
    const float* w2 = (const float*)d_in[2];
    float* out = (float*)d_out;

    const int smem_bytes = F_TOT * 4; // 104736
    cudaFuncSetAttribute(spectral_kernel,
                         cudaFuncAttributeMaxDynamicSharedMemorySize, smem_bytes);
    spectral_kernel<<<4096, THREADS, smem_bytes>>>(x, w1, w2, out);
}

// round 9
// speedup vs baseline: 2.2071x; 1.0702x over previous
#include <cuda_runtime.h>
#define THREADS 512

// float offsets in dynamic smem (total 21764 floats = 87056 B -> 2 CTAs/SM)
#define O_PMC  0       // [33][66] float2 : (cos,sin)(2pi*f(b)*h/128)   (4356 f)
#define O_SD   4356    // region 8704 f : SD[128][34]f2 | {WR,AH,R1} | {U,Gp,Gm}
#define O_BIG  13060   // region 8704 f : {XE,XO} | {FD2,Xf,CS32} | {R2,Xf,CS32}
#define F_TOT  21764

#define SD_WR   0
#define SD_AH   2176
#define SD_R1   4352
#define SD_GP   4420
#define SD_GM   5542
#define BG_XO   4352
#define BG_XF   4352
#define BG_CS32 6528

// folded 32-DHT pass1 with register twiddles: EO layout (E,O) pairs at
// [row*32+2w] (w=0..15), E16 at [1024+row]
template<int NR>
static __device__ __forceinline__ void dht32_p1f(const float* __restrict__ eo,
                                                 float2* __restrict__ R,
                                                 int h0, int lane)
{
    float r1[NR], r2[NR];
#pragma unroll
    for (int r = 0; r < NR; ++r) { r1[r] = 0.f; r2[r] = 0.f; }
    float s1, c1; sincospif((float)lane * (1.0f / 16.0f), &s1, &c1);
    const float t2 = 2.0f * c1;
    float cw = 1.f, sw = 0.f, cpv = c1, spv = -s1;
#pragma unroll
    for (int w = 0; w < 16; w += 2) {
        float cn = t2 * cw - cpv, sn = t2 * sw - spv;
#pragma unroll
        for (int r = 0; r < NR; ++r) {
            float4 e = *(const float4*)&eo[(h0 + r) * 32 + 2 * w]; // (E_w,O_w,E_w1,O_w1)
            r1[r] += e.x * cw + e.z * cn;
            r2[r] += e.y * sw + e.w * sn;
        }
        float cn2 = t2 * cn - cw, sn2 = t2 * sn - sw;
        cpv = cn; spv = sn; cw = cn2; sw = sn2;
    }
    const float sgn = (lane & 1) ? -1.f : 1.f;
#pragma unroll
    for (int r = 0; r < NR; ++r) {
        float t1 = r1[r] + sgn * eo[1024 + h0 + r];
        R[(h0 + r) * 33 + lane] = make_float2(t1 + r2[r], t1 - r2[r]); // (p,m)
    }
}

// folded pass2: R holds (P,M) rows 0..16; broadcast table reads (cheap)
template<int NR>
static __device__ __forceinline__ void dht32_p2f(const float2* __restrict__ R,
                                                 const float2* __restrict__ cs32,
                                                 float* __restrict__ dst,
                                                 float scale, int u0, int lane)
{
    float acc[NR];
#pragma unroll
    for (int r = 0; r < NR; ++r) acc[r] = 0.f;
#pragma unroll
    for (int h = 0; h < 16; h += 2) {
        float2 a = R[h * 33 + lane], b = R[(h + 1) * 33 + lane];
#pragma unroll
        for (int r = 0; r < NR; ++r) {
            float4 cs = *(const float4*)&cs32[(u0 + r) * 34 + h];
            acc[r] += cs.x * a.x + cs.y * a.y + cs.z * b.x + cs.w * b.y;
        }
    }
    float p16 = R[16 * 33 + lane].x;
#pragma unroll
    for (int r = 0; r < NR; ++r) {
        float sg = ((u0 + r) & 1) ? -p16 : p16;
        dst[(u0 + r) * 34 + lane] = (acc[r] + sg) * scale;
    }
}

__global__ __launch_bounds__(THREADS, 2)
void spectral_kernel(const float* __restrict__ Xg,
                     const float* __restrict__ W1g,
                     const float* __restrict__ W2g,
                     float* __restrict__ Og)
{
    extern __shared__ float sm[];
    float2* sPMc  = (float2*)(sm + O_PMC);
    float2* sSD   = (float2*)(sm + O_SD);
    float*  sWR   = sm + O_SD + SD_WR;
    float*  sAH   = sm + O_SD + SD_AH;
    float2* sR1   = (float2*)(sm + O_SD + SD_R1);
    float2* sU    = (float2*)(sm + O_SD);
    float*  sGp   = sm + O_SD + SD_GP;
    float*  sGm   = sm + O_SD + SD_GM;
    float*  sXE   = sm + O_BIG;
    float*  sXO   = sm + O_BIG + BG_XO;
    float2* sFD2  = (float2*)(sm + O_BIG);
    float*  sXf   = sm + O_BIG + BG_XF;
    float2* sCS32 = (float2*)(sm + O_BIG + BG_CS32);
    float2* sR2   = (float2*)(sm + O_BIG);

    const int tid  = threadIdx.x;
    const int lane = tid & 31;
    const int wid  = tid >> 5;
    const int img  = blockIdx.x;
    const float* X = Xg + (size_t)img * 16384;
    float*       O = Og + (size_t)img * 16384;

    // ---- persistent table (broadcast-only consumers) ----
    for (int i = tid; i < 33 * 65; i += THREADS) {
        int b = i / 65, h = i - b * 65;
        int f = (b < 32) ? b : 96;
        float s, c; sincospif((float)((f * h) & 127) * (1.0f / 64.0f), &s, &c);
        sPMc[b * 66 + h] = make_float2(c, s);
    }

    // ---- Stage A1, two passes of 64 rows; register twiddles ----
#pragma unroll 1
    for (int pass = 0; pass < 2; ++pass) {
        for (int i = tid; i < 64 * 64; i += THREADS) {
            int hl = i >> 6, w = i & 63;
            int h = pass * 64 + hl;
            float a = X[h * 128 + w];
            float e, o;
            if (w == 0) { e = a; o = 0.f; }
            else { float b = X[h * 128 + 128 - w]; e = a + b; o = a - b; }
            sXE[hl * 68 + w] = e; sXO[hl * 68 + w] = o;
        }
        if (tid < 64) sXE[tid * 68 + 64] = X[(pass * 64 + tid) * 128 + 64];
        __syncthreads();

        const int r0 = wid * 4;
        float s1, c1; sincospif((float)lane * (1.0f / 64.0f), &s1, &c1);
        const float t2 = 2.0f * c1;
        float a1[4] = {0,0,0,0}, a2[4] = {0,0,0,0};
        float cw = 1.f, sw = 0.f, cpv = c1, spv = -s1;
#pragma unroll 1
        for (int seg = 0; seg < 2; ++seg) {
            if (seg == 1) {  // exact restart at w = 32
                float s32, c32; sincospif((float)lane * 0.5f, &s32, &c32);
                cw = c32; sw = s32;
                cpv = c32 * c1 + s32 * s1;   // cos(31*theta)
                spv = s32 * c1 - c32 * s1;   // sin(31*theta)
            }
            const int wb = seg * 32;
#pragma unroll
            for (int w0 = 0; w0 < 32; w0 += 4) {
                const int w = wb + w0;
                float cA = cw, sA = sw;
                float cB = t2 * cA - cpv, sB = t2 * sA - spv;
                float cC = t2 * cB - cA,  sC = t2 * sB - sA;
                float cD = t2 * cC - cB,  sD = t2 * sC - sB;
                float cE = t2 * cD - cC,  sE = t2 * sD - sC;
                cpv = cD; spv = sD; cw = cE; sw = sE;
#pragma unroll
                for (int r = 0; r < 4; ++r) {
                    float4 e = *(const float4*)&sXE[(r0 + r) * 68 + w];
                    float4 o = *(const float4*)&sXO[(r0 + r) * 68 + w];
                    a1[r] += e.x * cA + e.y * cB + e.z * cC + e.w * cD;
                    a2[r] += o.x * sA + o.y * sB + o.z * sC + o.w * sD;
                }
            }
        }
        {
            const float sg64 = (lane & 1) ? -1.f : 1.f;   // cos(pi*lane)
#pragma unroll
            for (int r = 0; r < 4; ++r) a1[r] += sXE[(r0 + r) * 68 + 64] * sg64;
        }
#pragma unroll
        for (int r = 0; r < 4; ++r)
            sSD[(pass * 64 + r0 + r) * 34 + lane] = make_float2(a1[r] + a2[r], a1[r] - a2[r]);
        __syncthreads();
    }

    // ---- fold SD -> FD2 ; build CS32 ----
    for (int i = tid; i < 32 * 65; i += THREADS) {
        int v = i / 65, h = i - v * 65;
        float2 a = sSD[h * 34 + v];
        float sp, dm;
        if (h == 0 || h == 64) { sp = a.x; dm = 0.f; }
        else { float2 b = sSD[(128 - h) * 34 + v]; sp = a.x + b.x; dm = a.y - b.y; }
        sFD2[v * 66 + h] = make_float2(sp, dm);
    }
    for (int i = tid; i < 32 * 32; i += THREADS) {
        int u = i >> 5, h = i & 31;
        float s, c; sincospif((float)((u * h) & 31) * (1.0f / 16.0f), &s, &c);
        sCS32[u * 34 + h] = make_float2(c, s);
    }
    __syncthreads();

    // ---- Stage A2 (writes Xf) + weight load ----
    for (int i = tid; i < 2048; i += THREADS) {
        int t = i >> 10, idx = i & 1023;
        const float* Wsrc = (t == 0 ? W1g : W2g) + (size_t)img * 1024;
        sWR[t * 1088 + (idx >> 5) * 34 + (idx & 31)] = Wsrc[idx];
    }
    {
        const int b0 = wid * 2, b1 = wid * 2 + 1;
        float C0=0.f,S0=0.f,C1=0.f,S1=0.f,C2a=0.f,S2a=0.f;
#pragma unroll 4
        for (int h = 0; h < 64; h += 2) {
            float4 p0 = *(const float4*)&sPMc[b0 * 66 + h];
            float4 p1 = *(const float4*)&sPMc[b1 * 66 + h];
            float4 p2 = *(const float4*)&sPMc[32 * 66 + h];
            float4 d  = *(const float4*)&sFD2[lane * 66 + h];
            C0 += p0.x * d.x + p0.z * d.z;  S0 += p0.y * d.y + p0.w * d.w;
            C1 += p1.x * d.x + p1.z * d.z;  S1 += p1.y * d.y + p1.w * d.w;
            C2a += p2.x * d.x + p2.z * d.z; S2a += p2.y * d.y + p2.w * d.w;
        }
        {
            float2 d = sFD2[lane * 66 + 64];
            C0  += sPMc[b0 * 66 + 64].x * d.x;
            C1  += sPMc[b1 * 66 + 64].x * d.x;
            C2a += sPMc[32 * 66 + 64].x * d.x;
        }
        const float sc = 1.0f / 16384.0f;
        sXf[b0 * 34 + lane] = (C0 + S0) * sc;
        if (b0 >= 1) sXf[(64 - b0) * 34 + lane] = (C0 - S0) * sc;
        sXf[b1 * 34 + lane] = (C1 + S1) * sc;
        sXf[(64 - b1) * 34 + lane] = (C1 - S1) * sc;
        if (wid == 0) sXf[32 * 34 + lane] = (C2a + S2a) * sc;
    }
    __syncthreads();

    // ======== Stage B: folded 32-DHTs, register twiddles in pass1 ========
    {
        const int g = wid >> 3, role = (wid >> 2) & 1, w4 = wid & 3, w8 = wid & 7;
        float*  Xfg = sXf + g * 1088;
        float*  Wg  = sWR + g * 1088;
        float*  Ahg = sAH + g * 1088;
        float2* R1g = sR1 + g * 1056;
        float2* R2g = sR2 + g * 1056;

        float wv0[2], wv1[2]; float e16w = 0.f;
#pragma unroll
        for (int k = 0; k < 2; ++k) {
            int i = tid + k * THREADS;
            int gg = i >> 9, rem = i & 511, row = rem >> 4, w = rem & 15;
            const float* Ws = sWR + gg * 1088;
            wv0[k] = Ws[row * 34 + w];
            wv1[k] = (w == 0) ? 0.f : Ws[row * 34 + 32 - w];
        }
        if (tid < 64) e16w = (sWR + (tid >> 5) * 1088)[(tid & 31) * 34 + 16];
        for (int i = tid; i < 1024; i += THREADS) {
            int gg = i >> 9, rem = i & 511, row = rem >> 4, w = rem & 15;
            const float* A = sXf + gg * 1088;
            float* EO = sAH + gg * 1088;
            float av = A[row * 34 + w], e, o;
            if (w == 0) { e = av; o = 0.f; }
            else { float bv = A[row * 34 + 32 - w]; e = av + bv; o = av - bv; }
            EO[row * 32 + 2 * w] = e; EO[row * 32 + 2 * w + 1] = o;
        }
        if (tid < 64) (sAH + (tid >> 5) * 1088)[1024 + (tid & 31)] =
                          (sXf + (tid >> 5) * 1088)[(tid & 31) * 34 + 16];
        __syncthreads();
#pragma unroll
        for (int k = 0; k < 2; ++k) {
            int i = tid + k * THREADS;
            int gg = i >> 9, rem = i & 511, row = rem >> 4, w = rem & 15;
            float* EO = sWR + gg * 1088;
            float e, o;
            if (w == 0) { e = wv0[k]; o = 0.f; }
            else { e = wv0[k] + wv1[k]; o = wv0[k] - wv1[k]; }
            EO[row * 32 + 2 * w] = e; EO[row * 32 + 2 * w + 1] = o;
        }
        if (tid < 64) (sWR + (tid >> 5) * 1088)[1024 + (tid & 31)] = e16w;
        __syncthreads();

        if (role == 0) dht32_p1f<8>(Ahg, R1g, w4 * 8, lane);
        else           dht32_p1f<8>(Wg,  R2g, w4 * 8, lane);
        __syncthreads();
        for (int i = tid; i < 2176; i += THREADS) {
            int chain = i / 1088; int r2i = i - chain * 1088;
            int gg = r2i / 544; int r3 = r2i - gg * 544; int h = r3 >> 5, col = r3 & 31;
            float2* Rb = ((chain == 0) ? sR1 : sR2) + gg * 1056;
            float2 pm;
            if (h == 0)       { float2 v = Rb[col];            pm = make_float2(v.x, 0.f); }
            else if (h == 16) { float2 v = Rb[16 * 33 + col];  pm = make_float2(v.x, 0.f); }
            else { float2 va = Rb[h * 33 + col], vb = Rb[(32 - h) * 33 + col];
                   pm = make_float2(va.x + vb.x, va.y - vb.y); }
            Rb[h * 33 + col] = pm;
        }
        __syncthreads();
        if (role == 0) dht32_p2f<8>(R1g, sCS32, Ahg, 1.0f / 1024.0f, w4 * 8, lane);
        else           dht32_p2f<8>(R2g, sCS32, Wg,  1.0f / 1024.0f, w4 * 8, lane);
        __syncthreads();

        for (int i = tid; i < 1024; i += THREADS) {
            int gg = i >> 9, rem = i & 511, row = rem >> 4, w = rem & 15;
            const float* Ah = sAH + gg * 1088; const float* Wh = sWR + gg * 1088;
            float* EO = sXf + gg * 1088;
            float pv = Ah[row * 34 + w] * Wh[row * 34 + w], e, o;
            if (w == 0) { e = pv; o = 0.f; }
            else { float qv = Ah[row * 34 + 32 - w] * Wh[row * 34 + 32 - w];
                   e = pv + qv; o = pv - qv; }
            EO[row * 32 + 2 * w] = e; EO[row * 32 + 2 * w + 1] = o;
        }
        if (tid < 64) {
            int gg = tid >> 5, row = tid & 31;
            (sXf + gg * 1088)[1024 + row] =
                (sAH + gg * 1088)[row * 34 + 16] * (sWR + gg * 1088)[row * 34 + 16];
        }
        __syncthreads();
        dht32_p1f<4>(Xfg, R1g, w8 * 4, lane);
        __syncthreads();
        for (int i = tid; i < 1088; i += THREADS) {
            int gg = i / 544; int r3 = i - gg * 544; int h = r3 >> 5, col = r3 & 31;
            float2* Rb = sR1 + gg * 1056;
            float2 pm;
            if (h == 0)       { float2 v = Rb[col];            pm = make_float2(v.x, 0.f); }
            else if (h == 16) { float2 v = Rb[16 * 33 + col];  pm = make_float2(v.x, 0.f); }
            else { float2 va = Rb[h * 33 + col], vb = Rb[(32 - h) * 33 + col];
                   pm = make_float2(va.x + vb.x, va.y - vb.y); }
            Rb[h * 33 + col] = pm;
        }
        __syncthreads();
        dht32_p2f<4>(R1g, sCS32, Xfg, 1.0f / 65536.0f, w8 * 4, lane);
        __syncthreads();
    }

    // ---- C1 prep ----
    for (int i = tid; i < 33 * 32; i += THREADS) {
        int b = i >> 5, s = i & 31;
        float gp, gm;
        if (b == 0)      { gp = sXf[s];             gm = 0.f; }
        else if (b == 32){ gp = sXf[32 * 34 + s];   gm = gp;  }
        else {
            float xa = sXf[b * 34 + s], xb = sXf[(64 - b) * 34 + s];
            gp = xa + xb; gm = xa - xb;
        }
        sGp[b * 34 + s] = gp; sGm[b * 34 + s] = gm;
    }
    __syncthreads();

    // ---- Stage C1 ----
    {
        const int hb = wid * 4;
        float Uc[4] = {0,0,0,0}, Us[4] = {0,0,0,0};
#pragma unroll 1
        for (int b = 0; b < 33; ++b) {
            float gp = sGp[b * 34 + lane];
            float gm = sGm[b * 34 + lane];
#pragma unroll
            for (int j = 0; j < 4; j += 2) {
                float4 p = *(const float4*)&sPMc[b * 66 + hb + j];
                Uc[j]     += p.x * gp;  Us[j]     += p.y * gm;
                Uc[j + 1] += p.z * gp;  Us[j + 1] += p.w * gm;
            }
        }
#pragma unroll
        for (int j = 0; j < 4; ++j)
            sU[(hb + j) * 34 + lane] = make_float2(Uc[j] + Us[j], Uc[j] - Us[j]);
    }
    if (tid < 32) {
        float acc = 0.f;
#pragma unroll 1
        for (int b = 0; b < 32; b += 2)
            acc += sGp[b * 34 + tid] - sGp[(b + 1) * 34 + tid];
        acc += sGp[32 * 34 + tid];
        sU[64 * 34 + tid] = make_float2(acc, acc);
    }
    __syncthreads();

    for (int i = tid; i < 63 * 32; i += THREADS) {
        int r = 65 + (i >> 5), s = i & 31;
        float2 v = sU[(128 - r) * 34 + s];
        sU[r * 34 + s] = make_float2(v.y, v.x);
    }
    __syncthreads();

    // ---- Stage C2: register twiddles for wp and wq ----
    {
        const float sc = 1.0f / 1048576.0f;
        const int wp = lane;
        const int wq = lane ? (64 - lane) : 32;
        float s1p, c1p; sincospif((float)wp * (1.0f / 64.0f), &s1p, &c1p);
        float s1q, c1q; sincospif((float)wq * (1.0f / 64.0f), &s1q, &c1q);
        const float t2p = 2.0f * c1p, t2q = 2.0f * c1q;
        float s16p, c16p; sincospif((float)wp * 0.25f, &s16p, &c16p);
        float s16q, c16q; sincospif((float)wq * 0.25f, &s16q, &c16q);
#pragma unroll 1
        for (int half = 0; half < 2; ++half) {
            const int hb = wid * 8 + half * 4;
            float A[4]  = {0,0,0,0}, B[4]  = {0,0,0,0};
            float Ap[4] = {0,0,0,0}, Bp[4] = {0,0,0,0};
            float cwp = 1.f, swp = 0.f, cppv = c1p, sppv = -s1p;
            float cwq = 1.f, swq = 0.f, cqpv = c1q, sqpv = -s1q;
#pragma unroll 1
            for (int seg = 0; seg < 2; ++seg) {
                if (seg == 1) {   // exact restart at s = 16
                    cwp = c16p; swp = s16p;
                    cppv = c16p * c1p + s16p * s1p;
                    sppv = s16p * c1p - c16p * s1p;
                    cwq = c16q; swq = s16q;
                    cqpv = c16q * c1q + s16q * s1q;
                    sqpv = s16q * c1q - c16q * s1q;
                }
#pragma unroll
                for (int s0 = 0; s0 < 16; s0 += 2) {
                    const int s = seg * 16 + s0;
                    float cnp = t2p * cwp - cppv, snp = t2p * swp - sppv;
                    float cnq = t2q * cwq - cqpv, snq = t2q * swq - sqpv;
#pragma unroll
                    for (int j = 0; j < 4; ++j) {
                        float4 uu = *(const float4*)&sU[(hb + j) * 34 + s];
                        A[j]  += uu.x * cwp + uu.z * cnp;
                        B[j]  += uu.y * swp + uu.w * snp;
                        Ap[j] += uu.x * cwq + uu.z * cnq;
                        Bp[j] += uu.y * swq + uu.w * snq;
                    }
                    float cn2p = t2p * cnp - cwp, sn2p = t2p * snp - swp;
                    float cn2q = t2q * cnq - cwq, sn2q = t2q * snq - swq;
                    cppv = cnp; sppv = snp; cwp = cn2p; swp = sn2p;
                    cqpv = cnq; sqpv = snq; cwq = cn2q; swq = sn2q;
                }
            }
#pragma unroll
            for (int j = 0; j < 4; ++j) {
                O[(hb + j) * 128 + wp] = (A[j] + B[j]) * sc;
                if (wp) O[(hb + j) * 128 + (128 - wp)] = (A[j] - B[j]) * sc;
                O[(hb + j) * 128 + wq] = (Ap[j] + Bp[j]) * sc;
                O[(hb + j) * 128 + (128 - wq)] = (Ap[j] - Bp[j]) * sc;
            }
        }
    }
    if (tid < 128) {
        float acc = 0.f;
#pragma unroll 4
        for (int s = 0; s < 32; s += 2)
            acc += sU[tid * 34 + s].x - sU[tid * 34 + s + 1].x;
        O[tid * 128 + 64] = acc * (1.0f / 1048576.0f);
    }
}

extern "C" void kernel_launch(void* const* d_in, const int* in_sizes, int n_in,
                              void* d_out, int out_size)
{
    const float* x  = (const float*)d_in[0];
    const float* w1 = (const float*)d_in[1];
    const float* w2 = (const float*)d_in[2];
    float* out = (float*)d_out;

    const int smem_bytes = F_TOT * 4; // 87056
    cudaFuncSetAttribute(spectral_kernel,
                         cudaFuncAttributeMaxDynamicSharedMemorySize, smem_bytes);
    spectral_kernel<<<4096, THREADS, smem_bytes>>>(x, w1, w2, out);
}

// round 11
// speedup vs baseline: 2.2228x; 1.0071x over previous
#include <cuda_runtime.h>
#define THREADS 512

// float offsets in dynamic smem (total 17408 floats = 69632 B -> 3 CTAs/SM)
#define O_SD   0       // region 8704 f : SD[128][34]f2 | {WR,AH,R1} | {U,Gp,Gm}
#define O_BIG  8704    // region 8704 f : {XE,XO} | {FD2,Xf,CS32} | {R2,Xf,CS32}
#define F_TOT  17408

#define SD_WR   0
#define SD_AH   2176
#define SD_R1   4352
#define SD_GP   4420
#define SD_GM   5542
#define BG_XO   4352
#define BG_XF   4352
#define BG_CS32 6528

// folded 32-DHT pass1 with register twiddles: EO layout (E,O) pairs at
// [row*32+2w] (w=0..15), E16 at [1024+row]
template<int NR>
static __device__ __forceinline__ void dht32_p1f(const float* __restrict__ eo,
                                                 float2* __restrict__ R,
                                                 int h0, int lane)
{
    float r1[NR], r2[NR];
#pragma unroll
    for (int r = 0; r < NR; ++r) { r1[r] = 0.f; r2[r] = 0.f; }
    float s1, c1; sincospif((float)lane * (1.0f / 16.0f), &s1, &c1);
    const float t2 = 2.0f * c1;
    float cw = 1.f, sw = 0.f, cpv = c1, spv = -s1;
#pragma unroll
    for (int w = 0; w < 16; w += 2) {
        float cn = t2 * cw - cpv, sn = t2 * sw - spv;
#pragma unroll
        for (int r = 0; r < NR; ++r) {
            float4 e = *(const float4*)&eo[(h0 + r) * 32 + 2 * w];
            r1[r] += e.x * cw + e.z * cn;
            r2[r] += e.y * sw + e.w * sn;
        }
        float cn2 = t2 * cn - cw, sn2 = t2 * sn - sw;
        cpv = cn; spv = sn; cw = cn2; sw = sn2;
    }
    const float sgn = (lane & 1) ? -1.f : 1.f;
#pragma unroll
    for (int r = 0; r < NR; ++r) {
        float t1 = r1[r] + sgn * eo[1024 + h0 + r];
        R[(h0 + r) * 33 + lane] = make_float2(t1 + r2[r], t1 - r2[r]);
    }
}

// folded pass2: broadcast cs32 table reads
template<int NR>
static __device__ __forceinline__ void dht32_p2f(const float2* __restrict__ R,
                                                 const float2* __restrict__ cs32,
                                                 float* __restrict__ dst,
                                                 float scale, int u0, int lane)
{
    float acc[NR];
#pragma unroll
    for (int r = 0; r < NR; ++r) acc[r] = 0.f;
#pragma unroll
    for (int h = 0; h < 16; h += 2) {
        float2 a = R[h * 33 + lane], b = R[(h + 1) * 33 + lane];
#pragma unroll
        for (int r = 0; r < NR; ++r) {
            float4 cs = *(const float4*)&cs32[(u0 + r) * 34 + h];
            acc[r] += cs.x * a.x + cs.y * a.y + cs.z * b.x + cs.w * b.y;
        }
    }
    float p16 = R[16 * 33 + lane].x;
#pragma unroll
    for (int r = 0; r < NR; ++r) {
        float sg = ((u0 + r) & 1) ? -p16 : p16;
        dst[(u0 + r) * 34 + lane] = (acc[r] + sg) * scale;
    }
}

__global__ __launch_bounds__(THREADS, 3)
void spectral_kernel(const float* __restrict__ Xg,
                     const float* __restrict__ W1g,
                     const float* __restrict__ W2g,
                     float* __restrict__ Og)
{
    extern __shared__ float sm[];
    float2* sSD   = (float2*)(sm + O_SD);
    float*  sWR   = sm + O_SD + SD_WR;
    float*  sAH   = sm + O_SD + SD_AH;
    float2* sR1   = (float2*)(sm + O_SD + SD_R1);
    float2* sU    = (float2*)(sm + O_SD);
    float*  sGp   = sm + O_SD + SD_GP;
    float*  sGm   = sm + O_SD + SD_GM;
    float*  sXE   = sm + O_BIG;
    float*  sXO   = sm + O_BIG + BG_XO;
    float2* sFD2  = (float2*)(sm + O_BIG);
    float*  sXf   = sm + O_BIG + BG_XF;
    float2* sCS32 = (float2*)(sm + O_BIG + BG_CS32);
    float2* sR2   = (float2*)(sm + O_BIG);

    const int tid  = threadIdx.x;
    const int lane = tid & 31;
    const int wid  = tid >> 5;
    const int img  = blockIdx.x;
    const float* X = Xg + (size_t)img * 16384;
    float*       O = Og + (size_t)img * 16384;

    // ---- Stage A1, two passes of 64 rows; register twiddles ----
#pragma unroll 1
    for (int pass = 0; pass < 2; ++pass) {
        for (int i = tid; i < 64 * 64; i += THREADS) {
            int hl = i >> 6, w = i & 63;
            int h = pass * 64 + hl;
            float a = X[h * 128 + w];
            float e, o;
            if (w == 0) { e = a; o = 0.f; }
            else { float b = X[h * 128 + 128 - w]; e = a + b; o = a - b; }
            sXE[hl * 68 + w] = e; sXO[hl * 68 + w] = o;
        }
        if (tid < 64) sXE[tid * 68 + 64] = X[(pass * 64 + tid) * 128 + 64];
        __syncthreads();

        const int r0 = wid * 4;
        float s1, c1; sincospif((float)lane * (1.0f / 64.0f), &s1, &c1);
        const float t2 = 2.0f * c1;
        float a1[4] = {0,0,0,0}, a2[4] = {0,0,0,0};
        float cw = 1.f, sw = 0.f, cpv = c1, spv = -s1;
#pragma unroll 1
        for (int seg = 0; seg < 2; ++seg) {
            if (seg == 1) {
                float s32, c32; sincospif((float)lane * 0.5f, &s32, &c32);
                cw = c32; sw = s32;
                cpv = c32 * c1 + s32 * s1;
                spv = s32 * c1 - c32 * s1;
            }
            const int wb = seg * 32;
#pragma unroll
            for (int w0 = 0; w0 < 32; w0 += 4) {
                const int w = wb + w0;
                float cA = cw, sA = sw;
                float cB = t2 * cA - cpv, sB = t2 * sA - spv;
                float cC = t2 * cB - cA,  sC = t2 * sB - sA;
                float cD = t2 * cC - cB,  sD = t2 * sC - sB;
                float cE = t2 * cD - cC,  sE = t2 * sD - sC;
                cpv = cD; spv = sD; cw = cE; sw = sE;
#pragma unroll
                for (int r = 0; r < 4; ++r) {
                    float4 e = *(const float4*)&sXE[(r0 + r) * 68 + w];
                    float4 o = *(const float4*)&sXO[(r0 + r) * 68 + w];
                    a1[r] += e.x * cA + e.y * cB + e.z * cC + e.w * cD;
                    a2[r] += o.x * sA + o.y * sB + o.z * sC + o.w * sD;
                }
            }
        }
        {
            const float sg64 = (lane & 1) ? -1.f : 1.f;
#pragma unroll
            for (int r = 0; r < 4; ++r) a1[r] += sXE[(r0 + r) * 68 + 64] * sg64;
        }
#pragma unroll
        for (int r = 0; r < 4; ++r)
            sSD[(pass * 64 + r0 + r) * 34 + lane] = make_float2(a1[r] + a2[r], a1[r] - a2[r]);
        __syncthreads();
    }

    // ---- fold SD -> FD2 ; build CS32 ----
    for (int i = tid; i < 32 * 65; i += THREADS) {
        int v = i / 65, h = i - v * 65;
        float2 a = sSD[h * 34 + v];
        float sp, dm;
        if (h == 0 || h == 64) { sp = a.x; dm = 0.f; }
        else { float2 b = sSD[(128 - h) * 34 + v]; sp = a.x + b.x; dm = a.y - b.y; }
        sFD2[v * 66 + h] = make_float2(sp, dm);
    }
    for (int i = tid; i < 32 * 32; i += THREADS) {
        int u = i >> 5, h = i & 31;
        float s, c; sincospif((float)((u * h) & 31) * (1.0f / 16.0f), &s, &c);
        sCS32[u * 34 + h] = make_float2(c, s);
    }
    __syncthreads();

    // ---- Stage A2 (register twiddles over h) + weight load ----
    for (int i = tid; i < 2048; i += THREADS) {
        int t = i >> 10, idx = i & 1023;
        const float* Wsrc = (t == 0 ? W1g : W2g) + (size_t)img * 1024;
        sWR[t * 1088 + (idx >> 5) * 34 + (idx & 31)] = Wsrc[idx];
    }
    {
        const int b0 = wid * 2, b1 = wid * 2 + 1;
        float sb0, cb0; sincospif((float)wid * (1.0f / 32.0f), &sb0, &cb0); // theta0 = 2pi*b0/128
        float sb1, cb1; sincospif((float)b1 * (1.0f / 64.0f), &sb1, &cb1);  // theta1
        const float T0 = 2.f * cb0, T1 = 2.f * cb1;
        float C0=0.f,S0=0.f,C1v=0.f,S1=0.f,C2a=0.f,S2a=0.f;
        float cw0=1.f, sw0=0.f, cp0=cb0, sp0=-sb0;
        float cw1=1.f, sw1=0.f, cp1=cb1, sp1=-sb1;
        float sg = 1.f;
#pragma unroll 1
        for (int seg = 0; seg < 2; ++seg) {
            if (seg) {  // exact restart at h=32: angle0 = pi*wid, angle1 = pi*b1/2
                float par = (wid & 1) ? -1.f : 1.f;
                cw0 = par;       sw0 = 0.f;
                cp0 = par * cb0; sp0 = -par * sb0;
                cw1 = 0.f;       sw1 = par;
                cp1 = par * sb1; sp1 = par * cb1;
            }
#pragma unroll
            for (int h0 = 0; h0 < 32; h0 += 2) {
                const int h = seg * 32 + h0;
                float4 d = *(const float4*)&sFD2[lane * 66 + h];
                float cn0 = T0 * cw0 - cp0, sn0 = T0 * sw0 - sp0;
                float cn1 = T1 * cw1 - cp1, sn1 = T1 * sw1 - sp1;
                C0  += cw0 * d.x + cn0 * d.z;  S0 += sw0 * d.y + sn0 * d.w;
                C1v += cw1 * d.x + cn1 * d.z;  S1 += sw1 * d.y + sn1 * d.w;
                // f=96 row: cos(3pi/2 h)=sg at even h; sin(3pi/2 (h+1))=-sg at odd h+1
                C2a += sg * d.x;               S2a -= sg * d.w;
                sg = -sg;
                float c20 = T0 * cn0 - cw0, s20 = T0 * sn0 - sw0;
                float c21 = T1 * cn1 - cw1, s21 = T1 * sn1 - sw1;
                cp0 = cn0; sp0 = sn0; cw0 = c20; sw0 = s20;
                cp1 = cn1; sp1 = sn1; cw1 = c21; sw1 = s21;
            }
        }
        {   // h = 64 tail: cos(pi*b) = (-1)^b, sin = 0 ; f=96: cos(96pi)=1
            float2 d = sFD2[lane * 66 + 64];
            C0 += d.x; C1v -= d.x; C2a += d.x;
        }
        const float sc = 1.0f / 16384.0f;
        sXf[b0 * 34 + lane] = (C0 + S0) * sc;
        if (b0 >= 1) sXf[(64 - b0) * 34 + lane] = (C0 - S0) * sc;
        sXf[b1 * 34 + lane] = (C1v + S1) * sc;
        sXf[(64 - b1) * 34 + lane] = (C1v - S1) * sc;
        if (wid == 0) sXf[32 * 34 + lane] = (C2a + S2a) * sc;
    }
    __syncthreads();

    // ======== Stage B: folded 32-DHTs ========
    {
        const int g = wid >> 3, role = (wid >> 2) & 1, w4 = wid & 3, w8 = wid & 7;
        float*  Xfg = sXf + g * 1088;
        float*  Wg  = sWR + g * 1088;
        float*  Ahg = sAH + g * 1088;
        float2* R1g = sR1 + g * 1056;
        float2* R2g = sR2 + g * 1056;

        float wv0[2], wv1[2]; float e16w = 0.f;
#pragma unroll
        for (int k = 0; k < 2; ++k) {
            int i = tid + k * THREADS;
            int gg = i >> 9, rem = i & 511, row = rem >> 4, w = rem & 15;
            const float* Ws = sWR + gg * 1088;
            wv0[k] = Ws[row * 34 + w];
            wv1[k] = (w == 0) ? 0.f : Ws[row * 34 + 32 - w];
        }
        if (tid < 64) e16w = (sWR + (tid >> 5) * 1088)[(tid & 31) * 34 + 16];
        for (int i = tid; i < 1024; i += THREADS) {
            int gg = i >> 9, rem = i & 511, row = rem >> 4, w = rem & 15;
            const float* A = sXf + gg * 1088;
            float* EO = sAH + gg * 1088;
            float av = A[row * 34 + w], e, o;
            if (w == 0) { e = av; o = 0.f; }
            else { float bv = A[row * 34 + 32 - w]; e = av + bv; o = av - bv; }
            EO[row * 32 + 2 * w] = e; EO[row * 32 + 2 * w + 1] = o;
        }
        if (tid < 64) (sAH + (tid >> 5) * 1088)[1024 + (tid & 31)] =
                          (sXf + (tid >> 5) * 1088)[(tid & 31) * 34 + 16];
        __syncthreads();
#pragma unroll
        for (int k = 0; k < 2; ++k) {
            int i = tid + k * THREADS;
            int gg = i >> 9, rem = i & 511, row = rem >> 4, w = rem & 15;
            float* EO = sWR + gg * 1088;
            float e, o;
            if (w == 0) { e = wv0[k]; o = 0.f; }
            else { e = wv0[k] + wv1[k]; o = wv0[k] - wv1[k]; }
            EO[row * 32 + 2 * w] = e; EO[row * 32 + 2 * w + 1] = o;
        }
        if (tid < 64) (sWR + (tid >> 5) * 1088)[1024 + (tid & 31)] = e16w;
        __syncthreads();

        if (role == 0) dht32_p1f<8>(Ahg, R1g, w4 * 8, lane);
        else           dht32_p1f<8>(Wg,  R2g, w4 * 8, lane);
        __syncthreads();
        for (int i = tid; i < 2176; i += THREADS) {
            int chain = i / 1088; int r2i = i - chain * 1088;
            int gg = r2i / 544; int r3 = r2i - gg * 544; int h = r3 >> 5, col = r3 & 31;
            float2* Rb = ((chain == 0) ? sR1 : sR2) + gg * 1056;
            float2 pm;
            if (h == 0)       { float2 v = Rb[col];            pm = make_float2(v.x, 0.f); }
            else if (h == 16) { float2 v = Rb[16 * 33 + col];  pm = make_float2(v.x, 0.f); }
            else { float2 va = Rb[h * 33 + col], vb = Rb[(32 - h) * 33 + col];
                   pm = make_float2(va.x + vb.x, va.y - vb.y); }
            Rb[h * 33 + col] = pm;
        }
        __syncthreads();
        if (role == 0) dht32_p2f<8>(R1g, sCS32, Ahg, 1.0f / 1024.0f, w4 * 8, lane);
        else           dht32_p2f<8>(R2g, sCS32, Wg,  1.0f / 1024.0f, w4 * 8, lane);
        __syncthreads();

        for (int i = tid; i < 1024; i += THREADS) {
            int gg = i >> 9, rem = i & 511, row = rem >> 4, w = rem & 15;
            const float* Ah = sAH + gg * 1088; const float* Wh = sWR + gg * 1088;
            float* EO = sXf + gg * 1088;
            float pv = Ah[row * 34 + w] * Wh[row * 34 + w], e, o;
            if (w == 0) { e = pv; o = 0.f; }
            else { float qv = Ah[row * 34 + 32 - w] * Wh[row * 34 + 32 - w];
                   e = pv + qv; o = pv - qv; }
            EO[row * 32 + 2 * w] = e; EO[row * 32 + 2 * w + 1] = o;
        }
        if (tid < 64) {
            int gg = tid >> 5, row = tid & 31;
            (sXf + gg * 1088)[1024 + row] =
                (sAH + gg * 1088)[row * 34 + 16] * (sWR + gg * 1088)[row * 34 + 16];
        }
        __syncthreads();
        dht32_p1f<4>(Xfg, R1g, w8 * 4, lane);
        __syncthreads();
        for (int i = tid; i < 1088; i += THREADS) {
            int gg = i / 544; int r3 = i - gg * 544; int h = r3 >> 5, col = r3 & 31;
            float2* Rb = sR1 + gg * 1056;
            float2 pm;
            if (h == 0)       { float2 v = Rb[col];            pm = make_float2(v.x, 0.f); }
            else if (h == 16) { float2 v = Rb[16 * 33 + col];  pm = make_float2(v.x, 0.f); }
            else { float2 va = Rb[h * 33 + col], vb = Rb[(32 - h) * 33 + col];
                   pm = make_float2(va.x + vb.x, va.y - vb.y); }
            Rb[h * 33 + col] = pm;
        }
        __syncthreads();
        dht32_p2f<4>(R1g, sCS32, Xfg, 1.0f / 65536.0f, w8 * 4, lane);
        __syncthreads();
    }

    // ---- C1 prep ----
    for (int i = tid; i < 33 * 32; i += THREADS) {
        int b = i >> 5, s = i & 31;
        float gp, gm;
        if (b == 0)      { gp = sXf[s];             gm = 0.f; }
        else if (b == 32){ gp = sXf[32 * 34 + s];   gm = gp;  }
        else {
            float xa = sXf[b * 34 + s], xb = sXf[(64 - b) * 34 + s];
            gp = xa + xb; gm = xa - xb;
        }
        sGp[b * 34 + s] = gp; sGm[b * 34 + s] = gm;
    }
    __syncthreads();

    // ---- Stage C1: register twiddles over b (4 rows/warp) ----
    {
        const int hb = wid * 4;
        float cj[4], sj[4], cp[4], sp[4], T[4];
#pragma unroll
        for (int j = 0; j < 4; ++j) {
            float st, ct; sincospif((float)(hb + j) * (1.0f / 64.0f), &st, &ct);
            T[j] = 2.f * ct; cj[j] = 1.f; sj[j] = 0.f; cp[j] = ct; sp[j] = -st;
        }
        float Uc[4] = {0,0,0,0}, Us[4] = {0,0,0,0};
#pragma unroll 4
        for (int b = 0; b < 32; ++b) {
            float gp = sGp[b * 34 + lane];
            float gm = sGm[b * 34 + lane];
#pragma unroll
            for (int j = 0; j < 4; ++j) {
                Uc[j] += cj[j] * gp; Us[j] += sj[j] * gm;
                float cn = T[j] * cj[j] - cp[j], sn = T[j] * sj[j] - sp[j];
                cp[j] = cj[j]; sp[j] = sj[j]; cj[j] = cn; sj[j] = sn;
            }
        }
        {   // b = 32 tail (f=96): cos(3pi h'/2): m0:+1 m2:-1 ; sin: m1:-1 m3:+1
            float gp32 = sGp[32 * 34 + lane];
#pragma unroll
            for (int j = 0; j < 4; ++j) {
                int m = (hb + j) & 3;
                if (m == 0)      Uc[j] += gp32;
                else if (m == 1) Us[j] -= gp32;
                else if (m == 2) Uc[j] -= gp32;
                else             Us[j] += gp32;
            }
        }
#pragma unroll
        for (int j = 0; j < 4; ++j)
            sU[(hb + j) * 34 + lane] = make_float2(Uc[j] + Us[j], Uc[j] - Us[j]);
    }
    if (tid < 32) {
        float acc = 0.f;
#pragma unroll 1
        for (int b = 0; b < 32; b += 2)
            acc += sGp[b * 34 + tid] - sGp[(b + 1) * 34 + tid];
        acc += sGp[32 * 34 + tid];
        sU[64 * 34 + tid] = make_float2(acc, acc);
    }
    __syncthreads();

    for (int i = tid; i < 63 * 32; i += THREADS) {
        int r = 65 + (i >> 5), s = i & 31;
        float2 v = sU[(128 - r) * 34 + s];
        sU[r * 34 + s] = make_float2(v.y, v.x);
    }
    __syncthreads();

    // ---- Stage C2: register twiddles, 2 rows x 4 quarter-passes ----
    {
        const float sc = 1.0f / 1048576.0f;
        const int wp = lane;
        const int wq = lane ? (64 - lane) : 32;
        float s1p, c1p; sincospif((float)wp * (1.0f / 64.0f), &s1p, &c1p);
        float s1q, c1q; sincospif((float)wq * (1.0f / 64.0f), &s1q, &c1q);
        const float t2p = 2.0f * c1p, t2q = 2.0f * c1q;
        float s16p, c16p; sincospif((float)wp * 0.25f, &s16p, &c16p);
        float s16q, c16q; sincospif((float)wq * 0.25f, &s16q, &c16q);
#pragma unroll 1
        for (int qtr = 0; qtr < 4; ++qtr) {
            const int hb = wid * 8 + qtr * 2;
            float A[2]  = {0,0}, B[2]  = {0,0};
            float Ap[2] = {0,0}, Bp[2] = {0,0};
            float cwp = 1.f, swp = 0.f, cppv = c1p, sppv = -s1p;
            float cwq = 1.f, swq = 0.f, cqpv = c1q, sqpv = -s1q;
#pragma unroll 1
            for (int seg = 0; seg < 2; ++seg) {
                if (seg == 1) {
                    cwp = c16p; swp = s16p;
                    cppv = c16p * c1p + s16p * s1p;
                    sppv = s16p * c1p - c16p * s1p;
                    cwq = c16q; swq = s16q;
                    cqpv = c16q * c1q + s16q * s1q;
                    sqpv = s16q * c1q - c16q * s1q;
                }
#pragma unroll
                for (int s0 = 0; s0 < 16; s0 += 2) {
                    const int s = seg * 16 + s0;
                    float cnp = t2p * cwp - cppv, snp = t2p * swp - sppv;
                    float cnq = t2q * cwq - cqpv, snq = t2q * swq - sqpv;
#pragma unroll
                    for (int j = 0; j < 2; ++j) {
                        float4 uu = *(const float4*)&sU[(hb + j) * 34 + s];
                        A[j]  += uu.x * cwp + uu.z * cnp;
                        B[j]  += uu.y * swp + uu.w * snp;
                        Ap[j] += uu.x * cwq + uu.z * cnq;
                        Bp[j] += uu.y * swq + uu.w * snq;
                    }
                    float cn2p = t2p * cnp - cwp, sn2p = t2p * snp - swp;
                    float cn2q = t2q * cnq - cwq, sn2q = t2q * snq - swq;
                    cppv = cnp; sppv = snp; cwp = cn2p; swp = sn2p;
                    cqpv = cnq; sqpv = snq; cwq = cn2q; swq = sn2q;
                }
            }
#pragma unroll
            for (int j = 0; j < 2; ++j) {
                O[(hb + j) * 128 + wp] = (A[j] + B[j]) * sc;
                if (wp) O[(hb + j) * 128 + (128 - wp)] = (A[j] - B[j]) * sc;
                O[(hb + j) * 128 + wq] = (Ap[j] + Bp[j]) * sc;
                O[(hb + j) * 128 + (128 - wq)] = (Ap[j] - Bp[j]) * sc;
            }
        }
    }
    if (tid < 128) {
        float acc = 0.f;
#pragma unroll 4
        for (int s = 0; s < 32; s += 2)
            acc += sU[tid * 34 + s].x - sU[tid * 34 + s + 1].x;
        O[tid * 128 + 64] = acc * (1.0f / 1048576.0f);
    }
}

extern "C" void kernel_launch(void* const* d_in, const int* in_sizes, int n_in,
                              void* d_out, int out_size)
{
    const float* x  = (const float*)d_in[0];
    const float* w1 = (const float*)d_in[1];
    const float* w2 = (const float*)d_in[2];
    float* out = (float*)d_out;

    const int smem_bytes = F_TOT * 4; // 69632
    cudaFuncSetAttribute(spectral_kernel,
                         cudaFuncAttributeMaxDynamicSharedMemorySize, smem_bytes);
    spectral_kernel<<<4096, THREADS, smem_bytes>>>(x, w1, w2, out);
}

// round 12
// speedup vs baseline: 2.2891x; 1.0298x over previous
#include <cuda_runtime.h>
#define THREADS 512

// float offsets in dynamic smem (total 17408 floats = 69632 B -> 3 CTAs/SM)
#define O_SD   0       // region 8704 f : SD[128][34]f2 | {WR,AH,R1} | {U,Gp,Gm}
#define O_BIG  8704    // region 8704 f : {XE,XO} | {FD2,Xf,CS32} | {R2,Xf,CS32} | {CS2 table}
#define F_TOT  17408

#define SD_WR   0
#define SD_AH   2176
#define SD_R1   4352
#define SD_GP   4420
#define SD_GM   5542
#define BG_XO   4352
#define BG_XF   4352
#define BG_CS32 6528

// folded 32-DHT pass1 with register twiddles: EO layout (E,O) pairs at
// [row*32+2w] (w=0..15), E16 at [1024+row]
template<int NR>
static __device__ __forceinline__ void dht32_p1f(const float* __restrict__ eo,
                                                 float2* __restrict__ R,
                                                 int h0, int lane)
{
    float r1[NR], r2[NR];
#pragma unroll
    for (int r = 0; r < NR; ++r) { r1[r] = 0.f; r2[r] = 0.f; }
    float s1, c1; sincospif((float)lane * (1.0f / 16.0f), &s1, &c1);
    const float t2 = 2.0f * c1;
    float cw = 1.f, sw = 0.f, cpv = c1, spv = -s1;
#pragma unroll
    for (int w = 0; w < 16; w += 2) {
        float cn = t2 * cw - cpv, sn = t2 * sw - spv;
#pragma unroll
        for (int r = 0; r < NR; ++r) {
            float4 e = *(const float4*)&eo[(h0 + r) * 32 + 2 * w];
            r1[r] += e.x * cw + e.z * cn;
            r2[r] += e.y * sw + e.w * sn;
        }
        float cn2 = t2 * cn - cw, sn2 = t2 * sn - sw;
        cpv = cn; spv = sn; cw = cn2; sw = sn2;
    }
    const float sgn = (lane & 1) ? -1.f : 1.f;
#pragma unroll
    for (int r = 0; r < NR; ++r) {
        float t1 = r1[r] + sgn * eo[1024 + h0 + r];
        R[(h0 + r) * 33 + lane] = make_float2(t1 + r2[r], t1 - r2[r]);
    }
}

// folded pass2: broadcast cs32 table reads
template<int NR>
static __device__ __forceinline__ void dht32_p2f(const float2* __restrict__ R,
                                                 const float2* __restrict__ cs32,
                                                 float* __restrict__ dst,
                                                 float scale, int u0, int lane)
{
    float acc[NR];
#pragma unroll
    for (int r = 0; r < NR; ++r) acc[r] = 0.f;
#pragma unroll
    for (int h = 0; h < 16; h += 2) {
        float2 a = R[h * 33 + lane], b = R[(h + 1) * 33 + lane];
#pragma unroll
        for (int r = 0; r < NR; ++r) {
            float4 cs = *(const float4*)&cs32[(u0 + r) * 34 + h];
            acc[r] += cs.x * a.x + cs.y * a.y + cs.z * b.x + cs.w * b.y;
        }
    }
    float p16 = R[16 * 33 + lane].x;
#pragma unroll
    for (int r = 0; r < NR; ++r) {
        float sg = ((u0 + r) & 1) ? -p16 : p16;
        dst[(u0 + r) * 34 + lane] = (acc[r] + sg) * scale;
    }
}

__global__ __launch_bounds__(THREADS, 3)
void spectral_kernel(const float* __restrict__ Xg,
                     const float* __restrict__ W1g,
                     const float* __restrict__ W2g,
                     float* __restrict__ Og)
{
    extern __shared__ float sm[];
    float2* sSD   = (float2*)(sm + O_SD);
    float*  sWR   = sm + O_SD + SD_WR;
    float*  sAH   = sm + O_SD + SD_AH;
    float2* sR1   = (float2*)(sm + O_SD + SD_R1);
    float2* sU    = (float2*)(sm + O_SD);
    float*  sGp   = sm + O_SD + SD_GP;
    float*  sGm   = sm + O_SD + SD_GM;
    float*  sXE   = sm + O_BIG;
    float*  sXO   = sm + O_BIG + BG_XO;
    float2* sFD2  = (float2*)(sm + O_BIG);
    float*  sXf   = sm + O_BIG + BG_XF;
    float2* sCS32 = (float2*)(sm + O_BIG + BG_CS32);
    float2* sR2   = (float2*)(sm + O_BIG);
    float2* sCS2  = (float2*)(sm + O_BIG);    // C2 twiddle table [33][34], built after stage B

    const int tid  = threadIdx.x;
    const int lane = tid & 31;
    const int wid  = tid >> 5;
    const int img  = blockIdx.x;
    const float* X = Xg + (size_t)img * 16384;
    float*       O = Og + (size_t)img * 16384;

    // ---- Stage A1, two passes of 64 rows; register twiddles ----
#pragma unroll 1
    for (int pass = 0; pass < 2; ++pass) {
        for (int i = tid; i < 64 * 64; i += THREADS) {
            int hl = i >> 6, w = i & 63;
            int h = pass * 64 + hl;
            float a = X[h * 128 + w];
            float e, o;
            if (w == 0) { e = a; o = 0.f; }
            else { float b = X[h * 128 + 128 - w]; e = a + b; o = a - b; }
            sXE[hl * 68 + w] = e; sXO[hl * 68 + w] = o;
        }
        if (tid < 64) sXE[tid * 68 + 64] = X[(pass * 64 + tid) * 128 + 64];
        __syncthreads();

        const int r0 = wid * 4;
        float s1, c1; sincospif((float)lane * (1.0f / 64.0f), &s1, &c1);
        const float t2 = 2.0f * c1;
        float a1[4] = {0,0,0,0}, a2[4] = {0,0,0,0};
        float cw = 1.f, sw = 0.f, cpv = c1, spv = -s1;
#pragma unroll 1
        for (int seg = 0; seg < 2; ++seg) {
            if (seg == 1) {
                float s32, c32; sincospif((float)lane * 0.5f, &s32, &c32);
                cw = c32; sw = s32;
                cpv = c32 * c1 + s32 * s1;
                spv = s32 * c1 - c32 * s1;
            }
            const int wb = seg * 32;
#pragma unroll
            for (int w0 = 0; w0 < 32; w0 += 4) {
                const int w = wb + w0;
                float cA = cw, sA = sw;
                float cB = t2 * cA - cpv, sB = t2 * sA - spv;
                float cC = t2 * cB - cA,  sC = t2 * sB - sA;
                float cD = t2 * cC - cB,  sD = t2 * sC - sB;
                float cE = t2 * cD - cC,  sE = t2 * sD - sC;
                cpv = cD; spv = sD; cw = cE; sw = sE;
#pragma unroll
                for (int r = 0; r < 4; ++r) {
                    float4 e = *(const float4*)&sXE[(r0 + r) * 68 + w];
                    float4 o = *(const float4*)&sXO[(r0 + r) * 68 + w];
                    a1[r] += e.x * cA + e.y * cB + e.z * cC + e.w * cD;
                    a2[r] += o.x * sA + o.y * sB + o.z * sC + o.w * sD;
                }
            }
        }
        {
            const float sg64 = (lane & 1) ? -1.f : 1.f;
#pragma unroll
            for (int r = 0; r < 4; ++r) a1[r] += sXE[(r0 + r) * 68 + 64] * sg64;
        }
#pragma unroll
        for (int r = 0; r < 4; ++r)
            sSD[(pass * 64 + r0 + r) * 34 + lane] = make_float2(a1[r] + a2[r], a1[r] - a2[r]);
        __syncthreads();
    }

    // ---- fold SD -> FD2 (pow2 index) ; build CS32 ----
    for (int i = tid; i < 2048; i += THREADS) {   // 32 v x 64 h
        int v = i >> 6, h = i & 63;
        float2 a = sSD[h * 34 + v];
        float sp, dm;
        if (h == 0) { sp = a.x; dm = 0.f; }
        else { float2 b = sSD[(128 - h) * 34 + v]; sp = a.x + b.x; dm = a.y - b.y; }
        sFD2[v * 66 + h] = make_float2(sp, dm);
    }
    if (tid < 32) {   // h = 64 tail
        float2 a = sSD[64 * 34 + tid];
        sFD2[tid * 66 + 64] = make_float2(a.x, 0.f);
    }
    for (int i = tid; i < 32 * 32; i += THREADS) {
        int u = i >> 5, h = i & 31;
        float s, c; sincospif((float)((u * h) & 31) * (1.0f / 16.0f), &s, &c);
        sCS32[u * 34 + h] = make_float2(c, s);
    }
    __syncthreads();

    // ---- Stage A2 (register twiddles over h) + weight load ----
    for (int i = tid; i < 2048; i += THREADS) {
        int t = i >> 10, idx = i & 1023;
        const float* Wsrc = (t == 0 ? W1g : W2g) + (size_t)img * 1024;
        sWR[t * 1088 + (idx >> 5) * 34 + (idx & 31)] = Wsrc[idx];
    }
    {
        const int b0 = wid * 2, b1 = wid * 2 + 1;
        float sb0, cb0; sincospif((float)wid * (1.0f / 32.0f), &sb0, &cb0);
        float sb1, cb1; sincospif((float)b1 * (1.0f / 64.0f), &sb1, &cb1);
        const float T0 = 2.f * cb0, T1 = 2.f * cb1;
        float C0=0.f,S0=0.f,C1v=0.f,S1=0.f;
        float cw0=1.f, sw0=0.f, cp0=cb0, sp0=-sb0;
        float cw1=1.f, sw1=0.f, cp1=cb1, sp1=-sb1;
#pragma unroll 1
        for (int seg = 0; seg < 2; ++seg) {
            if (seg) {  // exact restart at h=32
                float par = (wid & 1) ? -1.f : 1.f;
                cw0 = par;       sw0 = 0.f;
                cp0 = par * cb0; sp0 = -par * sb0;
                cw1 = 0.f;       sw1 = par;
                cp1 = par * sb1; sp1 = par * cb1;
            }
#pragma unroll
            for (int h0 = 0; h0 < 32; h0 += 2) {
                const int h = seg * 32 + h0;
                float4 d = *(const float4*)&sFD2[lane * 66 + h];
                float cn0 = T0 * cw0 - cp0, sn0 = T0 * sw0 - sp0;
                float cn1 = T1 * cw1 - cp1, sn1 = T1 * sw1 - sp1;
                C0  += cw0 * d.x + cn0 * d.z;  S0 += sw0 * d.y + sn0 * d.w;
                C1v += cw1 * d.x + cn1 * d.z;  S1 += sw1 * d.y + sn1 * d.w;
                float c20 = T0 * cn0 - cw0, s20 = T0 * sn0 - sw0;
                float c21 = T1 * cn1 - cw1, s21 = T1 * sn1 - sw1;
                cp0 = cn0; sp0 = sn0; cw0 = c20; sw0 = s20;
                cp1 = cn1; sp1 = sn1; cw1 = c21; sw1 = s21;
            }
        }
        {   // h = 64 tail: cos(pi*b) = (-1)^b, sin = 0
            float2 d = sFD2[lane * 66 + 64];
            C0 += d.x; C1v -= d.x;
        }
        const float sc = 1.0f / 16384.0f;
        sXf[b0 * 34 + lane] = (C0 + S0) * sc;
        if (b0 >= 1) sXf[(64 - b0) * 34 + lane] = (C0 - S0) * sc;
        sXf[b1 * 34 + lane] = (C1v + S1) * sc;
        sXf[(64 - b1) * 34 + lane] = (C1v - S1) * sc;
    }
    if (wid == 0) {   // f=96 row, computed once
        float C2a = 0.f, S2a = 0.f, sg = 1.f;
#pragma unroll 4
        for (int h = 0; h < 64; h += 2) {
            float4 d = *(const float4*)&sFD2[lane * 66 + h];
            C2a += sg * d.x; S2a -= sg * d.w; sg = -sg;
        }
        C2a += sFD2[lane * 66 + 64].x;
        sXf[32 * 34 + lane] = (C2a + S2a) * (1.0f / 16384.0f);
    }
    __syncthreads();

    // ======== Stage B: folded 32-DHTs ========
    {
        const int g = wid >> 3, role = (wid >> 2) & 1, w4 = wid & 3, w8 = wid & 7;
        float*  Xfg = sXf + g * 1088;
        float*  Wg  = sWR + g * 1088;
        float*  Ahg = sAH + g * 1088;
        float2* R1g = sR1 + g * 1056;
        float2* R2g = sR2 + g * 1056;

        float wv0[2], wv1[2]; float e16w = 0.f;
#pragma unroll
        for (int k = 0; k < 2; ++k) {
            int i = tid + k * THREADS;
            int gg = i >> 9, rem = i & 511, row = rem >> 4, w = rem & 15;
            const float* Ws = sWR + gg * 1088;
            wv0[k] = Ws[row * 34 + w];
            wv1[k] = (w == 0) ? 0.f : Ws[row * 34 + 32 - w];
        }
        if (tid < 64) e16w = (sWR + (tid >> 5) * 1088)[(tid & 31) * 34 + 16];
        for (int i = tid; i < 1024; i += THREADS) {
            int gg = i >> 9, rem = i & 511, row = rem >> 4, w = rem & 15;
            const float* A = sXf + gg * 1088;
            float* EO = sAH + gg * 1088;
            float av = A[row * 34 + w], e, o;
            if (w == 0) { e = av; o = 0.f; }
            else { float bv = A[row * 34 + 32 - w]; e = av + bv; o = av - bv; }
            EO[row * 32 + 2 * w] = e; EO[row * 32 + 2 * w + 1] = o;
        }
        if (tid < 64) (sAH + (tid >> 5) * 1088)[1024 + (tid & 31)] =
                          (sXf + (tid >> 5) * 1088)[(tid & 31) * 34 + 16];
        __syncthreads();
#pragma unroll
        for (int k = 0; k < 2; ++k) {
            int i = tid + k * THREADS;
            int gg = i >> 9, rem = i & 511, row = rem >> 4, w = rem & 15;
            float* EO = sWR + gg * 1088;
            float e, o;
            if (w == 0) { e = wv0[k]; o = 0.f; }
            else { e = wv0[k] + wv1[k]; o = wv0[k] - wv1[k]; }
            EO[row * 32 + 2 * w] = e; EO[row * 32 + 2 * w + 1] = o;
        }
        if (tid < 64) (sWR + (tid >> 5) * 1088)[1024 + (tid & 31)] = e16w;
        __syncthreads();

        if (role == 0) dht32_p1f<8>(Ahg, R1g, w4 * 8, lane);
        else           dht32_p1f<8>(Wg,  R2g, w4 * 8, lane);
        __syncthreads();
        // fold R (pow2 main + h=16 tail)
        for (int i = tid; i < 2048; i += THREADS) {
            int col = i & 31, h = (i >> 5) & 15, gg = (i >> 9) & 1, chain = i >> 10;
            float2* Rb = ((chain == 0) ? sR1 : sR2) + gg * 1056;
            float2 pm;
            if (h == 0) { float2 v = Rb[col]; pm = make_float2(v.x, 0.f); }
            else { float2 va = Rb[h * 33 + col], vb = Rb[(32 - h) * 33 + col];
                   pm = make_float2(va.x + vb.x, va.y - vb.y); }
            Rb[h * 33 + col] = pm;
        }
        if (tid < 128) {
            int col = tid & 31, gg = (tid >> 5) & 1, chain = tid >> 6;
            float2* Rb = ((chain == 0) ? sR1 : sR2) + gg * 1056;
            float2 v = Rb[16 * 33 + col];
            Rb[16 * 33 + col] = make_float2(v.x, 0.f);
        }
        __syncthreads();
        if (role == 0) dht32_p2f<8>(R1g, sCS32, Ahg, 1.0f / 1024.0f, w4 * 8, lane);
        else           dht32_p2f<8>(R2g, sCS32, Wg,  1.0f / 1024.0f, w4 * 8, lane);
        __syncthreads();

        for (int i = tid; i < 1024; i += THREADS) {
            int gg = i >> 9, rem = i & 511, row = rem >> 4, w = rem & 15;
            const float* Ah = sAH + gg * 1088; const float* Wh = sWR + gg * 1088;
            float* EO = sXf + gg * 1088;
            float pv = Ah[row * 34 + w] * Wh[row * 34 + w], e, o;
            if (w == 0) { e = pv; o = 0.f; }
            else { float qv = Ah[row * 34 + 32 - w] * Wh[row * 34 + 32 - w];
                   e = pv + qv; o = pv - qv; }
            EO[row * 32 + 2 * w] = e; EO[row * 32 + 2 * w + 1] = o;
        }
        if (tid < 64) {
            int gg = tid >> 5, row = tid & 31;
            (sXf + gg * 1088)[1024 + row] =
                (sAH + gg * 1088)[row * 34 + 16] * (sWR + gg * 1088)[row * 34 + 16];
        }
        __syncthreads();
        dht32_p1f<4>(Xfg, R1g, w8 * 4, lane);
        __syncthreads();
        for (int i = tid; i < 1024; i += THREADS) {
            int col = i & 31, h = (i >> 5) & 15, gg = i >> 9;
            float2* Rb = sR1 + gg * 1056;
            float2 pm;
            if (h == 0) { float2 v = Rb[col]; pm = make_float2(v.x, 0.f); }
            else { float2 va = Rb[h * 33 + col], vb = Rb[(32 - h) * 33 + col];
                   pm = make_float2(va.x + vb.x, va.y - vb.y); }
            Rb[h * 33 + col] = pm;
        }
        if (tid < 64) {
            int col = tid & 31, gg = tid >> 5;
            float2* Rb = sR1 + gg * 1056;
            float2 v = Rb[16 * 33 + col];
            Rb[16 * 33 + col] = make_float2(v.x, 0.f);
        }
        __syncthreads();
        dht32_p2f<4>(R1g, sCS32, Xfg, 1.0f / 65536.0f, w8 * 4, lane);
        __syncthreads();
    }

    // ---- C1 prep: Gp/Gm + build C2 twiddle table (R2/FD2 region dead) ----
    for (int i = tid; i < 33 * 32; i += THREADS) {
        int b = i >> 5, s = i & 31;
        float gp, gm;
        if (b == 0)      { gp = sXf[s];             gm = 0.f; }
        else if (b == 32){ gp = sXf[32 * 34 + s];   gm = gp;  }
        else {
            float xa = sXf[b * 34 + s], xb = sXf[(64 - b) * 34 + s];
            gp = xa + xb; gm = xa - xb;
        }
        sGp[b * 34 + s] = gp; sGm[b * 34 + s] = gm;
    }
    for (int i = tid; i < 33 * 32; i += THREADS) {
        int w = i >> 5, v = i & 31;
        float s, c; sincospif((float)((w * v) & 127) * (1.0f / 64.0f), &s, &c);
        sCS2[w * 34 + v] = make_float2(c, s);
    }
    __syncthreads();

    // ---- Stage C1: register twiddles over b (4 rows/warp) ----
    {
        const int hb = wid * 4;
        float cj[4], sj[4], cp[4], sp[4], T[4];
#pragma unroll
        for (int j = 0; j < 4; ++j) {
            float st, ct; sincospif((float)(hb + j) * (1.0f / 64.0f), &st, &ct);
            T[j] = 2.f * ct; cj[j] = 1.f; sj[j] = 0.f; cp[j] = ct; sp[j] = -st;
        }
        float Uc[4] = {0,0,0,0}, Us[4] = {0,0,0,0};
#pragma unroll 4
        for (int b = 0; b < 32; ++b) {
            float gp = sGp[b * 34 + lane];
            float gm = sGm[b * 34 + lane];
#pragma unroll
            for (int j = 0; j < 4; ++j) {
                Uc[j] += cj[j] * gp; Us[j] += sj[j] * gm;
                float cn = T[j] * cj[j] - cp[j], sn = T[j] * sj[j] - sp[j];
                cp[j] = cj[j]; sp[j] = sj[j]; cj[j] = cn; sj[j] = sn;
            }
        }
        {   // b = 32 tail (f=96): cos(3pi h'/2): m0:+1 m2:-1 ; sin: m1:-1 m3:+1
            float gp32 = sGp[32 * 34 + lane];
#pragma unroll
            for (int j = 0; j < 4; ++j) {
                int m = (hb + j) & 3;
                if (m == 0)      Uc[j] += gp32;
                else if (m == 1) Us[j] -= gp32;
                else if (m == 2) Uc[j] -= gp32;
                else             Us[j] += gp32;
            }
        }
#pragma unroll
        for (int j = 0; j < 4; ++j)
            sU[(hb + j) * 34 + lane] = make_float2(Uc[j] + Us[j], Uc[j] - Us[j]);
    }
    if (tid < 32) {
        float acc = 0.f;
#pragma unroll 1
        for (int b = 0; b < 32; b += 2)
            acc += sGp[b * 34 + tid] - sGp[(b + 1) * 34 + tid];
        acc += sGp[32 * 34 + tid];
        sU[64 * 34 + tid] = make_float2(acc, acc);
    }
    __syncthreads();

    for (int i = tid; i < 63 * 32; i += THREADS) {
        int r = 65 + (i >> 5), s = i & 31;
        float2 v = sU[(128 - r) * 34 + s];
        sU[r * 34 + s] = make_float2(v.y, v.x);
    }
    __syncthreads();

    // ---- Stage C2: exact table + partner column, 2 rows x 4 quarter-passes ----
    {
        const float sc = 1.0f / 1048576.0f;
        const int wp = lane;
        const int wq = lane ? (64 - lane) : 32;
#pragma unroll 1
        for (int qtr = 0; qtr < 4; ++qtr) {
            const int hb = wid * 8 + qtr * 2;
            float A[2]  = {0,0}, B[2]  = {0,0};
            float Ap[2] = {0,0}, Bp[2] = {0,0};
#pragma unroll 4
            for (int s = 0; s < 32; s += 2) {
                float4 cs = *(const float4*)&sCS2[wp * 34 + s];
                float4 cp;
                if (lane == 0) cp = *(const float4*)&sCS2[32 * 34 + s];
                else           cp = make_float4(cs.x, -cs.y, -cs.z, cs.w);
#pragma unroll
                for (int j = 0; j < 2; ++j) {
                    float4 uu = *(const float4*)&sU[(hb + j) * 34 + s];
                    A[j]  += uu.x * cs.x + uu.z * cs.z;
                    B[j]  += uu.y * cs.y + uu.w * cs.w;
                    Ap[j] += uu.x * cp.x + uu.z * cp.z;
                    Bp[j] += uu.y * cp.y + uu.w * cp.w;
                }
            }
#pragma unroll
            for (int j = 0; j < 2; ++j) {
                O[(hb + j) * 128 + wp] = (A[j] + B[j]) * sc;
                if (wp) O[(hb + j) * 128 + (128 - wp)] = (A[j] - B[j]) * sc;
                O[(hb + j) * 128 + wq] = (Ap[j] + Bp[j]) * sc;
                O[(hb + j) * 128 + (128 - wq)] = (Ap[j] - Bp[j]) * sc;
            }
        }
    }
    if (tid < 128) {
        float acc = 0.f;
#pragma unroll 4
        for (int s = 0; s < 32; s += 2)
            acc += sU[tid * 34 + s].x - sU[tid * 34 + s + 1].x;
        O[tid * 128 + 64] = acc * (1.0f / 1048576.0f);
    }
}

extern "C" void kernel_launch(void* const* d_in, const int* in_sizes, int n_in,
                              void* d_out, int out_size)
{
    const float* x  = (const float*)d_in[0];
    const float* w1 = (const float*)d_in[1];
    const float* w2 = (const float*)d_in[2];
    float* out = (float*)d_out;

    const int smem_bytes = F_TOT * 4; // 69632
    cudaFuncSetAttribute(spectral_kernel,
                         cudaFuncAttributeMaxDynamicSharedMemorySize, smem_bytes);
    spectral_kernel<<<4096, THREADS, smem_bytes>>>(x, w1, w2, out);
}

// round 13
// speedup vs baseline: 2.3479x; 1.0257x over previous
#include <cuda_runtime.h>
#define THREADS 512

// float offsets in dynamic smem (total 17408 floats = 69632 B -> 3 CTAs/SM)
#define O_SD   0       // region 8704 f : SD[128][34]f2 | {WR,AH,R1} | {U,Gp,Gm}
#define O_BIG  8704    // region 8704 f : {XE,XO} | {FD2,Xf,CS32} | {R2,Xf,CS32} | {CS2}
#define F_TOT  17408

#define SD_WR   0
#define SD_AH   2176
#define SD_R1   4352
#define SD_GP   4420
#define SD_GM   5542
#define BG_XO   4352
#define BG_XF   4352
#define BG_CS32 6528

// folded 32-DHT pass1 with register twiddles: EO layout (E,O) pairs at
// [row*32+2w] (w=0..15), E16 at [1024+row]
template<int NR>
static __device__ __forceinline__ void dht32_p1f(const float* __restrict__ eo,
                                                 float2* __restrict__ R,
                                                 int h0, int lane)
{
    float r1[NR], r2[NR];
#pragma unroll
    for (int r = 0; r < NR; ++r) { r1[r] = 0.f; r2[r] = 0.f; }
    float s1, c1; sincospif((float)lane * (1.0f / 16.0f), &s1, &c1);
    const float t2 = 2.0f * c1;
    float cw = 1.f, sw = 0.f, cpv = c1, spv = -s1;
#pragma unroll
    for (int w = 0; w < 16; w += 2) {
        float cn = t2 * cw - cpv, sn = t2 * sw - spv;
#pragma unroll
        for (int r = 0; r < NR; ++r) {
            float4 e = *(const float4*)&eo[(h0 + r) * 32 + 2 * w];
            r1[r] += e.x * cw + e.z * cn;
            r2[r] += e.y * sw + e.w * sn;
        }
        float cn2 = t2 * cn - cw, sn2 = t2 * sn - sw;
        cpv = cn; spv = sn; cw = cn2; sw = sn2;
    }
    const float sgn = (lane & 1) ? -1.f : 1.f;
#pragma unroll
    for (int r = 0; r < NR; ++r) {
        float t1 = r1[r] + sgn * eo[1024 + h0 + r];
        R[(h0 + r) * 33 + lane] = make_float2(t1 + r2[r], t1 - r2[r]);
    }
}

// folded pass2: broadcast cs32 table reads
template<int NR>
static __device__ __forceinline__ void dht32_p2f(const float2* __restrict__ R,
                                                 const float2* __restrict__ cs32,
                                                 float* __restrict__ dst,
                                                 float scale, int u0, int lane)
{
    float acc[NR];
#pragma unroll
    for (int r = 0; r < NR; ++r) acc[r] = 0.f;
#pragma unroll
    for (int h = 0; h < 16; h += 2) {
        float2 a = R[h * 33 + lane], b = R[(h + 1) * 33 + lane];
#pragma unroll
        for (int r = 0; r < NR; ++r) {
            float4 cs = *(const float4*)&cs32[(u0 + r) * 34 + h];
            acc[r] += cs.x * a.x + cs.y * a.y + cs.z * b.x + cs.w * b.y;
        }
    }
    float p16 = R[16 * 33 + lane].x;
#pragma unroll
    for (int r = 0; r < NR; ++r) {
        float sg = ((u0 + r) & 1) ? -p16 : p16;
        dst[(u0 + r) * 34 + lane] = (acc[r] + sg) * scale;
    }
}

__global__ __launch_bounds__(THREADS, 3)
void spectral_kernel(const float* __restrict__ Xg,
                     const float* __restrict__ W1g,
                     const float* __restrict__ W2g,
                     float* __restrict__ Og)
{
    extern __shared__ float sm[];
    float2* sSD   = (float2*)(sm + O_SD);
    float*  sWR   = sm + O_SD + SD_WR;
    float*  sAH   = sm + O_SD + SD_AH;
    float2* sR1   = (float2*)(sm + O_SD + SD_R1);
    float2* sU    = (float2*)(sm + O_SD);
    float*  sGp   = sm + O_SD + SD_GP;
    float*  sGm   = sm + O_SD + SD_GM;
    float*  sXE   = sm + O_BIG;
    float*  sXO   = sm + O_BIG + BG_XO;
    float2* sFD2  = (float2*)(sm + O_BIG);
    float*  sXf   = sm + O_BIG + BG_XF;
    float2* sCS32 = (float2*)(sm + O_BIG + BG_CS32);
    float2* sR2   = (float2*)(sm + O_BIG);
    float2* sCS2  = (float2*)(sm + O_BIG);    // C2 twiddle table [33][34], built after stage B

    const int tid  = threadIdx.x;
    const int lane = tid & 31;
    const int wid  = tid >> 5;
    const int img  = blockIdx.x;
    const float* X = Xg + (size_t)img * 16384;
    float*       O = Og + (size_t)img * 16384;

    // ---- Stage A1, two passes of 64 rows; register twiddles ----
#pragma unroll 1
    for (int pass = 0; pass < 2; ++pass) {
        for (int i = tid; i < 64 * 64; i += THREADS) {
            int hl = i >> 6, w = i & 63;
            int h = pass * 64 + hl;
            float a = X[h * 128 + w];
            float e, o;
            if (w == 0) { e = a; o = 0.f; }
            else { float b = X[h * 128 + 128 - w]; e = a + b; o = a - b; }
            sXE[hl * 68 + w] = e; sXO[hl * 68 + w] = o;
        }
        if (tid < 64) sXE[tid * 68 + 64] = X[(pass * 64 + tid) * 128 + 64];
        __syncthreads();

        const int r0 = wid * 4;
        float s1, c1; sincospif((float)lane * (1.0f / 64.0f), &s1, &c1);
        const float t2 = 2.0f * c1;
        float a1[4] = {0,0,0,0}, a2[4] = {0,0,0,0};
        float cw = 1.f, sw = 0.f, cpv = c1, spv = -s1;
#pragma unroll 1
        for (int seg = 0; seg < 2; ++seg) {
            if (seg == 1) {
                float s32, c32; sincospif((float)lane * 0.5f, &s32, &c32);
                cw = c32; sw = s32;
                cpv = c32 * c1 + s32 * s1;
                spv = s32 * c1 - c32 * s1;
            }
            const int wb = seg * 32;
#pragma unroll
            for (int w0 = 0; w0 < 32; w0 += 4) {
                const int w = wb + w0;
                float cA = cw, sA = sw;
                float cB = t2 * cA - cpv, sB = t2 * sA - spv;
                float cC = t2 * cB - cA,  sC = t2 * sB - sA;
                float cD = t2 * cC - cB,  sD = t2 * sC - sB;
                float cE = t2 * cD - cC,  sE = t2 * sD - sC;
                cpv = cD; spv = sD; cw = cE; sw = sE;
#pragma unroll
                for (int r = 0; r < 4; ++r) {
                    float4 e = *(const float4*)&sXE[(r0 + r) * 68 + w];
                    float4 o = *(const float4*)&sXO[(r0 + r) * 68 + w];
                    a1[r] += e.x * cA + e.y * cB + e.z * cC + e.w * cD;
                    a2[r] += o.x * sA + o.y * sB + o.z * sC + o.w * sD;
                }
            }
        }
        {
            const float sg64 = (lane & 1) ? -1.f : 1.f;
#pragma unroll
            for (int r = 0; r < 4; ++r) a1[r] += sXE[(r0 + r) * 68 + 64] * sg64;
        }
#pragma unroll
        for (int r = 0; r < 4; ++r)
            sSD[(pass * 64 + r0 + r) * 34 + lane] = make_float2(a1[r] + a2[r], a1[r] - a2[r]);
        __syncthreads();
    }

    // ---- fold SD -> FD2 (pow2 index) ; build CS32 ----
    for (int i = tid; i < 2048; i += THREADS) {   // 32 v x 64 h
        int v = i >> 6, h = i & 63;
        float2 a = sSD[h * 34 + v];
        float sp, dm;
        if (h == 0) { sp = a.x; dm = 0.f; }
        else { float2 b = sSD[(128 - h) * 34 + v]; sp = a.x + b.x; dm = a.y - b.y; }
        sFD2[v * 66 + h] = make_float2(sp, dm);
    }
    if (tid < 32) {   // h = 64 tail
        float2 a = sSD[64 * 34 + tid];
        sFD2[tid * 66 + 64] = make_float2(a.x, 0.f);
    }
    for (int i = tid; i < 32 * 32; i += THREADS) {
        int u = i >> 5, h = i & 31;
        float s, c; sincospif((float)((u * h) & 31) * (1.0f / 16.0f), &s, &c);
        sCS32[u * 34 + h] = make_float2(c, s);
    }
    __syncthreads();

    // ---- Stage A2 (register twiddles over h) + weight load ----
    for (int i = tid; i < 2048; i += THREADS) {
        int t = i >> 10, idx = i & 1023;
        const float* Wsrc = (t == 0 ? W1g : W2g) + (size_t)img * 1024;
        sWR[t * 1088 + (idx >> 5) * 34 + (idx & 31)] = Wsrc[idx];
    }
    {
        const int b0 = wid * 2, b1 = wid * 2 + 1;
        float sb0, cb0; sincospif((float)wid * (1.0f / 32.0f), &sb0, &cb0);
        float sb1, cb1; sincospif((float)b1 * (1.0f / 64.0f), &sb1, &cb1);
        const float T0 = 2.f * cb0, T1 = 2.f * cb1;
        float C0=0.f,S0=0.f,C1v=0.f,S1=0.f;
        float cw0=1.f, sw0=0.f, cp0=cb0, sp0=-sb0;
        float cw1=1.f, sw1=0.f, cp1=cb1, sp1=-sb1;
#pragma unroll 1
        for (int seg = 0; seg < 2; ++seg) {
            if (seg) {  // exact restart at h=32
                float par = (wid & 1) ? -1.f : 1.f;
                cw0 = par;       sw0 = 0.f;
                cp0 = par * cb0; sp0 = -par * sb0;
                cw1 = 0.f;       sw1 = par;
                cp1 = par * sb1; sp1 = par * cb1;
            }
#pragma unroll
            for (int h0 = 0; h0 < 32; h0 += 2) {
                const int h = seg * 32 + h0;
                float4 d = *(const float4*)&sFD2[lane * 66 + h];
                float cn0 = T0 * cw0 - cp0, sn0 = T0 * sw0 - sp0;
                float cn1 = T1 * cw1 - cp1, sn1 = T1 * sw1 - sp1;
                C0  += cw0 * d.x + cn0 * d.z;  S0 += sw0 * d.y + sn0 * d.w;
                C1v += cw1 * d.x + cn1 * d.z;  S1 += sw1 * d.y + sn1 * d.w;
                float c20 = T0 * cn0 - cw0, s20 = T0 * sn0 - sw0;
                float c21 = T1 * cn1 - cw1, s21 = T1 * sn1 - sw1;
                cp0 = cn0; sp0 = sn0; cw0 = c20; sw0 = s20;
                cp1 = cn1; sp1 = sn1; cw1 = c21; sw1 = s21;
            }
        }
        {   // h = 64 tail: cos(pi*b) = (-1)^b, sin = 0
            float2 d = sFD2[lane * 66 + 64];
            C0 += d.x; C1v -= d.x;
        }
        const float sc = 1.0f / 16384.0f;
        sXf[b0 * 34 + lane] = (C0 + S0) * sc;
        if (b0 >= 1) sXf[(64 - b0) * 34 + lane] = (C0 - S0) * sc;
        sXf[b1 * 34 + lane] = (C1v + S1) * sc;
        sXf[(64 - b1) * 34 + lane] = (C1v - S1) * sc;
    }
    if (wid == 0) {   // f=96 row, computed once
        float C2a = 0.f, S2a = 0.f, sg = 1.f;
#pragma unroll 4
        for (int h = 0; h < 64; h += 2) {
            float4 d = *(const float4*)&sFD2[lane * 66 + h];
            C2a += sg * d.x; S2a -= sg * d.w; sg = -sg;
        }
        C2a += sFD2[lane * 66 + 64].x;
        sXf[32 * 34 + lane] = (C2a + S2a) * (1.0f / 16384.0f);
    }
    __syncthreads();

    // ======== Stage B: folded 32-DHTs ========
    {
        const int g = wid >> 3, role = (wid >> 2) & 1, w4 = wid & 3, w8 = wid & 7;
        float*  Xfg = sXf + g * 1088;
        float*  Wg  = sWR + g * 1088;
        float*  Ahg = sAH + g * 1088;
        float2* R1g = sR1 + g * 1056;
        float2* R2g = sR2 + g * 1056;

        float wv0[2], wv1[2]; float e16w = 0.f;
#pragma unroll
        for (int k = 0; k < 2; ++k) {
            int i = tid + k * THREADS;
            int gg = i >> 9, rem = i & 511, row = rem >> 4, w = rem & 15;
            const float* Ws = sWR + gg * 1088;
            wv0[k] = Ws[row * 34 + w];
            wv1[k] = (w == 0) ? 0.f : Ws[row * 34 + 32 - w];
        }
        if (tid < 64) e16w = (sWR + (tid >> 5) * 1088)[(tid & 31) * 34 + 16];
        for (int i = tid; i < 1024; i += THREADS) {
            int gg = i >> 9, rem = i & 511, row = rem >> 4, w = rem & 15;
            const float* A = sXf + gg * 1088;
            float* EO = sAH + gg * 1088;
            float av = A[row * 34 + w], e, o;
            if (w == 0) { e = av; o = 0.f; }
            else { float bv = A[row * 34 + 32 - w]; e = av + bv; o = av - bv; }
            EO[row * 32 + 2 * w] = e; EO[row * 32 + 2 * w + 1] = o;
        }
        if (tid < 64) (sAH + (tid >> 5) * 1088)[1024 + (tid & 31)] =
                          (sXf + (tid >> 5) * 1088)[(tid & 31) * 34 + 16];
        __syncthreads();
#pragma unroll
        for (int k = 0; k < 2; ++k) {
            int i = tid + k * THREADS;
            int gg = i >> 9, rem = i & 511, row = rem >> 4, w = rem & 15;
            float* EO = sWR + gg * 1088;
            float e, o;
            if (w == 0) { e = wv0[k]; o = 0.f; }
            else { e = wv0[k] + wv1[k]; o = wv0[k] - wv1[k]; }
            EO[row * 32 + 2 * w] = e; EO[row * 32 + 2 * w + 1] = o;
        }
        if (tid < 64) (sWR + (tid >> 5) * 1088)[1024 + (tid & 31)] = e16w;
        __syncthreads();

        if (role == 0) dht32_p1f<8>(Ahg, R1g, w4 * 8, lane);
        else           dht32_p1f<8>(Wg,  R2g, w4 * 8, lane);
        __syncthreads();
        // fold R (pow2 main + h=16 tail)
        for (int i = tid; i < 2048; i += THREADS) {
            int col = i & 31, h = (i >> 5) & 15, gg = (i >> 9) & 1, chain = i >> 10;
            float2* Rb = ((chain == 0) ? sR1 : sR2) + gg * 1056;
            float2 pm;
            if (h == 0) { float2 v = Rb[col]; pm = make_float2(v.x, 0.f); }
            else { float2 va = Rb[h * 33 + col], vb = Rb[(32 - h) * 33 + col];
                   pm = make_float2(va.x + vb.x, va.y - vb.y); }
            Rb[h * 33 + col] = pm;
        }
        if (tid < 128) {
            int col = tid & 31, gg = (tid >> 5) & 1, chain = tid >> 6;
            float2* Rb = ((chain == 0) ? sR1 : sR2) + gg * 1056;
            float2 v = Rb[16 * 33 + col];
            Rb[16 * 33 + col] = make_float2(v.x, 0.f);
        }
        __syncthreads();
        if (role == 0) dht32_p2f<8>(R1g, sCS32, Ahg, 1.0f / 1024.0f, w4 * 8, lane);
        else           dht32_p2f<8>(R2g, sCS32, Wg,  1.0f / 1024.0f, w4 * 8, lane);
        __syncthreads();

        for (int i = tid; i < 1024; i += THREADS) {
            int gg = i >> 9, rem = i & 511, row = rem >> 4, w = rem & 15;
            const float* Ah = sAH + gg * 1088; const float* Wh = sWR + gg * 1088;
            float* EO = sXf + gg * 1088;
            float pv = Ah[row * 34 + w] * Wh[row * 34 + w], e, o;
            if (w == 0) { e = pv; o = 0.f; }
            else { float qv = Ah[row * 34 + 32 - w] * Wh[row * 34 + 32 - w];
                   e = pv + qv; o = pv - qv; }
            EO[row * 32 + 2 * w] = e; EO[row * 32 + 2 * w + 1] = o;
        }
        if (tid < 64) {
            int gg = tid >> 5, row = tid & 31;
            (sXf + gg * 1088)[1024 + row] =
                (sAH + gg * 1088)[row * 34 + 16] * (sWR + gg * 1088)[row * 34 + 16];
        }
        __syncthreads();
        dht32_p1f<4>(Xfg, R1g, w8 * 4, lane);
        __syncthreads();
        for (int i = tid; i < 1024; i += THREADS) {
            int col = i & 31, h = (i >> 5) & 15, gg = i >> 9;
            float2* Rb = sR1 + gg * 1056;
            float2 pm;
            if (h == 0) { float2 v = Rb[col]; pm = make_float2(v.x, 0.f); }
            else { float2 va = Rb[h * 33 + col], vb = Rb[(32 - h) * 33 + col];
                   pm = make_float2(va.x + vb.x, va.y - vb.y); }
            Rb[h * 33 + col] = pm;
        }
        if (tid < 64) {
            int col = tid & 31, gg = tid >> 5;
            float2* Rb = sR1 + gg * 1056;
            float2 v = Rb[16 * 33 + col];
            Rb[16 * 33 + col] = make_float2(v.x, 0.f);
        }
        __syncthreads();
        dht32_p2f<4>(R1g, sCS32, Xfg, 1.0f / 65536.0f, w8 * 4, lane);
        __syncthreads();
    }

    // ---- C1 prep: Gp/Gm + build C2 twiddle table (R2/FD2 region dead) ----
    for (int i = tid; i < 33 * 32; i += THREADS) {
        int b = i >> 5, s = i & 31;
        float gp, gm;
        if (b == 0)      { gp = sXf[s];             gm = 0.f; }
        else if (b == 32){ gp = sXf[32 * 34 + s];   gm = gp;  }
        else {
            float xa = sXf[b * 34 + s], xb = sXf[(64 - b) * 34 + s];
            gp = xa + xb; gm = xa - xb;
        }
        sGp[b * 34 + s] = gp; sGm[b * 34 + s] = gm;
    }
    for (int i = tid; i < 33 * 32; i += THREADS) {
        int w = i >> 5, v = i & 31;
        float s, c; sincospif((float)((w * v) & 127) * (1.0f / 64.0f), &s, &c);
        sCS2[w * 34 + v] = make_float2(c, s);
    }
    __syncthreads();

    // ---- Stage C1: register twiddles over b (4 rows/warp) ----
    {
        const int hb = wid * 4;
        float cj[4], sj[4], cp[4], sp[4], T[4];
#pragma unroll
        for (int j = 0; j < 4; ++j) {
            float st, ct; sincospif((float)(hb + j) * (1.0f / 64.0f), &st, &ct);
            T[j] = 2.f * ct; cj[j] = 1.f; sj[j] = 0.f; cp[j] = ct; sp[j] = -st;
        }
        float Uc[4] = {0,0,0,0}, Us[4] = {0,0,0,0};
#pragma unroll 4
        for (int b = 0; b < 32; ++b) {
            float gp = sGp[b * 34 + lane];
            float gm = sGm[b * 34 + lane];
#pragma unroll
            for (int j = 0; j < 4; ++j) {
                Uc[j] += cj[j] * gp; Us[j] += sj[j] * gm;
                float cn = T[j] * cj[j] - cp[j], sn = T[j] * sj[j] - sp[j];
                cp[j] = cj[j]; sp[j] = sj[j]; cj[j] = cn; sj[j] = sn;
            }
        }
        {   // b = 32 tail (f=96): cos(3pi h'/2): m0:+1 m2:-1 ; sin: m1:-1 m3:+1
            float gp32 = sGp[32 * 34 + lane];
#pragma unroll
            for (int j = 0; j < 4; ++j) {
                int m = (hb + j) & 3;
                if (m == 0)      Uc[j] += gp32;
                else if (m == 1) Us[j] -= gp32;
                else if (m == 2) Uc[j] -= gp32;
                else             Us[j] += gp32;
            }
        }
#pragma unroll
        for (int j = 0; j < 4; ++j)
            sU[(hb + j) * 34 + lane] = make_float2(Uc[j] + Us[j], Uc[j] - Us[j]);
    }
    if (tid < 32) {
        float acc = 0.f;
#pragma unroll 1
        for (int b = 0; b < 32; b += 2)
            acc += sGp[b * 34 + tid] - sGp[(b + 1) * 34 + tid];
        acc += sGp[32 * 34 + tid];
        sU[64 * 34 + tid] = make_float2(acc, acc);
    }
    __syncthreads();

    for (int i = tid; i < 63 * 32; i += THREADS) {
        int r = 65 + (i >> 5), s = i & 31;
        float2 v = sU[(128 - r) * 34 + s];
        sU[r * 34 + s] = make_float2(v.y, v.x);
    }
    __syncthreads();

    // ---- Stage C2: exact table + partner column, 4 rows x 2 passes ----
    {
        const float sc = 1.0f / 1048576.0f;
        const int wp = lane;
        const int wq = lane ? (64 - lane) : 32;
#pragma unroll 1
        for (int half = 0; half < 2; ++half) {
            const int hb = wid * 8 + half * 4;
            float A[4]  = {0,0,0,0}, B[4]  = {0,0,0,0};
            float Ap[4] = {0,0,0,0}, Bp[4] = {0,0,0,0};
#pragma unroll 4
            for (int s = 0; s < 32; s += 2) {
                float4 cs = *(const float4*)&sCS2[wp * 34 + s];
                float4 cp;
                if (lane == 0) cp = *(const float4*)&sCS2[32 * 34 + s];
                else           cp = make_float4(cs.x, -cs.y, -cs.z, cs.w);
#pragma unroll
                for (int j = 0; j < 4; ++j) {
                    float4 uu = *(const float4*)&sU[(hb + j) * 34 + s];
                    A[j]  += uu.x * cs.x + uu.z * cs.z;
                    B[j]  += uu.y * cs.y + uu.w * cs.w;
                    Ap[j] += uu.x * cp.x + uu.z * cp.z;
                    Bp[j] += uu.y * cp.y + uu.w * cp.w;
                }
            }
#pragma unroll
            for (int j = 0; j < 4; ++j) {
                O[(hb + j) * 128 + wp] = (A[j] + B[j]) * sc;
                if (wp) O[(hb + j) * 128 + (128 - wp)] = (A[j] - B[j]) * sc;
                O[(hb + j) * 128 + wq] = (Ap[j] + Bp[j]) * sc;
                O[(hb + j) * 128 + (128 - wq)] = (Ap[j] - Bp[j]) * sc;
            }
        }
    }
    if (tid < 128) {
        float acc = 0.f;
#pragma unroll 4
        for (int s = 0; s < 32; s += 2)
            acc += sU[tid * 34 + s].x - sU[tid * 34 + s + 1].x;
        O[tid * 128 + 64] = acc * (1.0f / 1048576.0f);
    }
}

extern "C" void kernel_launch(void* const* d_in, const int* in_sizes, int n_in,
                              void* d_out, int out_size)
{
    const float* x  = (const float*)d_in[0];
    const float* w1 = (const float*)d_in[1];
    const float* w2 = (const float*)d_in[2];
    float* out = (float*)d_out;

    const int smem_bytes = F_TOT * 4; // 69632
    cudaFuncSetAttribute(spectral_kernel,
                         cudaFuncAttributeMaxDynamicSharedMemorySize, smem_bytes);
    spectral_kernel<<<4096, THREADS, smem_bytes>>>(x, w1, w2, out);
}

// round 17
// speedup vs baseline: 2.5415x; 1.0825x over previous
#include <cuda_runtime.h>
#define THREADS 512
typedef unsigned long long u64_t;

// float offsets in dynamic smem (total 17408 floats = 69632 B -> 3 CTAs/SM)
#define O_SD   0       // region 8704 f : SD[128][34]f2 | {WR,AH,R1} | {U,Gp,Gm}
#define O_BIG  8704    // region 8704 f : {XEO} | {FD2,Xf,CS32} | {R2,Xf,CS32} | {CS2}
#define F_TOT  17408

#define SD_WR   0
#define SD_AH   2176
#define SD_R1   4352
#define SD_GP   4420
#define SD_GM   5542
#define BG_XF   4352
#define BG_CS32 6528

static __device__ __forceinline__ u64_t pk2(float lo, float hi) {
    u64_t r; asm("mov.b64 %0, {%1, %2};" : "=l"(r) : "f"(lo), "f"(hi)); return r;
}
static __device__ __forceinline__ float2 up2(u64_t v) {
    float2 r; asm("mov.b64 {%0, %1}, %2;" : "=f"(r.x), "=f"(r.y) : "l"(v)); return r;
}
static __device__ __forceinline__ u64_t fma2_(u64_t a, u64_t b, u64_t c) {
    u64_t d; asm("fma.rn.f32x2 %0, %1, %2, %3;" : "=l"(d) : "l"(a), "l"(b), "l"(c)); return d;
}

// folded 32-DHT pass1, packed accumulators: EO layout (E,O) pairs at
// [row*32+2w] (w=0..15), E16 at [1024+row]
template<int NR>
static __device__ __forceinline__ void dht32_p1f(const float* __restrict__ eo,
                                                 float2* __restrict__ R,
                                                 int h0, int lane)
{
    u64_t acc[NR];
#pragma unroll
    for (int r = 0; r < NR; ++r) acc[r] = 0ULL;
    float s1, c1; sincospif((float)lane * (1.0f / 16.0f), &s1, &c1);
    const float t2 = 2.0f * c1;
    float cw = 1.f, sw = 0.f, cpv = c1, spv = -s1;
#pragma unroll
    for (int w = 0; w < 16; w += 2) {
        float cn = t2 * cw - cpv, sn = t2 * sw - spv;
        u64_t q0 = pk2(cw, sw), q1 = pk2(cn, sn);
#pragma unroll
        for (int r = 0; r < NR; ++r) {
            ulonglong2 e = *(const ulonglong2*)&eo[(h0 + r) * 32 + 2 * w];
            acc[r] = fma2_(e.x, q0, acc[r]);
            acc[r] = fma2_(e.y, q1, acc[r]);
        }
        float cn2 = t2 * cn - cw, sn2 = t2 * sn - sw;
        cpv = cn; spv = sn; cw = cn2; sw = sn2;
    }
    const float sgn = (lane & 1) ? -1.f : 1.f;
#pragma unroll
    for (int r = 0; r < NR; ++r) {
        float2 v = up2(acc[r]);
        float t1 = v.x + sgn * eo[1024 + h0 + r];
        R[(h0 + r) * 33 + lane] = make_float2(t1 + v.y, t1 - v.y);
    }
}

// folded pass2: broadcast cs32 table reads
template<int NR>
static __device__ __forceinline__ void dht32_p2f(const float2* __restrict__ R,
                                                 const float2* __restrict__ cs32,
                                                 float* __restrict__ dst,
                                                 float scale, int u0, int lane)
{
    float acc[NR];
#pragma unroll
    for (int r = 0; r < NR; ++r) acc[r] = 0.f;
#pragma unroll
    for (int h = 0; h < 16; h += 2) {
        float2 a = R[h * 33 + lane], b = R[(h + 1) * 33 + lane];
#pragma unroll
        for (int r = 0; r < NR; ++r) {
            float4 cs = *(const float4*)&cs32[(u0 + r) * 34 + h];
            acc[r] += cs.x * a.x + cs.y * a.y + cs.z * b.x + cs.w * b.y;
        }
    }
    float p16 = R[16 * 33 + lane].x;
#pragma unroll
    for (int r = 0; r < NR; ++r) {
        float sg = ((u0 + r) & 1) ? -p16 : p16;
        dst[(u0 + r) * 34 + lane] = (acc[r] + sg) * scale;
    }
}

__global__ __launch_bounds__(THREADS, 3)
void spectral_kernel(const float* __restrict__ Xg,
                     const float* __restrict__ W1g,
                     const float* __restrict__ W2g,
                     float* __restrict__ Og)
{
    extern __shared__ float sm[];
    float2* sSD   = (float2*)(sm + O_SD);
    float*  sWR   = sm + O_SD + SD_WR;
    float*  sAH   = sm + O_SD + SD_AH;
    float2* sR1   = (float2*)(sm + O_SD + SD_R1);
    float2* sU    = (float2*)(sm + O_SD);
    float*  sGp   = sm + O_SD + SD_GP;
    float*  sGm   = sm + O_SD + SD_GM;
    float*  sXEO  = sm + O_BIG;                 // [64][136] (e,o) pairs + e64 at +128
    float2* sFD2  = (float2*)(sm + O_BIG);
    float*  sXf   = sm + O_BIG + BG_XF;
    float2* sCS32 = (float2*)(sm + O_BIG + BG_CS32);
    float2* sR2   = (float2*)(sm + O_BIG);
    float2* sCS2  = (float2*)(sm + O_BIG);      // C2 twiddle table [33][34], built after stage B

    const int tid  = threadIdx.x;
    const int lane = tid & 31;
    const int wid  = tid >> 5;
    const int img  = blockIdx.x;
    const float* X = Xg + (size_t)img * 16384;
    float*       O = Og + (size_t)img * 16384;

    // ---- Stage A1, two passes of 64 rows; packed accumulation ----
#pragma unroll 1
    for (int pass = 0; pass < 2; ++pass) {
        for (int i = tid; i < 64 * 64; i += THREADS) {
            int hl = i >> 6, w = i & 63;
            int h = pass * 64 + hl;
            float a = X[h * 128 + w];
            float e, o;
            if (w == 0) { e = a; o = 0.f; }
            else { float b = X[h * 128 + 128 - w]; e = a + b; o = a - b; }
            sXEO[hl * 136 + 2 * w]     = e;
            sXEO[hl * 136 + 2 * w + 1] = o;
        }
        if (tid < 64) sXEO[tid * 136 + 128] = X[(pass * 64 + tid) * 128 + 64];
        __syncthreads();

        const int r0 = wid * 4;
        float s1, c1; sincospif((float)lane * (1.0f / 64.0f), &s1, &c1);
        const float t2 = 2.0f * c1;
        u64_t acc[4] = {0ULL, 0ULL, 0ULL, 0ULL};
        float cw = 1.f, sw = 0.f, cpv = c1, spv = -s1;
#pragma unroll 1
        for (int seg = 0; seg < 2; ++seg) {
            if (seg == 1) {
                float s32, c32; sincospif((float)lane * 0.5f, &s32, &c32);
                cw = c32; sw = s32;
                cpv = c32 * c1 + s32 * s1;
                spv = s32 * c1 - c32 * s1;
            }
            const int wb = seg * 32;
#pragma unroll
            for (int w0 = 0; w0 < 32; w0 += 4) {
                const int w = wb + w0;
                float cA = cw, sA = sw;
                float cB = t2 * cA - cpv, sB = t2 * sA - spv;
                float cC = t2 * cB - cA,  sC = t2 * sB - sA;
                float cD = t2 * cC - cB,  sD = t2 * sC - sB;
                float cE = t2 * cD - cC,  sE = t2 * sD - sC;
                cpv = cD; spv = sD; cw = cE; sw = sE;
                u64_t q0 = pk2(cA, sA), q1 = pk2(cB, sB);
                u64_t q2 = pk2(cC, sC), q3 = pk2(cD, sD);
#pragma unroll
                for (int r = 0; r < 4; ++r) {
                    ulonglong2 ea = *(const ulonglong2*)&sXEO[(r0 + r) * 136 + 2 * w];
                    ulonglong2 eb = *(const ulonglong2*)&sXEO[(r0 + r) * 136 + 2 * w + 4];
                    acc[r] = fma2_(ea.x, q0, acc[r]);
                    acc[r] = fma2_(ea.y, q1, acc[r]);
                    acc[r] = fma2_(eb.x, q2, acc[r]);
                    acc[r] = fma2_(eb.y, q3, acc[r]);
                }
            }
        }
        {
            const float sg64 = (lane & 1) ? -1.f : 1.f;
#pragma unroll
            for (int r = 0; r < 4; ++r) {
                float2 v = up2(acc[r]);
                float a1v = v.x + sXEO[(r0 + r) * 136 + 128] * sg64;
                sSD[(pass * 64 + r0 + r) * 34 + lane] = make_float2(a1v + v.y, a1v - v.y);
            }
        }
        __syncthreads();
    }

    // ---- fold SD -> FD2 (pow2 index) ; build CS32 ----
    for (int i = tid; i < 2048; i += THREADS) {   // 32 v x 64 h
        int v = i >> 6, h = i & 63;
        float2 a = sSD[h * 34 + v];
        float sp, dm;
        if (h == 0) { sp = a.x; dm = 0.f; }
        else { float2 b = sSD[(128 - h) * 34 + v]; sp = a.x + b.x; dm = a.y - b.y; }
        sFD2[v * 66 + h] = make_float2(sp, dm);
    }
    if (tid < 32) {   // h = 64 tail
        float2 a = sSD[64 * 34 + tid];
        sFD2[tid * 66 + 64] = make_float2(a.x, 0.f);
    }
    for (int i = tid; i < 32 * 32; i += THREADS) {
        int u = i >> 5, h = i & 31;
        float s, c; sincospif((float)((u * h) & 31) * (1.0f / 16.0f), &s, &c);
        sCS32[u * 34 + h] = make_float2(c, s);
    }
    __syncthreads();

    // ---- Stage A2 (register twiddles over h) + weight load ----
    for (int i = tid; i < 2048; i += THREADS) {
        int t = i >> 10, idx = i & 1023;
        const float* Wsrc = (t == 0 ? W1g : W2g) + (size_t)img * 1024;
        sWR[t * 1088 + (idx >> 5) * 34 + (idx & 31)] = Wsrc[idx];
    }
    {
        const int b0 = wid * 2, b1 = wid * 2 + 1;
        float sb0, cb0; sincospif((float)wid * (1.0f / 32.0f), &sb0, &cb0);
        float sb1, cb1; sincospif((float)b1 * (1.0f / 64.0f), &sb1, &cb1);
        const float T0 = 2.f * cb0, T1 = 2.f * cb1;
        float C0=0.f,S0=0.f,C1v=0.f,S1=0.f;
        float cw0=1.f, sw0=0.f, cp0=cb0, sp0=-sb0;
        float cw1=1.f, sw1=0.f, cp1=cb1, sp1=-sb1;
#pragma unroll 1
        for (int seg = 0; seg < 2; ++seg) {
            if (seg) {  // exact restart at h=32
                float par = (wid & 1) ? -1.f : 1.f;
                cw0 = par;       sw0 = 0.f;
                cp0 = par * cb0; sp0 = -par * sb0;
                cw1 = 0.f;       sw1 = par;
                cp1 = par * sb1; sp1 = par * cb1;
            }
#pragma unroll
            for (int h0 = 0; h0 < 32; h0 += 2) {
                const int h = seg * 32 + h0;
                float4 d = *(const float4*)&sFD2[lane * 66 + h];
                float cn0 = T0 * cw0 - cp0, sn0 = T0 * sw0 - sp0;
                float cn1 = T1 * cw1 - cp1, sn1 = T1 * sw1 - sp1;
                C0  += cw0 * d.x + cn0 * d.z;  S0 += sw0 * d.y + sn0 * d.w;
                C1v += cw1 * d.x + cn1 * d.z;  S1 += sw1 * d.y + sn1 * d.w;
                float c20 = T0 * cn0 - cw0, s20 = T0 * sn0 - sw0;
                float c21 = T1 * cn1 - cw1, s21 = T1 * sn1 - sw1;
                cp0 = cn0; sp0 = sn0; cw0 = c20; sw0 = s20;
                cp1 = cn1; sp1 = sn1; cw1 = c21; sw1 = s21;
            }
        }
        {   // h = 64 tail: cos(pi*b) = (-1)^b, sin = 0
            float2 d = sFD2[lane * 66 + 64];
            C0 += d.x; C1v -= d.x;
        }
        const float sc = 1.0f / 16384.0f;
        sXf[b0 * 34 + lane] = (C0 + S0) * sc;
        if (b0 >= 1) sXf[(64 - b0) * 34 + lane] = (C0 - S0) * sc;
        sXf[b1 * 34 + lane] = (C1v + S1) * sc;
        sXf[(64 - b1) * 34 + lane] = (C1v - S1) * sc;
    }
    if (wid == 0) {   // f=96 row, computed once
        float C2a = 0.f, S2a = 0.f, sg = 1.f;
#pragma unroll 4
        for (int h = 0; h < 64; h += 2) {
            float4 d = *(const float4*)&sFD2[lane * 66 + h];
            C2a += sg * d.x; S2a -= sg * d.w; sg = -sg;
        }
        C2a += sFD2[lane * 66 + 64].x;
        sXf[32 * 34 + lane] = (C2a + S2a) * (1.0f / 16384.0f);
    }
    __syncthreads();

    // ======== Stage B: folded 32-DHTs ========
    {
        const int g = wid >> 3, role = (wid >> 2) & 1, w4 = wid & 3, w8 = wid & 7;
        float*  Xfg = sXf + g * 1088;
        float*  Wg  = sWR + g * 1088;
        float*  Ahg = sAH + g * 1088;
        float2* R1g = sR1 + g * 1056;
        float2* R2g = sR2 + g * 1056;

        float wv0[2], wv1[2]; float e16w = 0.f;
#pragma unroll
        for (int k = 0; k < 2; ++k) {
            int i = tid + k * THREADS;
            int gg = i >> 9, rem = i & 511, row = rem >> 4, w = rem & 15;
            const float* Ws = sWR + gg * 1088;
            wv0[k] = Ws[row * 34 + w];
            wv1[k] = (w == 0) ? 0.f : Ws[row * 34 + 32 - w];
        }
        if (tid < 64) e16w = (sWR + (tid >> 5) * 1088)[(tid & 31) * 34 + 16];
        for (int i = tid; i < 1024; i += THREADS) {
            int gg = i >> 9, rem = i & 511, row = rem >> 4, w = rem & 15;
            const float* A = sXf + gg * 1088;
            float* EO = sAH + gg * 1088;
            float av = A[row * 34 + w], e, o;
            if (w == 0) { e = av; o = 0.f; }
            else { float bv = A[row * 34 + 32 - w]; e = av + bv; o = av - bv; }
            EO[row * 32 + 2 * w] = e; EO[row * 32 + 2 * w + 1] = o;
        }
        if (tid < 64) (sAH + (tid >> 5) * 1088)[1024 + (tid & 31)] =
                          (sXf + (tid >> 5) * 1088)[(tid & 31) * 34 + 16];
        __syncthreads();
#pragma unroll
        for (int k = 0; k < 2; ++k) {
            int i = tid + k * THREADS;
            int gg = i >> 9, rem = i & 511, row = rem >> 4, w = rem & 15;
            float* EO = sWR + gg * 1088;
            float e, o;
            if (w == 0) { e = wv0[k]; o = 0.f; }
            else { e = wv0[k] + wv1[k]; o = wv0[k] - wv1[k]; }
            EO[row * 32 + 2 * w] = e; EO[row * 32 + 2 * w + 1] = o;
        }
        if (tid < 64) (sWR + (tid >> 5) * 1088)[1024 + (tid & 31)] = e16w;
        __syncthreads();

        if (role == 0) dht32_p1f<8>(Ahg, R1g, w4 * 8, lane);
        else           dht32_p1f<8>(Wg,  R2g, w4 * 8, lane);
        __syncthreads();
        // fold R (pow2 main + h=16 tail)
        for (int i = tid; i < 2048; i += THREADS) {
            int col = i & 31, h = (i >> 5) & 15, gg = (i >> 9) & 1, chain = i >> 10;
            float2* Rb = ((chain == 0) ? sR1 : sR2) + gg * 1056;
            float2 pm;
            if (h == 0) { float2 v = Rb[col]; pm = make_float2(v.x, 0.f); }
            else { float2 va = Rb[h * 33 + col], vb = Rb[(32 - h) * 33 + col];
                   pm = make_float2(va.x + vb.x, va.y - vb.y); }
            Rb[h * 33 + col] = pm;
        }
        if (tid < 128) {
            int col = tid & 31, gg = (tid >> 5) & 1, chain = tid >> 6;
            float2* Rb = ((chain == 0) ? sR1 : sR2) + gg * 1056;
            float2 v = Rb[16 * 33 + col];
            Rb[16 * 33 + col] = make_float2(v.x, 0.f);
        }
        __syncthreads();
        if (role == 0) dht32_p2f<8>(R1g, sCS32, Ahg, 1.0f / 1024.0f, w4 * 8, lane);
        else           dht32_p2f<8>(R2g, sCS32, Wg,  1.0f / 1024.0f, w4 * 8, lane);
        __syncthreads();

        for (int i = tid; i < 1024; i += THREADS) {
            int gg = i >> 9, rem = i & 511, row = rem >> 4, w = rem & 15;
            const float* Ah = sAH + gg * 1088; const float* Wh = sWR + gg * 1088;
            float* EO = sXf + gg * 1088;
            float pv = Ah[row * 34 + w] * Wh[row * 34 + w], e, o;
            if (w == 0) { e = pv; o = 0.f; }
            else { float qv = Ah[row * 34 + 32 - w] * Wh[row * 34 + 32 - w];
                   e = pv + qv; o = pv - qv; }
            EO[row * 32 + 2 * w] = e; EO[row * 32 + 2 * w + 1] = o;
        }
        if (tid < 64) {
            int gg = tid >> 5, row = tid & 31;
            (sXf + gg * 1088)[1024 + row] =
                (sAH + gg * 1088)[row * 34 + 16] * (sWR + gg * 1088)[row * 34 + 16];
        }
        __syncthreads();
        dht32_p1f<4>(Xfg, R1g, w8 * 4, lane);
        __syncthreads();
        for (int i = tid; i < 1024; i += THREADS) {
            int col = i & 31, h = (i >> 5) & 15, gg = i >> 9;
            float2* Rb = sR1 + gg * 1056;
            float2 pm;
            if (h == 0) { float2 v = Rb[col]; pm = make_float2(v.x, 0.f); }
            else { float2 va = Rb[h * 33 + col], vb = Rb[(32 - h) * 33 + col];
                   pm = make_float2(va.x + vb.x, va.y - vb.y); }
            Rb[h * 33 + col] = pm;
        }
        if (tid < 64) {
            int col = tid & 31, gg = tid >> 5;
            float2* Rb = sR1 + gg * 1056;
            float2 v = Rb[16 * 33 + col];
            Rb[16 * 33 + col] = make_float2(v.x, 0.f);
        }
        __syncthreads();
        dht32_p2f<4>(R1g, sCS32, Xfg, 1.0f / 65536.0f, w8 * 4, lane);
        __syncthreads();
    }

    // ---- C1 prep: Gp/Gm + build C2 twiddle table (R2/FD2 region dead) ----
    for (int i = tid; i < 33 * 32; i += THREADS) {
        int b = i >> 5, s = i & 31;
        float gp, gm;
        if (b == 0)      { gp = sXf[s];             gm = 0.f; }
        else if (b == 32){ gp = sXf[32 * 34 + s];   gm = gp;  }
        else {
            float xa = sXf[b * 34 + s], xb = sXf[(64 - b) * 34 + s];
            gp = xa + xb; gm = xa - xb;
        }
        sGp[b * 34 + s] = gp; sGm[b * 34 + s] = gm;
    }
    for (int i = tid; i < 33 * 32; i += THREADS) {
        int w = i >> 5, v = i & 31;
        float s, c; sincospif((float)((w * v) & 127) * (1.0f / 64.0f), &s, &c);
        sCS2[w * 34 + v] = make_float2(c, s);
    }
    __syncthreads();

    // ---- Stage C1: register twiddles over b (4 rows/warp) ----
    {
        const int hb = wid * 4;
        float cj[4], sj[4], cp[4], sp[4], T[4];
#pragma unroll
        for (int j = 0; j < 4; ++j) {
            float st, ct; sincospif((float)(hb + j) * (1.0f / 64.0f), &st, &ct);
            T[j] = 2.f * ct; cj[j] = 1.f; sj[j] = 0.f; cp[j] = ct; sp[j] = -st;
        }
        float Uc[4] = {0,0,0,0}, Us[4] = {0,0,0,0};
#pragma unroll 4
        for (int b = 0; b < 32; ++b) {
            float gp = sGp[b * 34 + lane];
            float gm = sGm[b * 34 + lane];
#pragma unroll
            for (int j = 0; j < 4; ++j) {
                Uc[j] += cj[j] * gp; Us[j] += sj[j] * gm;
                float cn = T[j] * cj[j] - cp[j], sn = T[j] * sj[j] - sp[j];
                cp[j] = cj[j]; sp[j] = sj[j]; cj[j] = cn; sj[j] = sn;
            }
        }
        {   // b = 32 tail (f=96): cos(3pi h'/2): m0:+1 m2:-1 ; sin: m1:-1 m3:+1
            float gp32 = sGp[32 * 34 + lane];
#pragma unroll
            for (int j = 0; j < 4; ++j) {
                int m = (hb + j) & 3;
                if (m == 0)      Uc[j] += gp32;
                else if (m == 1) Us[j] -= gp32;
                else if (m == 2) Uc[j] -= gp32;
                else             Us[j] += gp32;
            }
        }
#pragma unroll
        for (int j = 0; j < 4; ++j)
            sU[(hb + j) * 34 + lane] = make_float2(Uc[j] + Us[j], Uc[j] - Us[j]);
    }
    if (tid < 32) {
        float acc = 0.f;
#pragma unroll 1
        for (int b = 0; b < 32; b += 2)
            acc += sGp[b * 34 + tid] - sGp[(b + 1) * 34 + tid];
        acc += sGp[32 * 34 + tid];
        sU[64 * 34 + tid] = make_float2(acc, acc);
    }
    __syncthreads();

    for (int i = tid; i < 63 * 32; i += THREADS) {
        int r = 65 + (i >> 5), s = i & 31;
        float2 v = sU[(128 - r) * 34 + s];
        sU[r * 34 + s] = make_float2(v.y, v.x);
    }
    __syncthreads();

    // ---- Stage C2: packed f32x2, exact table + sign-xor partner column ----
    {
        const float sc = 1.0f / 1048576.0f;
        const int wp = lane;
        const int wq = lane ? (64 - lane) : 32;
        const u64_t NEG_HI = 0x8000000000000000ULL;   // negate sin (even s)
        const u64_t NEG_LO = 0x0000000080000000ULL;   // negate cos (odd s)
#pragma unroll 1
        for (int half = 0; half < 2; ++half) {
            const int hb = wid * 8 + half * 4;
            u64_t AB[4]  = {0ULL,0ULL,0ULL,0ULL};
            u64_t ABp[4] = {0ULL,0ULL,0ULL,0ULL};
#pragma unroll 4
            for (int s = 0; s < 32; s += 2) {
                ulonglong2 cs = *(const ulonglong2*)&sCS2[wp * 34 + s];
                u64_t cq0, cq1;
                if (lane == 0) {
                    ulonglong2 t = *(const ulonglong2*)&sCS2[32 * 34 + s];
                    cq0 = t.x; cq1 = t.y;
                } else {
                    cq0 = cs.x ^ NEG_HI;
                    cq1 = cs.y ^ NEG_LO;
                }
#pragma unroll
                for (int j = 0; j < 4; ++j) {
                    ulonglong2 uu = *(const ulonglong2*)&sU[(hb + j) * 34 + s];
                    AB[j]  = fma2_(uu.x, cs.x, AB[j]);
                    AB[j]  = fma2_(uu.y, cs.y, AB[j]);
                    ABp[j] = fma2_(uu.x, cq0, ABp[j]);
                    ABp[j] = fma2_(uu.y, cq1, ABp[j]);
                }
            }
#pragma unroll
            for (int j = 0; j < 4; ++j) {
                float2 v  = up2(AB[j]);
                float2 vp = up2(ABp[j]);
                O[(hb + j) * 128 + wp] = (v.x + v.y) * sc;
                if (wp) O[(hb + j) * 128 + (128 - wp)] = (v.x - v.y) * sc;
                O[(hb + j) * 128 + wq] = (vp.x + vp.y) * sc;
                O[(hb + j) * 128 + (128 - wq)] = (vp.x - vp.y) * sc;
            }
        }
    }
    if (tid < 128) {
        float acc = 0.f;
#pragma unroll 4
        for (int s = 0; s < 32; s += 2)
            acc += sU[tid * 34 + s].x - sU[tid * 34 + s + 1].x;
        O[tid * 128 + 64] = acc * (1.0f / 1048576.0f);
    }
}

extern "C" void kernel_launch(void* const* d_in, const int* in_sizes, int n_in,
                              void* d_out, int out_size)
{
    const float* x  = (const float*)d_in[0];
    const float* w1 = (const float*)d_in[1];
    const float* w2 = (const float*)d_in[2];
    float* out = (float*)d_out;

    const int smem_bytes = F_TOT * 4; // 69632
    cudaFuncSetAttribute(spectral_kernel,
                         cudaFuncAttributeMaxDynamicSharedMemorySize, smem_bytes);
    spectral_kernel<<<4096, THREADS, smem_bytes>>>(x, w1, w2, out);
}